// round 9
// baseline (speedup 1.0000x reference)
#include <cuda_runtime.h>
#include <cuda_bf16.h>
#include <cstdint>

#define BATCH 64

// ------------------------- scratch (no allocs allowed) -------------------------
__device__ float    g_bufA[BATCH*32*160*160];   // conv1 out (fp32, for stats)
__device__ float    g_bufB[BATCH*32*160*160];   // rconv out (fp32, for pool)
#define NX (BATCH*3*170*170)
__device__ uint32_t g_xH2[NX];                  // input: overlapping bf16-hi pairs
__device__ uint32_t g_xL2[NX];
#define NACT (BATCH*16*160*160)
__device__ uint32_t g_actH2[NACT];              // act: channel-pair planes [b][16][160][160]
__device__ uint32_t g_actL2[NACT];
#define NPOOL (BATCH*32*80*80)
__device__ uint32_t g_poolH2[NPOOL];            // pool: overlapping pairs along x
__device__ uint32_t g_poolL2[NPOOL];
__device__ float g_c4[BATCH*16*73*73];
__device__ float g_c5[BATCH*16*33*33];
__device__ float g_c6[BATCH*16*28*28];
__device__ float g_c7[BATCH*16*24*24];
__device__ float g_c8[BATCH*16*8*8];

__device__ uint32_t g_w1HL[32*448];    // conv1 w, rows padded to 12, K=448
__device__ uint32_t g_wrHL[32*320];    // rconv w, k=t*32+ic, padded 288->320
__device__ uint32_t g_w4HL[16*2048];   // conv4 w

__device__ float g_wT5[1024*16];
__device__ float g_wT6[576*16];
__device__ float g_wT7[400*16];
__device__ float g_wT8[144*16];
__device__ float g_wTfc[1024*512];

__device__ float g_scale[512];
__device__ float g_shift[512];

// ------------------------- helpers -------------------------
__device__ __forceinline__ uint32_t smem_u32(const void* p) {
    uint32_t a;
    asm("{ .reg .u64 t; cvta.to.shared.u64 t, %1; cvt.u32.u64 %0, t; }" : "=r"(a) : "l"(p));
    return a;
}
__device__ __forceinline__ uint32_t sw128(uint32_t o) { return o ^ ((o >> 3) & 0x70); }

__device__ __forceinline__ uint32_t packHL(float v) {
    __nv_bfloat16 h = __float2bfloat16(v);
    float r = v - __bfloat162float(h);
    __nv_bfloat16 l = __float2bfloat16(r);
    uint16_t hb = *reinterpret_cast<uint16_t*>(&h);
    uint16_t lb = *reinterpret_cast<uint16_t*>(&l);
    return (uint32_t)hb | ((uint32_t)lb << 16);
}
// (v0,v1) -> hi-pair word and lo-pair word
__device__ __forceinline__ void split2(float a, float b, uint32_t& hi, uint32_t& lo) {
    __nv_bfloat162 h = __floats2bfloat162_rn(a, b);
    float ra = a - __bfloat162float(h.x);
    float rb = b - __bfloat162float(h.y);
    __nv_bfloat162 l = __floats2bfloat162_rn(ra, rb);
    hi = *reinterpret_cast<uint32_t*>(&h);
    lo = *reinterpret_cast<uint32_t*>(&l);
}

__device__ __forceinline__ void ldsm4(uint32_t* r, uint32_t addr) {
    asm volatile("ldmatrix.sync.aligned.m8n8.x4.shared.b16 {%0,%1,%2,%3}, [%4];"
                 : "=r"(r[0]), "=r"(r[1]), "=r"(r[2]), "=r"(r[3]) : "r"(addr));
}

__device__ __forceinline__ void mma_bf16(float* c,
        uint32_t a0, uint32_t a1, uint32_t a2, uint32_t a3,
        uint32_t b0, uint32_t b1) {
    asm volatile(
        "mma.sync.aligned.m16n8k16.row.col.f32.bf16.bf16.f32 "
        "{%0,%1,%2,%3}, {%4,%5,%6,%7}, {%8,%9}, {%0,%1,%2,%3};"
        : "+f"(c[0]), "+f"(c[1]), "+f"(c[2]), "+f"(c[3])
        : "r"(a0), "r"(a1), "r"(a2), "r"(a3), "r"(b0), "r"(b1));
}

// 3-term MMA block given prebuilt hi/lo fragment regs
#define MMA3(NT, ACCM)                                                              \
    do {                                                                            \
        _Pragma("unroll")                                                           \
        for (int nt = 0; nt < (NT); nt++) {                                         \
            float* cc2 = (ACCM) + nt*4;                                             \
            mma_bf16(cc2, ah0,ah1,ah2,ah3, b_hi[nt*2], b_hi[nt*2+1]);               \
            mma_bf16(cc2, al0,al1,al2,al3, b_hi[nt*2], b_hi[nt*2+1]);               \
            mma_bf16(cc2, ah0,ah1,ah2,ah3, b_lo[nt*2], b_lo[nt*2+1]);               \
        }                                                                           \
    } while (0)

// ------------------------- pre-pass kernels -------------------------
__global__ void split_x(const float* __restrict__ x) {
    int t = blockIdx.x * blockDim.x + threadIdx.x;
    if (t >= NX) return;
    float v0 = x[t];
    float v1 = (t + 1 < NX) ? x[t + 1] : 0.f;
    uint32_t h, l; split2(v0, v1, h, l);
    g_xH2[t] = h; g_xL2[t] = l;
}
__global__ void t_w1hl(const float* __restrict__ w) {
    int e = blockIdx.x * blockDim.x + threadIdx.x;
    if (e < 32*448) {
        int oc = e / 448, k = e - oc*448;
        int row = k / 12, col = k % 12;
        float v = 0.f;
        if (row < 33 && col < 11) {
            int ic = row / 11, ky = row % 11;
            v = w[oc*363 + ic*121 + ky*11 + col];
        }
        g_w1HL[e] = packHL(v);
    }
}
__global__ void t_wrhl(const float* __restrict__ w) {
    int e = blockIdx.x * blockDim.x + threadIdx.x;
    if (e < 32*320) {
        int oc = e / 320, k = e - oc*320;
        int t9 = k >> 5, ic = k & 31;
        g_wrHL[e] = (t9 < 9) ? packHL(w[oc*288 + ic*9 + t9]) : 0u;
    }
}
__global__ void t_w4hl(const float* __restrict__ w) {
    int e = blockIdx.x * blockDim.x + threadIdx.x;
    if (e < 16*2048) g_w4HL[e] = packHL(w[e]);
}

// norm + PReLU + channel-pair split: [b][pair q][y][x]
__global__ void act_kernel(const float* __restrict__ pa) {
    int t = blockIdx.x * blockDim.x + threadIdx.x;
    if (t >= NACT) return;
    int xx = t % 160;
    int y  = (t / 160) % 160;
    int q  = (t / 25600) % 16;
    int b  = t / 409600;
    int region = (y / 40) * 4 + (xx / 40);
    int c0 = 2*q;
    int base = ((b*32 + c0)*160 + y)*160 + xx;
    float v0 = g_bufA[base];
    float v1 = g_bufA[base + 25600];
    float a = __ldg(pa);
    float r0 = fmaf(v0, g_scale[region*32 + c0],     g_shift[region*32 + c0]);
    float r1 = fmaf(v1, g_scale[region*32 + c0 + 1], g_shift[region*32 + c0 + 1]);
    r0 = (r0 > 0.f) ? r0 : a * r0;
    r1 = (r1 > 0.f) ? r1 : a * r1;
    uint32_t h, l; split2(r0, r1, h, l);
    g_actH2[t] = h; g_actL2[t] = l;
}

// 2x2 maxpool with overlapping-pair split output
__global__ void pool_kernel() {
    int t = blockIdx.x * blockDim.x + threadIdx.x;
    if (t >= NPOOL) return;
    int xx = t % 80;
    int y  = (t / 80) % 80;
    int bc = t / 6400;
    const float* p = g_bufB + (bc * 160 + 2 * y) * 160 + 2 * xx;
    float v0 = fmaxf(fmaxf(p[0], p[1]), fmaxf(p[160], p[161]));
    float v1 = v0;
    if (xx < 79) v1 = fmaxf(fmaxf(p[2], p[3]), fmaxf(p[162], p[163]));
    uint32_t h, l; split2(v0, v1, h, l);
    g_poolH2[t] = h; g_poolL2[t] = l;
}

// ------------------------- conv1: M=512/CTA (64/warp), N=32, K=448 -------------------------
#define C1_SM 57344   // B_HI 7*4096 @0, B_LO @28672
__global__ void __launch_bounds__(256, 2) conv1_mma(const float* __restrict__ bias) {
    extern __shared__ char smem[];
    __shared__ int soffs[224];
    uint32_t sb = smem_u32(smem);
    int tid = threadIdx.x, wid = tid >> 5, lane = tid & 31;

    for (int pr = tid; pr < 224; pr += 256) {
        int off = 0;
        if (pr < 198) {
            int k = 2*pr, row = k / 12, col = k % 12;
            off = (row/11)*28900 + (row%11)*170 + col;
        }
        soffs[pr] = off;
    }
    // stage full B (7 chunks)
#pragma unroll
    for (int e = tid; e < 7168; e += 256) {
        int chunk = e >> 10, idx = e & 1023;
        int oc = idx >> 5, i = idx & 31;
        uint2 w2 = __ldg((const uint2*)(g_w1HL + oc*448 + chunk*64 + 2*i));
        uint32_t off = chunk*4096 + sw128((uint32_t)(oc*128 + i*4));
        *(uint32_t*)(smem + off)         = __byte_perm(w2.x, w2.y, 0x5410);
        *(uint32_t*)(smem + 28672 + off) = __byte_perm(w2.x, w2.y, 0x7632);
    }
    // pixel word-offsets: h = mt*2+half; pixel = blk*512 + wid*64 + mt*16 + half*8 + lane>>2
    int xoff[8];
#pragma unroll
    for (int h = 0; h < 8; h++) {
        int pp = blockIdx.x*512 + wid*64 + (h>>1)*16 + (h&1)*8 + (lane>>2);
        int xo = pp % 160, yo = (pp/160) % 160, b = pp / 25600;
        xoff[h] = b*86700 + yo*170 + xo;
    }
    float acc[64];
#pragma unroll
    for (int i = 0; i < 64; i++) acc[i] = 0.f;
    __syncthreads();

    for (int c = 0; c < 7; c++) {
        uint32_t bHi = sb + c*4096;
        uint32_t bLo = sb + 28672 + c*4096;
#pragma unroll
        for (int ks = 0; ks < 4; ks++) {
            int prA = c*32 + ks*8 + (lane & 3);
            int oA = soffs[prA], oB = soffs[prA + 4];
            uint32_t b_hi[8], b_lo[8];
            uint32_t bbyte = (uint32_t)(((((lane >> 4) << 3) + (lane & 7))*128) + (ks*16 + (lane & 8))*2);
            ldsm4(&b_hi[0], bHi + sw128(bbyte));
            ldsm4(&b_hi[4], bHi + sw128(bbyte) + 2048);
            ldsm4(&b_lo[0], bLo + sw128(bbyte));
            ldsm4(&b_lo[4], bLo + sw128(bbyte) + 2048);
#pragma unroll
            for (int mt = 0; mt < 4; mt++) {
                int q0 = xoff[mt*2], q1 = xoff[mt*2 + 1];
                uint32_t ah0 = __ldg(g_xH2 + q0 + oA);
                uint32_t ah1 = __ldg(g_xH2 + q1 + oA);
                uint32_t ah2 = __ldg(g_xH2 + q0 + oB);
                uint32_t ah3 = __ldg(g_xH2 + q1 + oB);
                uint32_t al0 = __ldg(g_xL2 + q0 + oA);
                uint32_t al1 = __ldg(g_xL2 + q1 + oA);
                uint32_t al2 = __ldg(g_xL2 + q0 + oB);
                uint32_t al3 = __ldg(g_xL2 + q1 + oB);
                MMA3(4, acc + mt*16);
            }
        }
    }
    // 4-phase epilogue (128 rows per phase)
    __syncthreads();
    float* stg = (float*)smem;
#pragma unroll
    for (int h = 0; h < 4; h++) {
        if ((wid >> 1) == h) {
#pragma unroll
            for (int mt = 0; mt < 4; mt++)
#pragma unroll
                for (int nt = 0; nt < 4; nt++)
#pragma unroll
                    for (int r = 0; r < 4; r++) {
                        int row = (wid & 1)*64 + mt*16 + (lane >> 2) + ((r >> 1) << 3);
                        int col = nt*8 + ((lane & 3) << 1) + (r & 1);
                        stg[row*33 + col] = acc[(mt*4 + nt)*4 + r];
                    }
        }
        __syncthreads();
        {
            int r  = tid & 127;
            int j0 = (tid >> 7) * 16;
            int pp = blockIdx.x * 512 + h * 128 + r;
            int xo2 = pp % 160, yo2 = (pp / 160) % 160, b2 = pp / 25600;
            float* op = g_bufA + (b2 * 32 * 160 + yo2) * 160 + xo2;
#pragma unroll
            for (int j = 0; j < 16; j++) {
                int jj = j0 + j;
                op[jj * 25600] = stg[r*33 + jj] + __ldg(bias + jj);
            }
        }
        __syncthreads();
    }
}

// ------------------------- stats -------------------------
__global__ void stats_kernel(const float* __restrict__ gamma, const float* __restrict__ beta) {
    int rc = blockIdx.x;
    int region = rc >> 5;
    int c  = rc & 31;
    int ri = region >> 2, ci = region & 3;
    int tid = threadIdx.x;

    double s = 0.0, ss = 0.0;
    for (int i = tid; i < 64 * 1600; i += 256) {
        int b = i / 1600;
        int p = i - b * 1600;
        int y = ri * 40 + p / 40;
        int xx = ci * 40 + (p % 40);
        float v = g_bufA[((b * 32 + c) * 160 + y) * 160 + xx];
        s += (double)v; ss += (double)v * (double)v;
    }
    __shared__ double sh_s[256], sh_ss[256];
    sh_s[tid] = s; sh_ss[tid] = ss;
    __syncthreads();
    for (int off = 128; off > 0; off >>= 1) {
        if (tid < off) { sh_s[tid] += sh_s[tid + off]; sh_ss[tid] += sh_ss[tid + off]; }
        __syncthreads();
    }
    if (tid == 0) {
        double mean = sh_s[0] / 102400.0;
        double var  = sh_ss[0] / 102400.0 - mean * mean;
        float sc = __ldg(gamma + c) * rsqrtf((float)var + 1e-5f);
        g_scale[rc] = sc;
        g_shift[rc] = __ldg(beta + c) - (float)mean * sc;
    }
}

// ------------------------- rconv: M=512/CTA (64/warp), N=32, K=320 -------------------------
#define RC_SM 40960   // B_HI 5*4096 @0, B_LO @20480
__global__ void __launch_bounds__(256, 2) rconv_mma(const float* __restrict__ bias) {
    extern __shared__ char smem[];
    uint32_t sb = smem_u32(smem);
    int tid = threadIdx.x, wid = tid >> 5, lane = tid & 31;

#pragma unroll
    for (int e = tid; e < 5120; e += 256) {
        int chunk = e >> 10, idx = e & 1023;
        int oc = idx >> 5, i = idx & 31;
        uint2 w2 = __ldg((const uint2*)(g_wrHL + oc*320 + chunk*64 + 2*i));
        uint32_t off = chunk*4096 + sw128((uint32_t)(oc*128 + i*4));
        *(uint32_t*)(smem + off)         = __byte_perm(w2.x, w2.y, 0x5410);
        *(uint32_t*)(smem + 20480 + off) = __byte_perm(w2.x, w2.y, 0x7632);
    }

    int px[8], msk[8];
#pragma unroll
    for (int h = 0; h < 8; h++) {
        int pp = blockIdx.x*512 + wid*64 + (h>>1)*16 + (h&1)*8 + (lane>>2);
        int xo = pp % 160, yo = (pp/160) % 160, b = pp / 25600;
        px[h] = b*409600 + yo*160 + xo;
        int lx = xo % 40, ly = yo % 40;
        int ry = ((ly > 0) ? 1 : 0) | 2 | ((ly < 39) ? 4 : 0);
        int cx = ((lx > 0) ? 1 : 0) | 2 | ((lx < 39) ? 4 : 0);
        int m = 0;
#pragma unroll
        for (int ty = 0; ty < 3; ty++)
#pragma unroll
            for (int tx = 0; tx < 3; tx++)
                if (((ry >> ty) & 1) && ((cx >> tx) & 1)) m |= 1 << (ty*3 + tx);
        msk[h] = m;
    }

    float acc[64];
#pragma unroll
    for (int i = 0; i < 64; i++) acc[i] = 0.f;
    __syncthreads();

    for (int c = 0; c < 5; c++) {
        uint32_t bHi = sb + c*4096;
        uint32_t bLo = sb + 20480 + c*4096;
        int t0 = 2*c, t1 = 2*c + 1;
        int ty0 = t0 / 3, ty1 = t1 / 3;
        int dd0 = (ty0 - 1)*160 + (t0 - 3*ty0 - 1);
        int dd1 = (ty1 - 1)*160 + (t1 - 3*ty1 - 1);
#pragma unroll
        for (int ks = 0; ks < 4; ks++) {
            bool useT1 = (ks >= 2);
            int t   = useT1 ? t1 : t0;
            int dd  = useT1 ? dd1 : dd0;
            bool tv = (t < 9);
            int q   = (ks & 1)*8 + (lane & 3);   // channel-pair plane
            int co0 = q*25600 + dd;
            int co1 = co0 + 4*25600;
            uint32_t b_hi[8], b_lo[8];
            uint32_t bbyte = (uint32_t)(((((lane >> 4) << 3) + (lane & 7))*128) + (ks*16 + (lane & 8))*2);
            ldsm4(&b_hi[0], bHi + sw128(bbyte));
            ldsm4(&b_hi[4], bHi + sw128(bbyte) + 2048);
            ldsm4(&b_lo[0], bLo + sw128(bbyte));
            ldsm4(&b_lo[4], bLo + sw128(bbyte) + 2048);
#pragma unroll
            for (int mt = 0; mt < 4; mt++) {
                bool ok0 = tv && ((msk[mt*2]     >> t) & 1);
                bool ok1 = tv && ((msk[mt*2 + 1] >> t) & 1);
                int q0 = px[mt*2], q1 = px[mt*2 + 1];
                uint32_t ah0 = ok0 ? __ldg(g_actH2 + q0 + co0) : 0u;
                uint32_t ah1 = ok1 ? __ldg(g_actH2 + q1 + co0) : 0u;
                uint32_t ah2 = ok0 ? __ldg(g_actH2 + q0 + co1) : 0u;
                uint32_t ah3 = ok1 ? __ldg(g_actH2 + q1 + co1) : 0u;
                uint32_t al0 = ok0 ? __ldg(g_actL2 + q0 + co0) : 0u;
                uint32_t al1 = ok1 ? __ldg(g_actL2 + q1 + co0) : 0u;
                uint32_t al2 = ok0 ? __ldg(g_actL2 + q0 + co1) : 0u;
                uint32_t al3 = ok1 ? __ldg(g_actL2 + q1 + co1) : 0u;
                MMA3(4, acc + mt*16);
            }
        }
    }
    __syncthreads();
    float* stg = (float*)smem;
#pragma unroll
    for (int h = 0; h < 4; h++) {
        if ((wid >> 1) == h) {
#pragma unroll
            for (int mt = 0; mt < 4; mt++)
#pragma unroll
                for (int nt = 0; nt < 4; nt++)
#pragma unroll
                    for (int r = 0; r < 4; r++) {
                        int row = (wid & 1)*64 + mt*16 + (lane >> 2) + ((r >> 1) << 3);
                        int col = nt*8 + ((lane & 3) << 1) + (r & 1);
                        stg[row*33 + col] = acc[(mt*4 + nt)*4 + r];
                    }
        }
        __syncthreads();
        {
            int r  = tid & 127;
            int j0 = (tid >> 7) * 16;
            int pp = blockIdx.x * 512 + h * 128 + r;
            int xo2 = pp % 160, yo2 = (pp / 160) % 160, b2 = pp / 25600;
            float* op = g_bufB + (b2 * 32 * 160 + yo2) * 160 + xo2;
#pragma unroll
            for (int j = 0; j < 16; j++) {
                int jj = j0 + j;
                op[jj * 25600] = stg[r*33 + jj] + __ldg(bias + jj);
            }
        }
        __syncthreads();
    }
}

// ------------------------- conv4: M=256, N=16, K=2048, pair loads -------------------------
#define CONV4_M (BATCH * 73 * 73)
#define C4_SM 32768
__global__ void __launch_bounds__(256) conv4_mma(const float* __restrict__ bias) {
    extern __shared__ char smem[];
    uint32_t sb = smem_u32(smem);
    int tid = threadIdx.x, wid = tid >> 5, lane = tid & 31;

    int px[4];
    bool pvh[4];
#pragma unroll
    for (int h = 0; h < 4; h++) {
        int pp = blockIdx.x*256 + wid*32 + (h>>1)*16 + (h&1)*8 + (lane>>2);
        pvh[h] = pp < CONV4_M;
        int pq = pvh[h] ? pp : 0;
        int xo = pq % 73, yo = (pq/73) % 73, b = pq / 5329;
        px[h] = b*204800 + yo*80 + xo;
    }

    float acc[16];
#pragma unroll
    for (int i = 0; i < 16; i++) acc[i] = 0.f;

    for (int qt = 0; qt < 4; qt++) {
        if (qt) __syncthreads();
#pragma unroll
        for (int e = tid; e < 4096; e += 256) {
            int chunk = e >> 9, idx = e & 511;
            int oc = idx >> 5, i = idx & 31;
            uint2 w2 = __ldg((const uint2*)(g_w4HL + oc*2048 + qt*512 + chunk*64 + 2*i));
            uint32_t off = chunk*2048 + sw128((uint32_t)(oc*128 + i*4));
            *(uint32_t*)(smem + off)         = __byte_perm(w2.x, w2.y, 0x5410);
            *(uint32_t*)(smem + 16384 + off) = __byte_perm(w2.x, w2.y, 0x7632);
        }
        __syncthreads();
#pragma unroll 1
        for (int cc = 0; cc < 8; cc++) {
            int c = qt*8 + cc;
            uint32_t bHi = sb + cc*2048;
            uint32_t bLo = sb + 16384 + cc*2048;
#pragma unroll
            for (int ks = 0; ks < 4; ks++) {
                int k  = c*64 + ks*16 + ((lane & 3) << 1);
                int co = (k >> 6)*6400 + ((k >> 3) & 7)*80 + (k & 7);
                uint32_t b_hi[4], b_lo[4];
                uint32_t bbyte = (uint32_t)(((((lane >> 4) << 3) + (lane & 7))*128) + (ks*16 + (lane & 8))*2);
                ldsm4(b_hi, bHi + sw128(bbyte));
                ldsm4(b_lo, bLo + sw128(bbyte));
#pragma unroll
                for (int mt = 0; mt < 2; mt++) {
                    bool v0 = pvh[mt*2], v1 = pvh[mt*2 + 1];
                    int q0 = px[mt*2], q1 = px[mt*2 + 1];
                    uint32_t ah0 = v0 ? __ldg(g_poolH2 + q0 + co)      : 0u;
                    uint32_t ah1 = v1 ? __ldg(g_poolH2 + q1 + co)      : 0u;
                    uint32_t ah2 = v0 ? __ldg(g_poolH2 + q0 + co + 80) : 0u;
                    uint32_t ah3 = v1 ? __ldg(g_poolH2 + q1 + co + 80) : 0u;
                    uint32_t al0 = v0 ? __ldg(g_poolL2 + q0 + co)      : 0u;
                    uint32_t al1 = v1 ? __ldg(g_poolL2 + q1 + co)      : 0u;
                    uint32_t al2 = v0 ? __ldg(g_poolL2 + q0 + co + 80) : 0u;
                    uint32_t al3 = v1 ? __ldg(g_poolL2 + q1 + co + 80) : 0u;
                    MMA3(2, acc + mt*8);
                }
            }
        }
    }
    __syncthreads();
    float* stg = (float*)smem;
#pragma unroll
    for (int h = 0; h < 2; h++) {
        if ((wid >> 2) == h) {
#pragma unroll
            for (int mt = 0; mt < 2; mt++)
#pragma unroll
                for (int nt = 0; nt < 2; nt++)
#pragma unroll
                    for (int r = 0; r < 4; r++) {
                        int row = (wid & 3)*32 + mt*16 + (lane >> 2) + ((r >> 1) << 3);
                        int col = nt*8 + ((lane & 3) << 1) + (r & 1);
                        stg[row*17 + col] = acc[(mt*2 + nt)*4 + r];
                    }
        }
        __syncthreads();
        {
            int r  = tid & 127;
            int j0 = (tid >> 7) * 8;
            int pq = blockIdx.x * 256 + h * 128 + r;
            if (pq < CONV4_M) {
                int xo2 = pq % 73, yo2 = (pq / 73) % 73, b2 = pq / 5329;
                float* op = g_c4 + (b2 * 16 * 73 + yo2) * 73 + xo2;
#pragma unroll
                for (int j = 0; j < 8; j++) {
                    int jj = j0 + j;
                    op[jj * 5329] = stg[r*17 + jj] + __ldg(bias + jj);
                }
            }
        }
        __syncthreads();
    }
}

// ------------------------- weight transpose for remaining direct convs -------------------------
#define DEFINE_TRANS(NAME, OC, R, DST)                                        \
__global__ void NAME(const float* __restrict__ w) {                           \
    int e = blockIdx.x * blockDim.x + threadIdx.x;                            \
    if (e < (OC)*(R)) {                                                       \
        int oc = e / (R);                                                     \
        int r  = e - oc * (R);                                                \
        DST[r*(OC) + oc] = w[e];                                              \
    }                                                                         \
}
DEFINE_TRANS(t_w5,  16, 1024, g_wT5)
DEFINE_TRANS(t_w6,  16,  576, g_wT6)
DEFINE_TRANS(t_w7,  16,  400, g_wT7)
DEFINE_TRANS(t_w8,  16,  144, g_wT8)
DEFINE_TRANS(t_wfc, 512, 1024, g_wTfc)

// ------------------------- conv5: reads g_c4 -------------------------
#define DEFINE_CONV16(NAME, IC, K, S, IH, IW, OH, OW, INBUF, WTBUF, OUTBUF)          \
__global__ void __launch_bounds__(128) NAME(const float* __restrict__ bias) {        \
    const int XP  = ((OW) + 1) / 2;                                                  \
    const int OFF = (OW) - XP;                                                       \
    int t = blockIdx.x * 128 + threadIdx.x;                                          \
    if (t >= BATCH * (OH) * XP) return;                                              \
    int xo = t % XP;                                                                 \
    int yo = (t / XP) % (OH);                                                        \
    int b  = t / (XP * (OH));                                                        \
    float a0[16], a1[16];                                                            \
    _Pragma("unroll")                                                                \
    for (int j = 0; j < 16; j++) { float bv = __ldg(bias + j); a0[j] = bv; a1[j] = bv; } \
    for (int ic = 0; ic < (IC); ic++) {                                              \
        const float* inp = INBUF + ((b*(IC) + ic)*(IH) + yo*(S))*(IW) + xo*(S);      \
        _Pragma("unroll 1")                                                          \
        for (int ky = 0; ky < (K); ky++) {                                           \
            const float* row = inp + ky*(IW);                                        \
            const float4* wrow = (const float4*)(WTBUF + (ic*(K)*(K) + ky*(K))*16);  \
            _Pragma("unroll")                                                        \
            for (int kx = 0; kx < (K); kx++) {                                       \
                float v0 = __ldg(row + kx);                                          \
                float v1 = __ldg(row + OFF*(S) + kx);                                \
                _Pragma("unroll")                                                    \
                for (int j = 0; j < 4; j++) {                                        \
                    float4 w4 = __ldg(wrow + kx*4 + j);                              \
                    a0[4*j+0] = fmaf(v0, w4.x, a0[4*j+0]); a1[4*j+0] = fmaf(v1, w4.x, a1[4*j+0]); \
                    a0[4*j+1] = fmaf(v0, w4.y, a0[4*j+1]); a1[4*j+1] = fmaf(v1, w4.y, a1[4*j+1]); \
                    a0[4*j+2] = fmaf(v0, w4.z, a0[4*j+2]); a1[4*j+2] = fmaf(v1, w4.z, a1[4*j+2]); \
                    a0[4*j+3] = fmaf(v0, w4.w, a0[4*j+3]); a1[4*j+3] = fmaf(v1, w4.w, a1[4*j+3]); \
                }                                                                    \
            }                                                                        \
        }                                                                            \
    }                                                                                \
    float* op = OUTBUF + (b*16*(OH) + yo)*(OW) + xo;                                 \
    _Pragma("unroll")                                                                \
    for (int j = 0; j < 16; j++) {                                                   \
        op[j*(OH)*(OW)]       = a0[j];                                               \
        op[j*(OH)*(OW) + OFF] = a1[j];                                               \
    }                                                                                \
}

DEFINE_CONV16(conv5_kernel, 16, 8, 2, 73, 73, 33, 33, g_c4, g_wT5, g_c5)
DEFINE_CONV16(conv6_kernel, 16, 6, 1, 33, 33, 28, 28, g_c5, g_wT6, g_c6)
DEFINE_CONV16(conv7_kernel, 16, 5, 1, 28, 28, 24, 24, g_c6, g_wT7, g_c7)
DEFINE_CONV16(conv8_kernel, 16, 3, 3, 24, 24,  8,  8, g_c7, g_wT8, g_c8)

// ------------------------- FC -------------------------
__global__ void fc_kernel(const float* __restrict__ bias, float* __restrict__ out) {
    __shared__ float sm[1024];
    int b = blockIdx.x;
    int o = threadIdx.x;
    sm[o]       = g_c8[b * 1024 + o];
    sm[o + 512] = g_c8[b * 1024 + o + 512];
    __syncthreads();
    float acc = __ldg(bias + o);
#pragma unroll 4
    for (int k = 0; k < 1024; k++)
        acc = fmaf(sm[k], g_wTfc[k * 512 + o], acc);
    out[b * 512 + o] = acc;
}

// ------------------------- launch -------------------------
static inline int gridFor(long n, int bs) { return (int)((n + bs - 1) / bs); }

extern "C" void kernel_launch(void* const* d_in, const int* in_sizes, int n_in,
                              void* d_out, int out_size) {
    const float* x        = (const float*)d_in[0];
    const float* conv1_w  = (const float*)d_in[1];
    const float* conv1_b  = (const float*)d_in[2];
    const float* bn_gamma = (const float*)d_in[3];
    const float* bn_beta  = (const float*)d_in[4];
    const float* prelu_a  = (const float*)d_in[5];
    const float* rconv_w  = (const float*)d_in[6];
    const float* rconv_b  = (const float*)d_in[7];
    const float* conv4_w  = (const float*)d_in[8];
    const float* conv4_b  = (const float*)d_in[9];
    const float* conv5_b  = (const float*)d_in[11];
    const float* conv6_b  = (const float*)d_in[13];
    const float* conv7_b  = (const float*)d_in[15];
    const float* conv8_b  = (const float*)d_in[17];
    const float* fc_b     = (const float*)d_in[19];
    float* out = (float*)d_out;

    cudaFuncSetAttribute(conv1_mma, cudaFuncAttributeMaxDynamicSharedMemorySize, C1_SM);
    cudaFuncSetAttribute(rconv_mma, cudaFuncAttributeMaxDynamicSharedMemorySize, RC_SM);
    cudaFuncSetAttribute(conv4_mma, cudaFuncAttributeMaxDynamicSharedMemorySize, C4_SM);

    // launches ordered so conv1_mma is the 4th launch (ncu captures it)
    split_x<<<gridFor(NX, 256), 256>>>(x);
    t_w1hl<<<gridFor(32*448, 256), 256>>>(conv1_w);
    t_wrhl<<<gridFor(32*320, 256), 256>>>(rconv_w);
    conv1_mma<<<3200, 256, C1_SM>>>(conv1_b);

    t_w4hl<<<gridFor(16*2048, 256), 256>>>(conv4_w);
    t_w5 <<<gridFor(16*1024, 256), 256>>>((const float*)d_in[10]);
    t_w6 <<<gridFor(16*576,  256), 256>>>((const float*)d_in[12]);
    t_w7 <<<gridFor(16*400,  256), 256>>>((const float*)d_in[14]);
    t_w8 <<<gridFor(16*144,  256), 256>>>((const float*)d_in[16]);
    t_wfc<<<gridFor(512*1024,256), 256>>>((const float*)d_in[18]);

    stats_kernel<<<512, 256>>>(bn_gamma, bn_beta);
    act_kernel<<<gridFor(NACT, 256), 256>>>(prelu_a);
    rconv_mma<<<3200, 256, RC_SM>>>(rconv_b);
    pool_kernel<<<gridFor(NPOOL, 256), 256>>>();

    conv4_mma<<<gridFor(CONV4_M, 256), 256, C4_SM>>>(conv4_b);
    conv5_kernel<<<gridFor((long)BATCH*33*17, 128), 128>>>(conv5_b);
    conv6_kernel<<<gridFor((long)BATCH*28*14, 128), 128>>>(conv6_b);
    conv7_kernel<<<gridFor((long)BATCH*24*12, 128), 128>>>(conv7_b);
    conv8_kernel<<<gridFor((long)BATCH*8*4,   128), 128>>>(conv8_b);

    fc_kernel<<<BATCH, 512>>>(fc_b, out);
}

// round 10
// speedup vs baseline: 1.0328x; 1.0328x over previous
#include <cuda_runtime.h>
#include <cuda_bf16.h>
#include <cstdint>

#define BATCH 64

// ------------------------- scratch (no allocs allowed) -------------------------
__device__ float    g_bufA[BATCH*32*160*160];   // conv1 out (fp32, for stats)
__device__ float    g_bufB[BATCH*32*160*160];   // rconv out (fp32, for pool)
#define NX (BATCH*3*170*170)
__device__ uint32_t g_xH2[NX];                  // input: overlapping bf16-hi pairs
__device__ uint32_t g_xL2[NX];
#define NACT (BATCH*16*160*160)
__device__ uint32_t g_actH2[NACT];              // act: channel-pair planes [b][16][160][160]
__device__ uint32_t g_actL2[NACT];
#define NPOOL (BATCH*32*80*80)
__device__ uint32_t g_poolH2[NPOOL];            // pool: overlapping pairs along x
__device__ uint32_t g_poolL2[NPOOL];
__device__ float g_c4[BATCH*16*73*73];
__device__ float g_c5[BATCH*16*33*33];
__device__ float g_c6[BATCH*16*28*28];
__device__ float g_c7[BATCH*16*24*24];
__device__ float g_c8[BATCH*16*8*8];

__device__ uint32_t g_w1HL[32*448];    // conv1 w, rows padded to 12, K=448
__device__ uint32_t g_wrHL[32*320];    // rconv w, k=t*32+ic, padded 288->320
__device__ uint32_t g_w4HL[16*2048];   // conv4 w

__device__ float g_wT5[1024*16];
__device__ float g_wT6[576*16];
__device__ float g_wT7[400*16];
__device__ float g_wT8[144*16];
__device__ float g_wTfc[1024*512];

__device__ float g_scale[512];
__device__ float g_shift[512];

// ------------------------- helpers -------------------------
__device__ __forceinline__ uint32_t smem_u32(const void* p) {
    uint32_t a;
    asm("{ .reg .u64 t; cvta.to.shared.u64 t, %1; cvt.u32.u64 %0, t; }" : "=r"(a) : "l"(p));
    return a;
}
__device__ __forceinline__ uint32_t sw128(uint32_t o) { return o ^ ((o >> 3) & 0x70); }

__device__ __forceinline__ uint32_t packHL(float v) {
    __nv_bfloat16 h = __float2bfloat16(v);
    float r = v - __bfloat162float(h);
    __nv_bfloat16 l = __float2bfloat16(r);
    uint16_t hb = *reinterpret_cast<uint16_t*>(&h);
    uint16_t lb = *reinterpret_cast<uint16_t*>(&l);
    return (uint32_t)hb | ((uint32_t)lb << 16);
}
__device__ __forceinline__ void split2(float a, float b, uint32_t& hi, uint32_t& lo) {
    __nv_bfloat162 h = __floats2bfloat162_rn(a, b);
    float ra = a - __bfloat162float(h.x);
    float rb = b - __bfloat162float(h.y);
    __nv_bfloat162 l = __floats2bfloat162_rn(ra, rb);
    hi = *reinterpret_cast<uint32_t*>(&h);
    lo = *reinterpret_cast<uint32_t*>(&l);
}

__device__ __forceinline__ void ldsm4(uint32_t* r, uint32_t addr) {
    asm volatile("ldmatrix.sync.aligned.m8n8.x4.shared.b16 {%0,%1,%2,%3}, [%4];"
                 : "=r"(r[0]), "=r"(r[1]), "=r"(r[2]), "=r"(r[3]) : "r"(addr));
}

__device__ __forceinline__ void mma_bf16(float* c,
        uint32_t a0, uint32_t a1, uint32_t a2, uint32_t a3,
        uint32_t b0, uint32_t b1) {
    asm volatile(
        "mma.sync.aligned.m16n8k16.row.col.f32.bf16.bf16.f32 "
        "{%0,%1,%2,%3}, {%4,%5,%6,%7}, {%8,%9}, {%0,%1,%2,%3};"
        : "+f"(c[0]), "+f"(c[1]), "+f"(c[2]), "+f"(c[3])
        : "r"(a0), "r"(a1), "r"(a2), "r"(a3), "r"(b0), "r"(b1));
}

#define MMA3(NT, ACCM)                                                              \
    do {                                                                            \
        _Pragma("unroll")                                                           \
        for (int nt = 0; nt < (NT); nt++) {                                         \
            float* cc2 = (ACCM) + nt*4;                                             \
            mma_bf16(cc2, ah0,ah1,ah2,ah3, b_hi[nt*2], b_hi[nt*2+1]);               \
            mma_bf16(cc2, al0,al1,al2,al3, b_hi[nt*2], b_hi[nt*2+1]);               \
            mma_bf16(cc2, ah0,ah1,ah2,ah3, b_lo[nt*2], b_lo[nt*2+1]);               \
        }                                                                           \
    } while (0)

// ------------------------- pre-pass kernels -------------------------
__global__ void split_x(const float* __restrict__ x) {
    int t = blockIdx.x * blockDim.x + threadIdx.x;
    if (t >= NX) return;
    float v0 = x[t];
    float v1 = (t + 1 < NX) ? x[t + 1] : 0.f;
    uint32_t h, l; split2(v0, v1, h, l);
    g_xH2[t] = h; g_xL2[t] = l;
}
__global__ void t_w1hl(const float* __restrict__ w) {
    int e = blockIdx.x * blockDim.x + threadIdx.x;
    if (e < 32*448) {
        int oc = e / 448, k = e - oc*448;
        int row = k / 12, col = k % 12;
        float v = 0.f;
        if (row < 33 && col < 11) {
            int ic = row / 11, ky = row % 11;
            v = w[oc*363 + ic*121 + ky*11 + col];
        }
        g_w1HL[e] = packHL(v);
    }
}
__global__ void t_wrhl(const float* __restrict__ w) {
    int e = blockIdx.x * blockDim.x + threadIdx.x;
    if (e < 32*320) {
        int oc = e / 320, k = e - oc*320;
        int t9 = k >> 5, ic = k & 31;
        g_wrHL[e] = (t9 < 9) ? packHL(w[oc*288 + ic*9 + t9]) : 0u;
    }
}
__global__ void t_w4hl(const float* __restrict__ w) {
    int e = blockIdx.x * blockDim.x + threadIdx.x;
    if (e < 16*2048) g_w4HL[e] = packHL(w[e]);
}

// norm + PReLU + channel-pair split: [b][pair q][y][x]
__global__ void act_kernel(const float* __restrict__ pa) {
    int t = blockIdx.x * blockDim.x + threadIdx.x;
    if (t >= NACT) return;
    int xx = t % 160;
    int y  = (t / 160) % 160;
    int q  = (t / 25600) % 16;
    int b  = t / 409600;
    int region = (y / 40) * 4 + (xx / 40);
    int c0 = 2*q;
    int base = ((b*32 + c0)*160 + y)*160 + xx;
    float v0 = g_bufA[base];
    float v1 = g_bufA[base + 25600];
    float a = __ldg(pa);
    float r0 = fmaf(v0, g_scale[region*32 + c0],     g_shift[region*32 + c0]);
    float r1 = fmaf(v1, g_scale[region*32 + c0 + 1], g_shift[region*32 + c0 + 1]);
    r0 = (r0 > 0.f) ? r0 : a * r0;
    r1 = (r1 > 0.f) ? r1 : a * r1;
    uint32_t h, l; split2(r0, r1, h, l);
    g_actH2[t] = h; g_actL2[t] = l;
}

// 2x2 maxpool with overlapping-pair split output
__global__ void pool_kernel() {
    int t = blockIdx.x * blockDim.x + threadIdx.x;
    if (t >= NPOOL) return;
    int xx = t % 80;
    int y  = (t / 80) % 80;
    int bc = t / 6400;
    const float* p = g_bufB + (bc * 160 + 2 * y) * 160 + 2 * xx;
    float v0 = fmaxf(fmaxf(p[0], p[1]), fmaxf(p[160], p[161]));
    float v1 = v0;
    if (xx < 79) v1 = fmaxf(fmaxf(p[2], p[3]), fmaxf(p[162], p[163]));
    uint32_t h, l; split2(v0, v1, h, l);
    g_poolH2[t] = h; g_poolL2[t] = l;
}

// ------------------------- conv1: M=256/CTA (32/warp), N=32, K=448, pair loads -------------------------
#define C1_SM 57344   // B_HI 7*4096 @0, B_LO @28672
__global__ void __launch_bounds__(256) conv1_mma(const float* __restrict__ bias) {
    extern __shared__ char smem[];
    __shared__ int soffs[224];
    uint32_t sb = smem_u32(smem);
    int tid = threadIdx.x, wid = tid >> 5, lane = tid & 31;

    for (int pr = tid; pr < 224; pr += 256) {
        int off = 0;
        if (pr < 198) {
            int k = 2*pr, row = k / 12, col = k % 12;
            off = (row/11)*28900 + (row%11)*170 + col;
        }
        soffs[pr] = off;
    }
    // stage full B (7 chunks)
#pragma unroll
    for (int e = tid; e < 7168; e += 256) {
        int chunk = e >> 10, idx = e & 1023;
        int oc = idx >> 5, i = idx & 31;
        uint2 w2 = __ldg((const uint2*)(g_w1HL + oc*448 + chunk*64 + 2*i));
        uint32_t off = chunk*4096 + sw128((uint32_t)(oc*128 + i*4));
        *(uint32_t*)(smem + off)         = __byte_perm(w2.x, w2.y, 0x5410);
        *(uint32_t*)(smem + 28672 + off) = __byte_perm(w2.x, w2.y, 0x7632);
    }
    // 4 pixel word-offsets: h = mt*2+half; pixel = blk*256 + wid*32 + mt*16 + half*8 + lane>>2
    int xoff[4];
#pragma unroll
    for (int h = 0; h < 4; h++) {
        int pp = blockIdx.x*256 + wid*32 + (h>>1)*16 + (h&1)*8 + (lane>>2);
        int xo = pp % 160, yo = (pp/160) % 160, b = pp / 25600;
        xoff[h] = b*86700 + yo*170 + xo;
    }
    float acc[32];
#pragma unroll
    for (int i = 0; i < 32; i++) acc[i] = 0.f;
    __syncthreads();

    for (int c = 0; c < 7; c++) {
        uint32_t bHi = sb + c*4096;
        uint32_t bLo = sb + 28672 + c*4096;
#pragma unroll
        for (int ks = 0; ks < 4; ks++) {
            int prA = c*32 + ks*8 + (lane & 3);
            int oA = soffs[prA], oB = soffs[prA + 4];
            uint32_t b_hi[8], b_lo[8];
            uint32_t bbyte = (uint32_t)(((((lane >> 4) << 3) + (lane & 7))*128) + (ks*16 + (lane & 8))*2);
            ldsm4(&b_hi[0], bHi + sw128(bbyte));
            ldsm4(&b_hi[4], bHi + sw128(bbyte) + 2048);
            ldsm4(&b_lo[0], bLo + sw128(bbyte));
            ldsm4(&b_lo[4], bLo + sw128(bbyte) + 2048);
#pragma unroll
            for (int mt = 0; mt < 2; mt++) {
                int q0 = xoff[mt*2], q1 = xoff[mt*2 + 1];
                uint32_t ah0 = __ldg(g_xH2 + q0 + oA);
                uint32_t ah1 = __ldg(g_xH2 + q1 + oA);
                uint32_t ah2 = __ldg(g_xH2 + q0 + oB);
                uint32_t ah3 = __ldg(g_xH2 + q1 + oB);
                uint32_t al0 = __ldg(g_xL2 + q0 + oA);
                uint32_t al1 = __ldg(g_xL2 + q1 + oA);
                uint32_t al2 = __ldg(g_xL2 + q0 + oB);
                uint32_t al3 = __ldg(g_xL2 + q1 + oB);
                MMA3(4, acc + mt*16);
            }
        }
    }
    // 2-phase epilogue
    __syncthreads();
    float* stg = (float*)smem;
#pragma unroll
    for (int h = 0; h < 2; h++) {
        if ((wid >> 2) == h) {
#pragma unroll
            for (int mt = 0; mt < 2; mt++)
#pragma unroll
                for (int nt = 0; nt < 4; nt++)
#pragma unroll
                    for (int r = 0; r < 4; r++) {
                        int row = (wid & 3)*32 + mt*16 + (lane >> 2) + ((r >> 1) << 3);
                        int col = nt*8 + ((lane & 3) << 1) + (r & 1);
                        stg[row*33 + col] = acc[(mt*4 + nt)*4 + r];
                    }
        }
        __syncthreads();
        {
            int r  = tid & 127;
            int j0 = (tid >> 7) * 16;
            int pp = blockIdx.x * 256 + h * 128 + r;
            int xo2 = pp % 160, yo2 = (pp / 160) % 160, b2 = pp / 25600;
            float* op = g_bufA + (b2 * 32 * 160 + yo2) * 160 + xo2;
#pragma unroll
            for (int j = 0; j < 16; j++) {
                int jj = j0 + j;
                op[jj * 25600] = stg[r*33 + jj] + __ldg(bias + jj);
            }
        }
        __syncthreads();
    }
}

// ------------------------- stats -------------------------
__global__ void stats_kernel(const float* __restrict__ gamma, const float* __restrict__ beta) {
    int rc = blockIdx.x;
    int region = rc >> 5;
    int c  = rc & 31;
    int ri = region >> 2, ci = region & 3;
    int tid = threadIdx.x;

    double s = 0.0, ss = 0.0;
    for (int i = tid; i < 64 * 1600; i += 256) {
        int b = i / 1600;
        int p = i - b * 1600;
        int y = ri * 40 + p / 40;
        int xx = ci * 40 + (p % 40);
        float v = g_bufA[((b * 32 + c) * 160 + y) * 160 + xx];
        s += (double)v; ss += (double)v * (double)v;
    }
    __shared__ double sh_s[256], sh_ss[256];
    sh_s[tid] = s; sh_ss[tid] = ss;
    __syncthreads();
    for (int off = 128; off > 0; off >>= 1) {
        if (tid < off) { sh_s[tid] += sh_s[tid + off]; sh_ss[tid] += sh_ss[tid + off]; }
        __syncthreads();
    }
    if (tid == 0) {
        double mean = sh_s[0] / 102400.0;
        double var  = sh_ss[0] / 102400.0 - mean * mean;
        float sc = __ldg(gamma + c) * rsqrtf((float)var + 1e-5f);
        g_scale[rc] = sc;
        g_shift[rc] = __ldg(beta + c) - (float)mean * sc;
    }
}

// ------------------------- rconv: M=256/CTA (32/warp), N=32, K=320, channel-pair loads -------------------------
#define RC_SM 40960   // B_HI 5*4096 @0, B_LO @20480
__global__ void __launch_bounds__(256) rconv_mma(const float* __restrict__ bias) {
    extern __shared__ char smem[];
    uint32_t sb = smem_u32(smem);
    int tid = threadIdx.x, wid = tid >> 5, lane = tid & 31;

#pragma unroll
    for (int e = tid; e < 5120; e += 256) {
        int chunk = e >> 10, idx = e & 1023;
        int oc = idx >> 5, i = idx & 31;
        uint2 w2 = __ldg((const uint2*)(g_wrHL + oc*320 + chunk*64 + 2*i));
        uint32_t off = chunk*4096 + sw128((uint32_t)(oc*128 + i*4));
        *(uint32_t*)(smem + off)         = __byte_perm(w2.x, w2.y, 0x5410);
        *(uint32_t*)(smem + 20480 + off) = __byte_perm(w2.x, w2.y, 0x7632);
    }

    int px[4], msk[4];
#pragma unroll
    for (int h = 0; h < 4; h++) {
        int pp = blockIdx.x*256 + wid*32 + (h>>1)*16 + (h&1)*8 + (lane>>2);
        int xo = pp % 160, yo = (pp/160) % 160, b = pp / 25600;
        px[h] = b*409600 + yo*160 + xo;
        int lx = xo % 40, ly = yo % 40;
        int ry = ((ly > 0) ? 1 : 0) | 2 | ((ly < 39) ? 4 : 0);
        int cx = ((lx > 0) ? 1 : 0) | 2 | ((lx < 39) ? 4 : 0);
        int m = 0;
#pragma unroll
        for (int ty = 0; ty < 3; ty++)
#pragma unroll
            for (int tx = 0; tx < 3; tx++)
                if (((ry >> ty) & 1) && ((cx >> tx) & 1)) m |= 1 << (ty*3 + tx);
        msk[h] = m;
    }

    float acc[32];
#pragma unroll
    for (int i = 0; i < 32; i++) acc[i] = 0.f;
    __syncthreads();

    for (int c = 0; c < 5; c++) {
        uint32_t bHi = sb + c*4096;
        uint32_t bLo = sb + 20480 + c*4096;
        int t0 = 2*c, t1 = 2*c + 1;
        int ty0 = t0 / 3, ty1 = t1 / 3;
        int dd0 = (ty0 - 1)*160 + (t0 - 3*ty0 - 1);
        int dd1 = (ty1 - 1)*160 + (t1 - 3*ty1 - 1);
#pragma unroll
        for (int ks = 0; ks < 4; ks++) {
            bool useT1 = (ks >= 2);
            int t   = useT1 ? t1 : t0;
            int dd  = useT1 ? dd1 : dd0;
            bool tv = (t < 9);
            int q   = (ks & 1)*8 + (lane & 3);   // channel-pair plane
            int co0 = q*25600 + dd;
            int co1 = co0 + 4*25600;
            uint32_t b_hi[8], b_lo[8];
            uint32_t bbyte = (uint32_t)(((((lane >> 4) << 3) + (lane & 7))*128) + (ks*16 + (lane & 8))*2);
            ldsm4(&b_hi[0], bHi + sw128(bbyte));
            ldsm4(&b_hi[4], bHi + sw128(bbyte) + 2048);
            ldsm4(&b_lo[0], bLo + sw128(bbyte));
            ldsm4(&b_lo[4], bLo + sw128(bbyte) + 2048);
#pragma unroll
            for (int mt = 0; mt < 2; mt++) {
                bool ok0 = tv && ((msk[mt*2]     >> t) & 1);
                bool ok1 = tv && ((msk[mt*2 + 1] >> t) & 1);
                int q0 = px[mt*2], q1 = px[mt*2 + 1];
                uint32_t ah0 = ok0 ? __ldg(g_actH2 + q0 + co0) : 0u;
                uint32_t ah1 = ok1 ? __ldg(g_actH2 + q1 + co0) : 0u;
                uint32_t ah2 = ok0 ? __ldg(g_actH2 + q0 + co1) : 0u;
                uint32_t ah3 = ok1 ? __ldg(g_actH2 + q1 + co1) : 0u;
                uint32_t al0 = ok0 ? __ldg(g_actL2 + q0 + co0) : 0u;
                uint32_t al1 = ok1 ? __ldg(g_actL2 + q1 + co0) : 0u;
                uint32_t al2 = ok0 ? __ldg(g_actL2 + q0 + co1) : 0u;
                uint32_t al3 = ok1 ? __ldg(g_actL2 + q1 + co1) : 0u;
                MMA3(4, acc + mt*16);
            }
        }
    }
    __syncthreads();
    float* stg = (float*)smem;
#pragma unroll
    for (int h = 0; h < 2; h++) {
        if ((wid >> 2) == h) {
#pragma unroll
            for (int mt = 0; mt < 2; mt++)
#pragma unroll
                for (int nt = 0; nt < 4; nt++)
#pragma unroll
                    for (int r = 0; r < 4; r++) {
                        int row = (wid & 3)*32 + mt*16 + (lane >> 2) + ((r >> 1) << 3);
                        int col = nt*8 + ((lane & 3) << 1) + (r & 1);
                        stg[row*33 + col] = acc[(mt*4 + nt)*4 + r];
                    }
        }
        __syncthreads();
        {
            int r  = tid & 127;
            int j0 = (tid >> 7) * 16;
            int pp = blockIdx.x * 256 + h * 128 + r;
            int xo2 = pp % 160, yo2 = (pp / 160) % 160, b2 = pp / 25600;
            float* op = g_bufB + (b2 * 32 * 160 + yo2) * 160 + xo2;
#pragma unroll
            for (int j = 0; j < 16; j++) {
                int jj = j0 + j;
                op[jj * 25600] = stg[r*33 + jj] + __ldg(bias + jj);
            }
        }
        __syncthreads();
    }
}

// ------------------------- conv4: M=256, N=16, K=2048, pair loads -------------------------
#define CONV4_M (BATCH * 73 * 73)
#define C4_SM 32768
__global__ void __launch_bounds__(256) conv4_mma(const float* __restrict__ bias) {
    extern __shared__ char smem[];
    uint32_t sb = smem_u32(smem);
    int tid = threadIdx.x, wid = tid >> 5, lane = tid & 31;

    int px[4];
    bool pvh[4];
#pragma unroll
    for (int h = 0; h < 4; h++) {
        int pp = blockIdx.x*256 + wid*32 + (h>>1)*16 + (h&1)*8 + (lane>>2);
        pvh[h] = pp < CONV4_M;
        int pq = pvh[h] ? pp : 0;
        int xo = pq % 73, yo = (pq/73) % 73, b = pq / 5329;
        px[h] = b*204800 + yo*80 + xo;
    }

    float acc[16];
#pragma unroll
    for (int i = 0; i < 16; i++) acc[i] = 0.f;

    for (int qt = 0; qt < 4; qt++) {
        if (qt) __syncthreads();
#pragma unroll
        for (int e = tid; e < 4096; e += 256) {
            int chunk = e >> 9, idx = e & 511;
            int oc = idx >> 5, i = idx & 31;
            uint2 w2 = __ldg((const uint2*)(g_w4HL + oc*2048 + qt*512 + chunk*64 + 2*i));
            uint32_t off = chunk*2048 + sw128((uint32_t)(oc*128 + i*4));
            *(uint32_t*)(smem + off)         = __byte_perm(w2.x, w2.y, 0x5410);
            *(uint32_t*)(smem + 16384 + off) = __byte_perm(w2.x, w2.y, 0x7632);
        }
        __syncthreads();
#pragma unroll 1
        for (int cc = 0; cc < 8; cc++) {
            int c = qt*8 + cc;
            uint32_t bHi = sb + cc*2048;
            uint32_t bLo = sb + 16384 + cc*2048;
#pragma unroll
            for (int ks = 0; ks < 4; ks++) {
                int k  = c*64 + ks*16 + ((lane & 3) << 1);
                int co = (k >> 6)*6400 + ((k >> 3) & 7)*80 + (k & 7);
                uint32_t b_hi[4], b_lo[4];
                uint32_t bbyte = (uint32_t)(((((lane >> 4) << 3) + (lane & 7))*128) + (ks*16 + (lane & 8))*2);
                ldsm4(b_hi, bHi + sw128(bbyte));
                ldsm4(b_lo, bLo + sw128(bbyte));
#pragma unroll
                for (int mt = 0; mt < 2; mt++) {
                    bool v0 = pvh[mt*2], v1 = pvh[mt*2 + 1];
                    int q0 = px[mt*2], q1 = px[mt*2 + 1];
                    uint32_t ah0 = v0 ? __ldg(g_poolH2 + q0 + co)      : 0u;
                    uint32_t ah1 = v1 ? __ldg(g_poolH2 + q1 + co)      : 0u;
                    uint32_t ah2 = v0 ? __ldg(g_poolH2 + q0 + co + 80) : 0u;
                    uint32_t ah3 = v1 ? __ldg(g_poolH2 + q1 + co + 80) : 0u;
                    uint32_t al0 = v0 ? __ldg(g_poolL2 + q0 + co)      : 0u;
                    uint32_t al1 = v1 ? __ldg(g_poolL2 + q1 + co)      : 0u;
                    uint32_t al2 = v0 ? __ldg(g_poolL2 + q0 + co + 80) : 0u;
                    uint32_t al3 = v1 ? __ldg(g_poolL2 + q1 + co + 80) : 0u;
                    MMA3(2, acc + mt*8);
                }
            }
        }
    }
    __syncthreads();
    float* stg = (float*)smem;
#pragma unroll
    for (int h = 0; h < 2; h++) {
        if ((wid >> 2) == h) {
#pragma unroll
            for (int mt = 0; mt < 2; mt++)
#pragma unroll
                for (int nt = 0; nt < 2; nt++)
#pragma unroll
                    for (int r = 0; r < 4; r++) {
                        int row = (wid & 3)*32 + mt*16 + (lane >> 2) + ((r >> 1) << 3);
                        int col = nt*8 + ((lane & 3) << 1) + (r & 1);
                        stg[row*17 + col] = acc[(mt*2 + nt)*4 + r];
                    }
        }
        __syncthreads();
        {
            int r  = tid & 127;
            int j0 = (tid >> 7) * 8;
            int pq = blockIdx.x * 256 + h * 128 + r;
            if (pq < CONV4_M) {
                int xo2 = pq % 73, yo2 = (pq / 73) % 73, b2 = pq / 5329;
                float* op = g_c4 + (b2 * 16 * 73 + yo2) * 73 + xo2;
#pragma unroll
                for (int j = 0; j < 8; j++) {
                    int jj = j0 + j;
                    op[jj * 5329] = stg[r*17 + jj] + __ldg(bias + jj);
                }
            }
        }
        __syncthreads();
    }
}

// ------------------------- weight transpose for remaining direct convs -------------------------
#define DEFINE_TRANS(NAME, OC, R, DST)                                        \
__global__ void NAME(const float* __restrict__ w) {                           \
    int e = blockIdx.x * blockDim.x + threadIdx.x;                            \
    if (e < (OC)*(R)) {                                                       \
        int oc = e / (R);                                                     \
        int r  = e - oc * (R);                                                \
        DST[r*(OC) + oc] = w[e];                                              \
    }                                                                         \
}
DEFINE_TRANS(t_w5,  16, 1024, g_wT5)
DEFINE_TRANS(t_w6,  16,  576, g_wT6)
DEFINE_TRANS(t_w7,  16,  400, g_wT7)
DEFINE_TRANS(t_w8,  16,  144, g_wT8)
DEFINE_TRANS(t_wfc, 512, 1024, g_wTfc)

// ------------------------- generic OC=16 direct conv, 2 pixels/thread -------------------------
#define DEFINE_CONV16(NAME, IC, K, S, IH, IW, OH, OW, INBUF, WTBUF, OUTBUF)          \
__global__ void __launch_bounds__(128) NAME(const float* __restrict__ bias) {        \
    const int XP  = ((OW) + 1) / 2;                                                  \
    const int OFF = (OW) - XP;                                                       \
    int t = blockIdx.x * 128 + threadIdx.x;                                          \
    if (t >= BATCH * (OH) * XP) return;                                              \
    int xo = t % XP;                                                                 \
    int yo = (t / XP) % (OH);                                                        \
    int b  = t / (XP * (OH));                                                        \
    float a0[16], a1[16];                                                            \
    _Pragma("unroll")                                                                \
    for (int j = 0; j < 16; j++) { float bv = __ldg(bias + j); a0[j] = bv; a1[j] = bv; } \
    for (int ic = 0; ic < (IC); ic++) {                                              \
        const float* inp = INBUF + ((b*(IC) + ic)*(IH) + yo*(S))*(IW) + xo*(S);      \
        _Pragma("unroll 1")                                                          \
        for (int ky = 0; ky < (K); ky++) {                                           \
            const float* row = inp + ky*(IW);                                        \
            const float4* wrow = (const float4*)(WTBUF + (ic*(K)*(K) + ky*(K))*16);  \
            _Pragma("unroll")                                                        \
            for (int kx = 0; kx < (K); kx++) {                                       \
                float v0 = __ldg(row + kx);                                          \
                float v1 = __ldg(row + OFF*(S) + kx);                                \
                _Pragma("unroll")                                                    \
                for (int j = 0; j < 4; j++) {                                        \
                    float4 w4 = __ldg(wrow + kx*4 + j);                              \
                    a0[4*j+0] = fmaf(v0, w4.x, a0[4*j+0]); a1[4*j+0] = fmaf(v1, w4.x, a1[4*j+0]); \
                    a0[4*j+1] = fmaf(v0, w4.y, a0[4*j+1]); a1[4*j+1] = fmaf(v1, w4.y, a1[4*j+1]); \
                    a0[4*j+2] = fmaf(v0, w4.z, a0[4*j+2]); a1[4*j+2] = fmaf(v1, w4.z, a1[4*j+2]); \
                    a0[4*j+3] = fmaf(v0, w4.w, a0[4*j+3]); a1[4*j+3] = fmaf(v1, w4.w, a1[4*j+3]); \
                }                                                                    \
            }                                                                        \
        }                                                                            \
    }                                                                                \
    float* op = OUTBUF + (b*16*(OH) + yo)*(OW) + xo;                                 \
    _Pragma("unroll")                                                                \
    for (int j = 0; j < 16; j++) {                                                   \
        op[j*(OH)*(OW)]       = a0[j];                                               \
        op[j*(OH)*(OW) + OFF] = a1[j];                                               \
    }                                                                                \
}

DEFINE_CONV16(conv5_kernel, 16, 8, 2, 73, 73, 33, 33, g_c4, g_wT5, g_c5)
DEFINE_CONV16(conv6_kernel, 16, 6, 1, 33, 33, 28, 28, g_c5, g_wT6, g_c6)
DEFINE_CONV16(conv7_kernel, 16, 5, 1, 28, 28, 24, 24, g_c6, g_wT7, g_c7)
DEFINE_CONV16(conv8_kernel, 16, 3, 3, 24, 24,  8,  8, g_c7, g_wT8, g_c8)

// ------------------------- FC -------------------------
__global__ void fc_kernel(const float* __restrict__ bias, float* __restrict__ out) {
    __shared__ float sm[1024];
    int b = blockIdx.x;
    int o = threadIdx.x;
    sm[o]       = g_c8[b * 1024 + o];
    sm[o + 512] = g_c8[b * 1024 + o + 512];
    __syncthreads();
    float acc = __ldg(bias + o);
#pragma unroll 4
    for (int k = 0; k < 1024; k++)
        acc = fmaf(sm[k], g_wTfc[k * 512 + o], acc);
    out[b * 512 + o] = acc;
}

// ------------------------- launch -------------------------
static inline int gridFor(long n, int bs) { return (int)((n + bs - 1) / bs); }

extern "C" void kernel_launch(void* const* d_in, const int* in_sizes, int n_in,
                              void* d_out, int out_size) {
    const float* x        = (const float*)d_in[0];
    const float* conv1_w  = (const float*)d_in[1];
    const float* conv1_b  = (const float*)d_in[2];
    const float* bn_gamma = (const float*)d_in[3];
    const float* bn_beta  = (const float*)d_in[4];
    const float* prelu_a  = (const float*)d_in[5];
    const float* rconv_w  = (const float*)d_in[6];
    const float* rconv_b  = (const float*)d_in[7];
    const float* conv4_w  = (const float*)d_in[8];
    const float* conv4_b  = (const float*)d_in[9];
    const float* conv5_b  = (const float*)d_in[11];
    const float* conv6_b  = (const float*)d_in[13];
    const float* conv7_b  = (const float*)d_in[15];
    const float* conv8_b  = (const float*)d_in[17];
    const float* fc_b     = (const float*)d_in[19];
    float* out = (float*)d_out;

    cudaFuncSetAttribute(conv1_mma, cudaFuncAttributeMaxDynamicSharedMemorySize, C1_SM);
    cudaFuncSetAttribute(rconv_mma, cudaFuncAttributeMaxDynamicSharedMemorySize, RC_SM);
    cudaFuncSetAttribute(conv4_mma, cudaFuncAttributeMaxDynamicSharedMemorySize, C4_SM);

    // launches ordered so conv1_mma is the 4th launch (ncu captures it)
    split_x<<<gridFor(NX, 256), 256>>>(x);
    t_w1hl<<<gridFor(32*448, 256), 256>>>(conv1_w);
    t_wrhl<<<gridFor(32*320, 256), 256>>>(rconv_w);
    conv1_mma<<<6400, 256, C1_SM>>>(conv1_b);

    t_w4hl<<<gridFor(16*2048, 256), 256>>>(conv4_w);
    t_w5 <<<gridFor(16*1024, 256), 256>>>((const float*)d_in[10]);
    t_w6 <<<gridFor(16*576,  256), 256>>>((const float*)d_in[12]);
    t_w7 <<<gridFor(16*400,  256), 256>>>((const float*)d_in[14]);
    t_w8 <<<gridFor(16*144,  256), 256>>>((const float*)d_in[16]);
    t_wfc<<<gridFor(512*1024,256), 256>>>((const float*)d_in[18]);

    stats_kernel<<<512, 256>>>(bn_gamma, bn_beta);
    act_kernel<<<gridFor(NACT, 256), 256>>>(prelu_a);
    rconv_mma<<<6400, 256, RC_SM>>>(rconv_b);
    pool_kernel<<<gridFor(NPOOL, 256), 256>>>();

    conv4_mma<<<gridFor(CONV4_M, 256), 256, C4_SM>>>(conv4_b);
    conv5_kernel<<<gridFor((long)BATCH*33*17, 128), 128>>>(conv5_b);
    conv6_kernel<<<gridFor((long)BATCH*28*14, 128), 128>>>(conv6_b);
    conv7_kernel<<<gridFor((long)BATCH*24*12, 128), 128>>>(conv7_b);
    conv8_kernel<<<gridFor((long)BATCH*8*4,   128), 128>>>(conv8_b);

    fc_kernel<<<BATCH, 512>>>(fc_b, out);
}

// round 11
// speedup vs baseline: 1.0545x; 1.0210x over previous
#include <cuda_runtime.h>
#include <cuda_bf16.h>
#include <cstdint>

#define BATCH 64

// ------------------------- scratch (no allocs allowed) -------------------------
__device__ float    g_bufA[BATCH*32*160*160];   // conv1 out (fp32, for stats)
__device__ float    g_bufB[BATCH*32*160*160];   // rconv out (fp32, for pool)
#define NX (BATCH*3*170*170)
__device__ uint32_t g_xH2[NX];                  // input: overlapping bf16-hi pairs
__device__ uint32_t g_xL2[NX];
#define NACT (BATCH*16*160*160)
__device__ uint32_t g_actH2[NACT];              // act: channel-pair planes [b][16][160][160]
__device__ uint32_t g_actL2[NACT];
#define NPOOL (BATCH*32*80*80)
__device__ uint32_t g_poolH2[NPOOL];            // pool: overlapping pairs along x
__device__ uint32_t g_poolL2[NPOOL];
__device__ float g_c4[BATCH*16*73*73];
#define NC4 (BATCH*16*73*73)
__device__ uint32_t g_c4H2[NC4];                // c4: overlapping pairs along x
__device__ uint32_t g_c4L2[NC4];
__device__ float g_c5[BATCH*16*33*33];
__device__ float g_c6[BATCH*16*28*28];
__device__ float g_c7[BATCH*16*24*24];
__device__ float g_c8[BATCH*16*8*8];

__device__ uint32_t g_w1HL[32*448];    // conv1 w, rows padded to 12, K=448
__device__ uint32_t g_wrHL[32*320];    // rconv w, k=t*32+ic, padded 288->320
__device__ uint32_t g_w4HL[16*2048];   // conv4 w
__device__ uint32_t g_w5HL[16*1024];   // conv5 w

__device__ float g_wT6[576*16];
__device__ float g_wT7[400*16];
__device__ float g_wT8[144*16];
__device__ float g_wTfc[1024*512];

__device__ float g_scale[512];
__device__ float g_shift[512];

// ------------------------- helpers -------------------------
__device__ __forceinline__ uint32_t smem_u32(const void* p) {
    uint32_t a;
    asm("{ .reg .u64 t; cvta.to.shared.u64 t, %1; cvt.u32.u64 %0, t; }" : "=r"(a) : "l"(p));
    return a;
}
__device__ __forceinline__ uint32_t sw128(uint32_t o) { return o ^ ((o >> 3) & 0x70); }

__device__ __forceinline__ uint32_t packHL(float v) {
    __nv_bfloat16 h = __float2bfloat16(v);
    float r = v - __bfloat162float(h);
    __nv_bfloat16 l = __float2bfloat16(r);
    uint16_t hb = *reinterpret_cast<uint16_t*>(&h);
    uint16_t lb = *reinterpret_cast<uint16_t*>(&l);
    return (uint32_t)hb | ((uint32_t)lb << 16);
}
__device__ __forceinline__ void split2(float a, float b, uint32_t& hi, uint32_t& lo) {
    __nv_bfloat162 h = __floats2bfloat162_rn(a, b);
    float ra = a - __bfloat162float(h.x);
    float rb = b - __bfloat162float(h.y);
    __nv_bfloat162 l = __floats2bfloat162_rn(ra, rb);
    hi = *reinterpret_cast<uint32_t*>(&h);
    lo = *reinterpret_cast<uint32_t*>(&l);
}

__device__ __forceinline__ void ldsm4(uint32_t* r, uint32_t addr) {
    asm volatile("ldmatrix.sync.aligned.m8n8.x4.shared.b16 {%0,%1,%2,%3}, [%4];"
                 : "=r"(r[0]), "=r"(r[1]), "=r"(r[2]), "=r"(r[3]) : "r"(addr));
}

__device__ __forceinline__ void mma_bf16(float* c,
        uint32_t a0, uint32_t a1, uint32_t a2, uint32_t a3,
        uint32_t b0, uint32_t b1) {
    asm volatile(
        "mma.sync.aligned.m16n8k16.row.col.f32.bf16.bf16.f32 "
        "{%0,%1,%2,%3}, {%4,%5,%6,%7}, {%8,%9}, {%0,%1,%2,%3};"
        : "+f"(c[0]), "+f"(c[1]), "+f"(c[2]), "+f"(c[3])
        : "r"(a0), "r"(a1), "r"(a2), "r"(a3), "r"(b0), "r"(b1));
}

#define MMA3(NT, ACCM)                                                              \
    do {                                                                            \
        _Pragma("unroll")                                                           \
        for (int nt = 0; nt < (NT); nt++) {                                         \
            float* cc2 = (ACCM) + nt*4;                                             \
            mma_bf16(cc2, ah0,ah1,ah2,ah3, b_hi[nt*2], b_hi[nt*2+1]);               \
            mma_bf16(cc2, al0,al1,al2,al3, b_hi[nt*2], b_hi[nt*2+1]);               \
            mma_bf16(cc2, ah0,ah1,ah2,ah3, b_lo[nt*2], b_lo[nt*2+1]);               \
        }                                                                           \
    } while (0)

// ------------------------- pre-pass kernels -------------------------
__global__ void split_x(const float* __restrict__ x) {
    int t = blockIdx.x * blockDim.x + threadIdx.x;
    if (t >= NX) return;
    float v0 = x[t];
    float v1 = (t + 1 < NX) ? x[t + 1] : 0.f;
    uint32_t h, l; split2(v0, v1, h, l);
    g_xH2[t] = h; g_xL2[t] = l;
}
__global__ void t_w1hl(const float* __restrict__ w) {
    int e = blockIdx.x * blockDim.x + threadIdx.x;
    if (e < 32*448) {
        int oc = e / 448, k = e - oc*448;
        int row = k / 12, col = k % 12;
        float v = 0.f;
        if (row < 33 && col < 11) {
            int ic = row / 11, ky = row % 11;
            v = w[oc*363 + ic*121 + ky*11 + col];
        }
        g_w1HL[e] = packHL(v);
    }
}
__global__ void t_wrhl(const float* __restrict__ w) {
    int e = blockIdx.x * blockDim.x + threadIdx.x;
    if (e < 32*320) {
        int oc = e / 320, k = e - oc*320;
        int t9 = k >> 5, ic = k & 31;
        g_wrHL[e] = (t9 < 9) ? packHL(w[oc*288 + ic*9 + t9]) : 0u;
    }
}
__global__ void t_w4hl(const float* __restrict__ w) {
    int e = blockIdx.x * blockDim.x + threadIdx.x;
    if (e < 16*2048) g_w4HL[e] = packHL(w[e]);
}
__global__ void t_w5hl(const float* __restrict__ w) {
    int e = blockIdx.x * blockDim.x + threadIdx.x;
    if (e < 16*1024) g_w5HL[e] = packHL(w[e]);
}

// norm + PReLU + channel-pair split: [b][pair q][y][x]
__global__ void act_kernel(const float* __restrict__ pa) {
    int t = blockIdx.x * blockDim.x + threadIdx.x;
    if (t >= NACT) return;
    int xx = t % 160;
    int y  = (t / 160) % 160;
    int q  = (t / 25600) % 16;
    int b  = t / 409600;
    int region = (y / 40) * 4 + (xx / 40);
    int c0 = 2*q;
    int base = ((b*32 + c0)*160 + y)*160 + xx;
    float v0 = g_bufA[base];
    float v1 = g_bufA[base + 25600];
    float a = __ldg(pa);
    float r0 = fmaf(v0, g_scale[region*32 + c0],     g_shift[region*32 + c0]);
    float r1 = fmaf(v1, g_scale[region*32 + c0 + 1], g_shift[region*32 + c0 + 1]);
    r0 = (r0 > 0.f) ? r0 : a * r0;
    r1 = (r1 > 0.f) ? r1 : a * r1;
    uint32_t h, l; split2(r0, r1, h, l);
    g_actH2[t] = h; g_actL2[t] = l;
}

// 2x2 maxpool with overlapping-pair split output
__global__ void pool_kernel() {
    int t = blockIdx.x * blockDim.x + threadIdx.x;
    if (t >= NPOOL) return;
    int xx = t % 80;
    int y  = (t / 80) % 80;
    int bc = t / 6400;
    const float* p = g_bufB + (bc * 160 + 2 * y) * 160 + 2 * xx;
    float v0 = fmaxf(fmaxf(p[0], p[1]), fmaxf(p[160], p[161]));
    float v1 = v0;
    if (xx < 79) v1 = fmaxf(fmaxf(p[2], p[3]), fmaxf(p[162], p[163]));
    uint32_t h, l; split2(v0, v1, h, l);
    g_poolH2[t] = h; g_poolL2[t] = l;
}

// c4 -> overlapping-pair split (for conv5 MMA)
__global__ void split_c4() {
    int t = blockIdx.x * blockDim.x + threadIdx.x;
    if (t >= NC4) return;
    float v0 = g_c4[t];
    float v1 = (t + 1 < NC4) ? g_c4[t + 1] : 0.f;
    uint32_t h, l; split2(v0, v1, h, l);
    g_c4H2[t] = h; g_c4L2[t] = l;
}

// ------------------------- conv1: M=256/CTA (32/warp), N=32, K=448, pair loads -------------------------
#define C1_SM 57344   // B_HI 7*4096 @0, B_LO @28672
__global__ void __launch_bounds__(256) conv1_mma(const float* __restrict__ bias) {
    extern __shared__ char smem[];
    __shared__ int soffs[224];
    uint32_t sb = smem_u32(smem);
    int tid = threadIdx.x, wid = tid >> 5, lane = tid & 31;

    for (int pr = tid; pr < 224; pr += 256) {
        int off = 0;
        if (pr < 198) {
            int k = 2*pr, row = k / 12, col = k % 12;
            off = (row/11)*28900 + (row%11)*170 + col;
        }
        soffs[pr] = off;
    }
#pragma unroll
    for (int e = tid; e < 7168; e += 256) {
        int chunk = e >> 10, idx = e & 1023;
        int oc = idx >> 5, i = idx & 31;
        uint2 w2 = __ldg((const uint2*)(g_w1HL + oc*448 + chunk*64 + 2*i));
        uint32_t off = chunk*4096 + sw128((uint32_t)(oc*128 + i*4));
        *(uint32_t*)(smem + off)         = __byte_perm(w2.x, w2.y, 0x5410);
        *(uint32_t*)(smem + 28672 + off) = __byte_perm(w2.x, w2.y, 0x7632);
    }
    int xoff[4];
#pragma unroll
    for (int h = 0; h < 4; h++) {
        int pp = blockIdx.x*256 + wid*32 + (h>>1)*16 + (h&1)*8 + (lane>>2);
        int xo = pp % 160, yo = (pp/160) % 160, b = pp / 25600;
        xoff[h] = b*86700 + yo*170 + xo;
    }
    float acc[32];
#pragma unroll
    for (int i = 0; i < 32; i++) acc[i] = 0.f;
    __syncthreads();

    for (int c = 0; c < 7; c++) {
        uint32_t bHi = sb + c*4096;
        uint32_t bLo = sb + 28672 + c*4096;
#pragma unroll
        for (int ks = 0; ks < 4; ks++) {
            int prA = c*32 + ks*8 + (lane & 3);
            int oA = soffs[prA], oB = soffs[prA + 4];
            uint32_t b_hi[8], b_lo[8];
            uint32_t bbyte = (uint32_t)(((((lane >> 4) << 3) + (lane & 7))*128) + (ks*16 + (lane & 8))*2);
            ldsm4(&b_hi[0], bHi + sw128(bbyte));
            ldsm4(&b_hi[4], bHi + sw128(bbyte) + 2048);
            ldsm4(&b_lo[0], bLo + sw128(bbyte));
            ldsm4(&b_lo[4], bLo + sw128(bbyte) + 2048);
#pragma unroll
            for (int mt = 0; mt < 2; mt++) {
                int q0 = xoff[mt*2], q1 = xoff[mt*2 + 1];
                uint32_t ah0 = __ldg(g_xH2 + q0 + oA);
                uint32_t ah1 = __ldg(g_xH2 + q1 + oA);
                uint32_t ah2 = __ldg(g_xH2 + q0 + oB);
                uint32_t ah3 = __ldg(g_xH2 + q1 + oB);
                uint32_t al0 = __ldg(g_xL2 + q0 + oA);
                uint32_t al1 = __ldg(g_xL2 + q1 + oA);
                uint32_t al2 = __ldg(g_xL2 + q0 + oB);
                uint32_t al3 = __ldg(g_xL2 + q1 + oB);
                MMA3(4, acc + mt*16);
            }
        }
    }
    __syncthreads();
    float* stg = (float*)smem;
#pragma unroll
    for (int h = 0; h < 2; h++) {
        if ((wid >> 2) == h) {
#pragma unroll
            for (int mt = 0; mt < 2; mt++)
#pragma unroll
                for (int nt = 0; nt < 4; nt++)
#pragma unroll
                    for (int r = 0; r < 4; r++) {
                        int row = (wid & 3)*32 + mt*16 + (lane >> 2) + ((r >> 1) << 3);
                        int col = nt*8 + ((lane & 3) << 1) + (r & 1);
                        stg[row*33 + col] = acc[(mt*4 + nt)*4 + r];
                    }
        }
        __syncthreads();
        {
            int r  = tid & 127;
            int j0 = (tid >> 7) * 16;
            int pp = blockIdx.x * 256 + h * 128 + r;
            int xo2 = pp % 160, yo2 = (pp / 160) % 160, b2 = pp / 25600;
            float* op = g_bufA + (b2 * 32 * 160 + yo2) * 160 + xo2;
#pragma unroll
            for (int j = 0; j < 16; j++) {
                int jj = j0 + j;
                op[jj * 25600] = stg[r*33 + jj] + __ldg(bias + jj);
            }
        }
        __syncthreads();
    }
}

// ------------------------- stats -------------------------
__global__ void stats_kernel(const float* __restrict__ gamma, const float* __restrict__ beta) {
    int rc = blockIdx.x;
    int region = rc >> 5;
    int c  = rc & 31;
    int ri = region >> 2, ci = region & 3;
    int tid = threadIdx.x;

    double s = 0.0, ss = 0.0;
    for (int i = tid; i < 64 * 1600; i += 256) {
        int b = i / 1600;
        int p = i - b * 1600;
        int y = ri * 40 + p / 40;
        int xx = ci * 40 + (p % 40);
        float v = g_bufA[((b * 32 + c) * 160 + y) * 160 + xx];
        s += (double)v; ss += (double)v * (double)v;
    }
    __shared__ double sh_s[256], sh_ss[256];
    sh_s[tid] = s; sh_ss[tid] = ss;
    __syncthreads();
    for (int off = 128; off > 0; off >>= 1) {
        if (tid < off) { sh_s[tid] += sh_s[tid + off]; sh_ss[tid] += sh_ss[tid + off]; }
        __syncthreads();
    }
    if (tid == 0) {
        double mean = sh_s[0] / 102400.0;
        double var  = sh_ss[0] / 102400.0 - mean * mean;
        float sc = __ldg(gamma + c) * rsqrtf((float)var + 1e-5f);
        g_scale[rc] = sc;
        g_shift[rc] = __ldg(beta + c) - (float)mean * sc;
    }
}

// ------------------------- rconv: M=256/CTA (32/warp), N=32, K=320, channel-pair loads -------------------------
#define RC_SM 40960   // B_HI 5*4096 @0, B_LO @20480
__global__ void __launch_bounds__(256) rconv_mma(const float* __restrict__ bias) {
    extern __shared__ char smem[];
    uint32_t sb = smem_u32(smem);
    int tid = threadIdx.x, wid = tid >> 5, lane = tid & 31;

#pragma unroll
    for (int e = tid; e < 5120; e += 256) {
        int chunk = e >> 10, idx = e & 1023;
        int oc = idx >> 5, i = idx & 31;
        uint2 w2 = __ldg((const uint2*)(g_wrHL + oc*320 + chunk*64 + 2*i));
        uint32_t off = chunk*4096 + sw128((uint32_t)(oc*128 + i*4));
        *(uint32_t*)(smem + off)         = __byte_perm(w2.x, w2.y, 0x5410);
        *(uint32_t*)(smem + 20480 + off) = __byte_perm(w2.x, w2.y, 0x7632);
    }

    int px[4], msk[4];
#pragma unroll
    for (int h = 0; h < 4; h++) {
        int pp = blockIdx.x*256 + wid*32 + (h>>1)*16 + (h&1)*8 + (lane>>2);
        int xo = pp % 160, yo = (pp/160) % 160, b = pp / 25600;
        px[h] = b*409600 + yo*160 + xo;
        int lx = xo % 40, ly = yo % 40;
        int ry = ((ly > 0) ? 1 : 0) | 2 | ((ly < 39) ? 4 : 0);
        int cx = ((lx > 0) ? 1 : 0) | 2 | ((lx < 39) ? 4 : 0);
        int m = 0;
#pragma unroll
        for (int ty = 0; ty < 3; ty++)
#pragma unroll
            for (int tx = 0; tx < 3; tx++)
                if (((ry >> ty) & 1) && ((cx >> tx) & 1)) m |= 1 << (ty*3 + tx);
        msk[h] = m;
    }

    float acc[32];
#pragma unroll
    for (int i = 0; i < 32; i++) acc[i] = 0.f;
    __syncthreads();

    for (int c = 0; c < 5; c++) {
        uint32_t bHi = sb + c*4096;
        uint32_t bLo = sb + 20480 + c*4096;
        int t0 = 2*c, t1 = 2*c + 1;
        int ty0 = t0 / 3, ty1 = t1 / 3;
        int dd0 = (ty0 - 1)*160 + (t0 - 3*ty0 - 1);
        int dd1 = (ty1 - 1)*160 + (t1 - 3*ty1 - 1);
#pragma unroll
        for (int ks = 0; ks < 4; ks++) {
            bool useT1 = (ks >= 2);
            int t   = useT1 ? t1 : t0;
            int dd  = useT1 ? dd1 : dd0;
            bool tv = (t < 9);
            int q   = (ks & 1)*8 + (lane & 3);
            int co0 = q*25600 + dd;
            int co1 = co0 + 4*25600;
            uint32_t b_hi[8], b_lo[8];
            uint32_t bbyte = (uint32_t)(((((lane >> 4) << 3) + (lane & 7))*128) + (ks*16 + (lane & 8))*2);
            ldsm4(&b_hi[0], bHi + sw128(bbyte));
            ldsm4(&b_hi[4], bHi + sw128(bbyte) + 2048);
            ldsm4(&b_lo[0], bLo + sw128(bbyte));
            ldsm4(&b_lo[4], bLo + sw128(bbyte) + 2048);
#pragma unroll
            for (int mt = 0; mt < 2; mt++) {
                bool ok0 = tv && ((msk[mt*2]     >> t) & 1);
                bool ok1 = tv && ((msk[mt*2 + 1] >> t) & 1);
                int q0 = px[mt*2], q1 = px[mt*2 + 1];
                uint32_t ah0 = ok0 ? __ldg(g_actH2 + q0 + co0) : 0u;
                uint32_t ah1 = ok1 ? __ldg(g_actH2 + q1 + co0) : 0u;
                uint32_t ah2 = ok0 ? __ldg(g_actH2 + q0 + co1) : 0u;
                uint32_t ah3 = ok1 ? __ldg(g_actH2 + q1 + co1) : 0u;
                uint32_t al0 = ok0 ? __ldg(g_actL2 + q0 + co0) : 0u;
                uint32_t al1 = ok1 ? __ldg(g_actL2 + q1 + co0) : 0u;
                uint32_t al2 = ok0 ? __ldg(g_actL2 + q0 + co1) : 0u;
                uint32_t al3 = ok1 ? __ldg(g_actL2 + q1 + co1) : 0u;
                MMA3(4, acc + mt*16);
            }
        }
    }
    __syncthreads();
    float* stg = (float*)smem;
#pragma unroll
    for (int h = 0; h < 2; h++) {
        if ((wid >> 2) == h) {
#pragma unroll
            for (int mt = 0; mt < 2; mt++)
#pragma unroll
                for (int nt = 0; nt < 4; nt++)
#pragma unroll
                    for (int r = 0; r < 4; r++) {
                        int row = (wid & 3)*32 + mt*16 + (lane >> 2) + ((r >> 1) << 3);
                        int col = nt*8 + ((lane & 3) << 1) + (r & 1);
                        stg[row*33 + col] = acc[(mt*4 + nt)*4 + r];
                    }
        }
        __syncthreads();
        {
            int r  = tid & 127;
            int j0 = (tid >> 7) * 16;
            int pp = blockIdx.x * 256 + h * 128 + r;
            int xo2 = pp % 160, yo2 = (pp / 160) % 160, b2 = pp / 25600;
            float* op = g_bufB + (b2 * 32 * 160 + yo2) * 160 + xo2;
#pragma unroll
            for (int j = 0; j < 16; j++) {
                int jj = j0 + j;
                op[jj * 25600] = stg[r*33 + jj] + __ldg(bias + jj);
            }
        }
        __syncthreads();
    }
}

// ------------------------- conv4: M=512/CTA (64/warp), N=16, K=2048, pair loads -------------------------
#define CONV4_M (BATCH * 73 * 73)
#define C4_SM 32768
__global__ void __launch_bounds__(256) conv4_mma(const float* __restrict__ bias) {
    extern __shared__ char smem[];
    uint32_t sb = smem_u32(smem);
    int tid = threadIdx.x, wid = tid >> 5, lane = tid & 31;

    int px[8];
    bool pvh[8];
#pragma unroll
    for (int h = 0; h < 8; h++) {
        int pp = blockIdx.x*512 + wid*64 + (h>>1)*16 + (h&1)*8 + (lane>>2);
        pvh[h] = pp < CONV4_M;
        int pq = pvh[h] ? pp : 0;
        int xo = pq % 73, yo = (pq/73) % 73, b = pq / 5329;
        px[h] = b*204800 + yo*80 + xo;
    }

    float acc[32];
#pragma unroll
    for (int i = 0; i < 32; i++) acc[i] = 0.f;

    for (int qt = 0; qt < 4; qt++) {
        if (qt) __syncthreads();
#pragma unroll
        for (int e = tid; e < 4096; e += 256) {
            int chunk = e >> 9, idx = e & 511;
            int oc = idx >> 5, i = idx & 31;
            uint2 w2 = __ldg((const uint2*)(g_w4HL + oc*2048 + qt*512 + chunk*64 + 2*i));
            uint32_t off = chunk*2048 + sw128((uint32_t)(oc*128 + i*4));
            *(uint32_t*)(smem + off)         = __byte_perm(w2.x, w2.y, 0x5410);
            *(uint32_t*)(smem + 16384 + off) = __byte_perm(w2.x, w2.y, 0x7632);
        }
        __syncthreads();
#pragma unroll 1
        for (int cc = 0; cc < 8; cc++) {
            int c = qt*8 + cc;
            uint32_t bHi = sb + cc*2048;
            uint32_t bLo = sb + 16384 + cc*2048;
#pragma unroll
            for (int ks = 0; ks < 4; ks++) {
                int k  = c*64 + ks*16 + ((lane & 3) << 1);
                int co = (k >> 6)*6400 + ((k >> 3) & 7)*80 + (k & 7);
                uint32_t b_hi[4], b_lo[4];
                uint32_t bbyte = (uint32_t)(((((lane >> 4) << 3) + (lane & 7))*128) + (ks*16 + (lane & 8))*2);
                ldsm4(b_hi, bHi + sw128(bbyte));
                ldsm4(b_lo, bLo + sw128(bbyte));
#pragma unroll
                for (int mt = 0; mt < 4; mt++) {
                    bool v0 = pvh[mt*2], v1 = pvh[mt*2 + 1];
                    int q0 = px[mt*2], q1 = px[mt*2 + 1];
                    uint32_t ah0 = v0 ? __ldg(g_poolH2 + q0 + co)      : 0u;
                    uint32_t ah1 = v1 ? __ldg(g_poolH2 + q1 + co)      : 0u;
                    uint32_t ah2 = v0 ? __ldg(g_poolH2 + q0 + co + 80) : 0u;
                    uint32_t ah3 = v1 ? __ldg(g_poolH2 + q1 + co + 80) : 0u;
                    uint32_t al0 = v0 ? __ldg(g_poolL2 + q0 + co)      : 0u;
                    uint32_t al1 = v1 ? __ldg(g_poolL2 + q1 + co)      : 0u;
                    uint32_t al2 = v0 ? __ldg(g_poolL2 + q0 + co + 80) : 0u;
                    uint32_t al3 = v1 ? __ldg(g_poolL2 + q1 + co + 80) : 0u;
                    MMA3(2, acc + mt*8);
                }
            }
        }
    }
    __syncthreads();
    float* stg = (float*)smem;
#pragma unroll
    for (int h = 0; h < 4; h++) {
        if ((wid >> 1) == h) {
#pragma unroll
            for (int mt = 0; mt < 4; mt++)
#pragma unroll
                for (int nt = 0; nt < 2; nt++)
#pragma unroll
                    for (int r = 0; r < 4; r++) {
                        int row = (wid & 1)*64 + mt*16 + (lane >> 2) + ((r >> 1) << 3);
                        int col = nt*8 + ((lane & 3) << 1) + (r & 1);
                        stg[row*17 + col] = acc[(mt*2 + nt)*4 + r];
                    }
        }
        __syncthreads();
        {
            int r  = tid & 127;
            int j0 = (tid >> 7) * 8;
            int pq = blockIdx.x * 512 + h * 128 + r;
            if (pq < CONV4_M) {
                int xo2 = pq % 73, yo2 = (pq / 73) % 73, b2 = pq / 5329;
                float* op = g_c4 + (b2 * 16 * 73 + yo2) * 73 + xo2;
#pragma unroll
                for (int j = 0; j < 8; j++) {
                    int jj = j0 + j;
                    op[jj * 5329] = stg[r*17 + jj] + __ldg(bias + jj);
                }
            }
        }
        __syncthreads();
    }
}

// ------------------------- conv5: MMA, M=256/CTA, N=16, K=1024, stride 2 -------------------------
#define CONV5_M (BATCH * 33 * 33)
#define C5_SM 65536   // B_HI 16*2048 @0, B_LO @32768
__global__ void __launch_bounds__(256) conv5_mma(const float* __restrict__ bias) {
    extern __shared__ char smem[];
    uint32_t sb = smem_u32(smem);
    int tid = threadIdx.x, wid = tid >> 5, lane = tid & 31;

    // stage full B (16 chunks)
#pragma unroll
    for (int e = tid; e < 8192; e += 256) {
        int chunk = e >> 9, idx = e & 511;
        int oc = idx >> 5, i = idx & 31;
        uint2 w2 = __ldg((const uint2*)(g_w5HL + oc*1024 + chunk*64 + 2*i));
        uint32_t off = chunk*2048 + sw128((uint32_t)(oc*128 + i*4));
        *(uint32_t*)(smem + off)         = __byte_perm(w2.x, w2.y, 0x5410);
        *(uint32_t*)(smem + 32768 + off) = __byte_perm(w2.x, w2.y, 0x7632);
    }

    int px[4];
    bool pvh[4];
#pragma unroll
    for (int h = 0; h < 4; h++) {
        int pp = blockIdx.x*256 + wid*32 + (h>>1)*16 + (h&1)*8 + (lane>>2);
        pvh[h] = pp < CONV5_M;
        int pq = pvh[h] ? pp : 0;
        int xo = pq % 33, yo = (pq/33) % 33, b = pq / 1089;
        px[h] = b*85264 + (2*yo)*73 + 2*xo;
    }

    float acc[16];
#pragma unroll
    for (int i = 0; i < 16; i++) acc[i] = 0.f;
    __syncthreads();

#pragma unroll 1
    for (int c = 0; c < 16; c++) {
        uint32_t bHi = sb + c*2048;
        uint32_t bLo = sb + 32768 + c*2048;
#pragma unroll
        for (int ks = 0; ks < 4; ks++) {
            int k  = c*64 + ks*16 + ((lane & 3) << 1);
            int co = (k >> 6)*5329 + ((k >> 3) & 7)*73 + (k & 7);
            uint32_t b_hi[4], b_lo[4];
            uint32_t bbyte = (uint32_t)(((((lane >> 4) << 3) + (lane & 7))*128) + (ks*16 + (lane & 8))*2);
            ldsm4(b_hi, bHi + sw128(bbyte));
            ldsm4(b_lo, bLo + sw128(bbyte));
#pragma unroll
            for (int mt = 0; mt < 2; mt++) {
                bool v0 = pvh[mt*2], v1 = pvh[mt*2 + 1];
                int q0 = px[mt*2], q1 = px[mt*2 + 1];
                uint32_t ah0 = v0 ? __ldg(g_c4H2 + q0 + co)      : 0u;
                uint32_t ah1 = v1 ? __ldg(g_c4H2 + q1 + co)      : 0u;
                uint32_t ah2 = v0 ? __ldg(g_c4H2 + q0 + co + 73) : 0u;
                uint32_t ah3 = v1 ? __ldg(g_c4H2 + q1 + co + 73) : 0u;
                uint32_t al0 = v0 ? __ldg(g_c4L2 + q0 + co)      : 0u;
                uint32_t al1 = v1 ? __ldg(g_c4L2 + q1 + co)      : 0u;
                uint32_t al2 = v0 ? __ldg(g_c4L2 + q0 + co + 73) : 0u;
                uint32_t al3 = v1 ? __ldg(g_c4L2 + q1 + co + 73) : 0u;
                MMA3(2, acc + mt*8);
            }
        }
    }
    __syncthreads();
    float* stg = (float*)smem;
#pragma unroll
    for (int h = 0; h < 2; h++) {
        if ((wid >> 2) == h) {
#pragma unroll
            for (int mt = 0; mt < 2; mt++)
#pragma unroll
                for (int nt = 0; nt < 2; nt++)
#pragma unroll
                    for (int r = 0; r < 4; r++) {
                        int row = (wid & 3)*32 + mt*16 + (lane >> 2) + ((r >> 1) << 3);
                        int col = nt*8 + ((lane & 3) << 1) + (r & 1);
                        stg[row*17 + col] = acc[(mt*2 + nt)*4 + r];
                    }
        }
        __syncthreads();
        {
            int r  = tid & 127;
            int j0 = (tid >> 7) * 8;
            int pq = blockIdx.x * 256 + h * 128 + r;
            if (pq < CONV5_M) {
                int xo2 = pq % 33, yo2 = (pq / 33) % 33, b2 = pq / 1089;
                float* op = g_c5 + (b2 * 16 * 33 + yo2) * 33 + xo2;
#pragma unroll
                for (int j = 0; j < 8; j++) {
                    int jj = j0 + j;
                    op[jj * 1089] = stg[r*17 + jj] + __ldg(bias + jj);
                }
            }
        }
        __syncthreads();
    }
}

// ------------------------- weight transpose for remaining direct convs -------------------------
#define DEFINE_TRANS(NAME, OC, R, DST)                                        \
__global__ void NAME(const float* __restrict__ w) {                           \
    int e = blockIdx.x * blockDim.x + threadIdx.x;                            \
    if (e < (OC)*(R)) {                                                       \
        int oc = e / (R);                                                     \
        int r  = e - oc * (R);                                                \
        DST[r*(OC) + oc] = w[e];                                              \
    }                                                                         \
}
DEFINE_TRANS(t_w6,  16,  576, g_wT6)
DEFINE_TRANS(t_w7,  16,  400, g_wT7)
DEFINE_TRANS(t_w8,  16,  144, g_wT8)
DEFINE_TRANS(t_wfc, 512, 1024, g_wTfc)

// ------------------------- generic OC=16 direct conv, 2 pixels/thread -------------------------
#define DEFINE_CONV16(NAME, IC, K, S, IH, IW, OH, OW, INBUF, WTBUF, OUTBUF)          \
__global__ void __launch_bounds__(128) NAME(const float* __restrict__ bias) {        \
    const int XP  = ((OW) + 1) / 2;                                                  \
    const int OFF = (OW) - XP;                                                       \
    int t = blockIdx.x * 128 + threadIdx.x;                                          \
    if (t >= BATCH * (OH) * XP) return;                                              \
    int xo = t % XP;                                                                 \
    int yo = (t / XP) % (OH);                                                        \
    int b  = t / (XP * (OH));                                                        \
    float a0[16], a1[16];                                                            \
    _Pragma("unroll")                                                                \
    for (int j = 0; j < 16; j++) { float bv = __ldg(bias + j); a0[j] = bv; a1[j] = bv; } \
    for (int ic = 0; ic < (IC); ic++) {                                              \
        const float* inp = INBUF + ((b*(IC) + ic)*(IH) + yo*(S))*(IW) + xo*(S);      \
        _Pragma("unroll 1")                                                          \
        for (int ky = 0; ky < (K); ky++) {                                           \
            const float* row = inp + ky*(IW);                                        \
            const float4* wrow = (const float4*)(WTBUF + (ic*(K)*(K) + ky*(K))*16);  \
            _Pragma("unroll")                                                        \
            for (int kx = 0; kx < (K); kx++) {                                       \
                float v0 = __ldg(row + kx);                                          \
                float v1 = __ldg(row + OFF*(S) + kx);                                \
                _Pragma("unroll")                                                    \
                for (int j = 0; j < 4; j++) {                                        \
                    float4 w4 = __ldg(wrow + kx*4 + j);                              \
                    a0[4*j+0] = fmaf(v0, w4.x, a0[4*j+0]); a1[4*j+0] = fmaf(v1, w4.x, a1[4*j+0]); \
                    a0[4*j+1] = fmaf(v0, w4.y, a0[4*j+1]); a1[4*j+1] = fmaf(v1, w4.y, a1[4*j+1]); \
                    a0[4*j+2] = fmaf(v0, w4.z, a0[4*j+2]); a1[4*j+2] = fmaf(v1, w4.z, a1[4*j+2]); \
                    a0[4*j+3] = fmaf(v0, w4.w, a0[4*j+3]); a1[4*j+3] = fmaf(v1, w4.w, a1[4*j+3]); \
                }                                                                    \
            }                                                                        \
        }                                                                            \
    }                                                                                \
    float* op = OUTBUF + (b*16*(OH) + yo)*(OW) + xo;                                 \
    _Pragma("unroll")                                                                \
    for (int j = 0; j < 16; j++) {                                                   \
        op[j*(OH)*(OW)]       = a0[j];                                               \
        op[j*(OH)*(OW) + OFF] = a1[j];                                               \
    }                                                                                \
}

DEFINE_CONV16(conv6_kernel, 16, 6, 1, 33, 33, 28, 28, g_c5, g_wT6, g_c6)
DEFINE_CONV16(conv7_kernel, 16, 5, 1, 28, 28, 24, 24, g_c6, g_wT7, g_c7)
DEFINE_CONV16(conv8_kernel, 16, 3, 3, 24, 24,  8,  8, g_c7, g_wT8, g_c8)

// ------------------------- FC -------------------------
__global__ void fc_kernel(const float* __restrict__ bias, float* __restrict__ out) {
    __shared__ float sm[1024];
    int b = blockIdx.x;
    int o = threadIdx.x;
    sm[o]       = g_c8[b * 1024 + o];
    sm[o + 512] = g_c8[b * 1024 + o + 512];
    __syncthreads();
    float acc = __ldg(bias + o);
#pragma unroll 4
    for (int k = 0; k < 1024; k++)
        acc = fmaf(sm[k], g_wTfc[k * 512 + o], acc);
    out[b * 512 + o] = acc;
}

// ------------------------- launch -------------------------
static inline int gridFor(long n, int bs) { return (int)((n + bs - 1) / bs); }

extern "C" void kernel_launch(void* const* d_in, const int* in_sizes, int n_in,
                              void* d_out, int out_size) {
    const float* x        = (const float*)d_in[0];
    const float* conv1_w  = (const float*)d_in[1];
    const float* conv1_b  = (const float*)d_in[2];
    const float* bn_gamma = (const float*)d_in[3];
    const float* bn_beta  = (const float*)d_in[4];
    const float* prelu_a  = (const float*)d_in[5];
    const float* rconv_w  = (const float*)d_in[6];
    const float* rconv_b  = (const float*)d_in[7];
    const float* conv4_w  = (const float*)d_in[8];
    const float* conv4_b  = (const float*)d_in[9];
    const float* conv5_b  = (const float*)d_in[11];
    const float* conv6_b  = (const float*)d_in[13];
    const float* conv7_b  = (const float*)d_in[15];
    const float* conv8_b  = (const float*)d_in[17];
    const float* fc_b     = (const float*)d_in[19];
    float* out = (float*)d_out;

    cudaFuncSetAttribute(conv1_mma, cudaFuncAttributeMaxDynamicSharedMemorySize, C1_SM);
    cudaFuncSetAttribute(rconv_mma, cudaFuncAttributeMaxDynamicSharedMemorySize, RC_SM);
    cudaFuncSetAttribute(conv4_mma, cudaFuncAttributeMaxDynamicSharedMemorySize, C4_SM);
    cudaFuncSetAttribute(conv5_mma, cudaFuncAttributeMaxDynamicSharedMemorySize, C5_SM);

    // launches ordered so conv1_mma is the 4th launch (ncu captures it)
    split_x<<<gridFor(NX, 256), 256>>>(x);
    t_w1hl<<<gridFor(32*448, 256), 256>>>(conv1_w);
    t_wrhl<<<gridFor(32*320, 256), 256>>>(rconv_w);
    conv1_mma<<<6400, 256, C1_SM>>>(conv1_b);

    t_w4hl<<<gridFor(16*2048, 256), 256>>>(conv4_w);
    t_w5hl<<<gridFor(16*1024, 256), 256>>>((const float*)d_in[10]);
    t_w6 <<<gridFor(16*576,  256), 256>>>((const float*)d_in[12]);
    t_w7 <<<gridFor(16*400,  256), 256>>>((const float*)d_in[14]);
    t_w8 <<<gridFor(16*144,  256), 256>>>((const float*)d_in[16]);
    t_wfc<<<gridFor(512*1024,256), 256>>>((const float*)d_in[18]);

    stats_kernel<<<512, 256>>>(bn_gamma, bn_beta);
    act_kernel<<<gridFor(NACT, 256), 256>>>(prelu_a);
    rconv_mma<<<6400, 256, RC_SM>>>(rconv_b);
    pool_kernel<<<gridFor(NPOOL, 256), 256>>>();

    conv4_mma<<<gridFor(CONV4_M, 512), 256, C4_SM>>>(conv4_b);
    split_c4<<<gridFor(NC4, 256), 256>>>();
    conv5_mma<<<gridFor(CONV5_M, 256), 256, C5_SM>>>(conv5_b);
    conv6_kernel<<<gridFor((long)BATCH*28*14, 128), 128>>>(conv6_b);
    conv7_kernel<<<gridFor((long)BATCH*24*12, 128), 128>>>(conv7_b);
    conv8_kernel<<<gridFor((long)BATCH*8*4,   128), 128>>>(conv8_b);

    fc_kernel<<<BATCH, 512>>>(fc_b, out);
}

// round 12
// speedup vs baseline: 1.0837x; 1.0277x over previous
#include <cuda_runtime.h>
#include <cuda_bf16.h>
#include <cstdint>

#define BATCH 64

// ------------------------- scratch (no allocs allowed) -------------------------
__device__ float    g_bufA[BATCH*32*160*160];   // conv1 out (fp32, for stats)
__device__ float    g_bufB[BATCH*32*160*160];   // rconv out (fp32, for pool)
#define NX (BATCH*3*170*170)
__device__ uint32_t g_xH2[NX];                  // input: overlapping bf16-hi pairs
__device__ uint32_t g_xL2[NX];
#define NACT (BATCH*16*160*160)
__device__ uint32_t g_actH2[NACT];              // act: channel-pair planes [b][16][160][160]
__device__ uint32_t g_actL2[NACT];
#define NPOOL (BATCH*32*80*80)
__device__ uint32_t g_poolH2[NPOOL];            // pool: overlapping pairs along x
__device__ uint32_t g_poolL2[NPOOL];
__device__ float g_c4[BATCH*16*73*73];
#define NC4 (BATCH*16*73*73)
__device__ uint32_t g_c4H2[NC4];                // c4: overlapping pairs along x
__device__ uint32_t g_c4L2[NC4];
__device__ float g_c5[BATCH*16*33*33];
__device__ float g_c6[BATCH*16*28*28];
__device__ float g_c7[BATCH*16*24*24];
__device__ float g_c8[BATCH*16*8*8];

__device__ uint32_t g_w1HL[32*448];    // conv1 w, rows padded to 12, K=448
__device__ uint32_t g_wrHL[32*320];    // rconv w, k=t*32+ic, padded 288->320
__device__ uint32_t g_w4HL[16*2048];   // conv4 w
__device__ uint32_t g_w5HL[16*1024];   // conv5 w

__device__ float g_wT6[576*16];
__device__ float g_wT7[400*16];
__device__ float g_wT8[144*16];
__device__ float g_wTfc[1024*512];

__device__ float g_scale[512];
__device__ float g_shift[512];

// ------------------------- helpers -------------------------
__device__ __forceinline__ uint32_t smem_u32(const void* p) {
    uint32_t a;
    asm("{ .reg .u64 t; cvta.to.shared.u64 t, %1; cvt.u32.u64 %0, t; }" : "=r"(a) : "l"(p));
    return a;
}
__device__ __forceinline__ uint32_t sw128(uint32_t o) { return o ^ ((o >> 3) & 0x70); }

__device__ __forceinline__ uint32_t packHL(float v) {
    __nv_bfloat16 h = __float2bfloat16(v);
    float r = v - __bfloat162float(h);
    __nv_bfloat16 l = __float2bfloat16(r);
    uint16_t hb = *reinterpret_cast<uint16_t*>(&h);
    uint16_t lb = *reinterpret_cast<uint16_t*>(&l);
    return (uint32_t)hb | ((uint32_t)lb << 16);
}
__device__ __forceinline__ void split2(float a, float b, uint32_t& hi, uint32_t& lo) {
    __nv_bfloat162 h = __floats2bfloat162_rn(a, b);
    float ra = a - __bfloat162float(h.x);
    float rb = b - __bfloat162float(h.y);
    __nv_bfloat162 l = __floats2bfloat162_rn(ra, rb);
    hi = *reinterpret_cast<uint32_t*>(&h);
    lo = *reinterpret_cast<uint32_t*>(&l);
}

__device__ __forceinline__ void ldsm4(uint32_t* r, uint32_t addr) {
    asm volatile("ldmatrix.sync.aligned.m8n8.x4.shared.b16 {%0,%1,%2,%3}, [%4];"
                 : "=r"(r[0]), "=r"(r[1]), "=r"(r[2]), "=r"(r[3]) : "r"(addr));
}

__device__ __forceinline__ void mma_bf16(float* c,
        uint32_t a0, uint32_t a1, uint32_t a2, uint32_t a3,
        uint32_t b0, uint32_t b1) {
    asm volatile(
        "mma.sync.aligned.m16n8k16.row.col.f32.bf16.bf16.f32 "
        "{%0,%1,%2,%3}, {%4,%5,%6,%7}, {%8,%9}, {%0,%1,%2,%3};"
        : "+f"(c[0]), "+f"(c[1]), "+f"(c[2]), "+f"(c[3])
        : "r"(a0), "r"(a1), "r"(a2), "r"(a3), "r"(b0), "r"(b1));
}

#define MMA3(NT, ACCM)                                                              \
    do {                                                                            \
        _Pragma("unroll")                                                           \
        for (int nt = 0; nt < (NT); nt++) {                                         \
            float* cc2 = (ACCM) + nt*4;                                             \
            mma_bf16(cc2, ah0,ah1,ah2,ah3, b_hi[nt*2], b_hi[nt*2+1]);               \
            mma_bf16(cc2, al0,al1,al2,al3, b_hi[nt*2], b_hi[nt*2+1]);               \
            mma_bf16(cc2, ah0,ah1,ah2,ah3, b_lo[nt*2], b_lo[nt*2+1]);               \
        }                                                                           \
    } while (0)

// ------------------------- pre-pass kernels -------------------------
__global__ void split_x(const float* __restrict__ x) {
    int t = blockIdx.x * blockDim.x + threadIdx.x;
    if (t >= NX) return;
    float v0 = x[t];
    float v1 = (t + 1 < NX) ? x[t + 1] : 0.f;
    uint32_t h, l; split2(v0, v1, h, l);
    g_xH2[t] = h; g_xL2[t] = l;
}
__global__ void t_w1hl(const float* __restrict__ w) {
    int e = blockIdx.x * blockDim.x + threadIdx.x;
    if (e < 32*448) {
        int oc = e / 448, k = e - oc*448;
        int row = k / 12, col = k % 12;
        float v = 0.f;
        if (row < 33 && col < 11) {
            int ic = row / 11, ky = row % 11;
            v = w[oc*363 + ic*121 + ky*11 + col];
        }
        g_w1HL[e] = packHL(v);
    }
}
__global__ void t_wrhl(const float* __restrict__ w) {
    int e = blockIdx.x * blockDim.x + threadIdx.x;
    if (e < 32*320) {
        int oc = e / 320, k = e - oc*320;
        int t9 = k >> 5, ic = k & 31;
        g_wrHL[e] = (t9 < 9) ? packHL(w[oc*288 + ic*9 + t9]) : 0u;
    }
}
__global__ void t_w4hl(const float* __restrict__ w) {
    int e = blockIdx.x * blockDim.x + threadIdx.x;
    if (e < 16*2048) g_w4HL[e] = packHL(w[e]);
}
__global__ void t_w5hl(const float* __restrict__ w) {
    int e = blockIdx.x * blockDim.x + threadIdx.x;
    if (e < 16*1024) g_w5HL[e] = packHL(w[e]);
}

// norm + PReLU + channel-pair split: [b][pair q][y][x]
__global__ void act_kernel(const float* __restrict__ pa) {
    int t = blockIdx.x * blockDim.x + threadIdx.x;
    if (t >= NACT) return;
    int xx = t % 160;
    int y  = (t / 160) % 160;
    int q  = (t / 25600) % 16;
    int b  = t / 409600;
    int region = (y / 40) * 4 + (xx / 40);
    int c0 = 2*q;
    int base = ((b*32 + c0)*160 + y)*160 + xx;
    float v0 = g_bufA[base];
    float v1 = g_bufA[base + 25600];
    float a = __ldg(pa);
    float r0 = fmaf(v0, g_scale[region*32 + c0],     g_shift[region*32 + c0]);
    float r1 = fmaf(v1, g_scale[region*32 + c0 + 1], g_shift[region*32 + c0 + 1]);
    r0 = (r0 > 0.f) ? r0 : a * r0;
    r1 = (r1 > 0.f) ? r1 : a * r1;
    uint32_t h, l; split2(r0, r1, h, l);
    g_actH2[t] = h; g_actL2[t] = l;
}

// 2x2 maxpool with overlapping-pair split output
__global__ void pool_kernel() {
    int t = blockIdx.x * blockDim.x + threadIdx.x;
    if (t >= NPOOL) return;
    int xx = t % 80;
    int y  = (t / 80) % 80;
    int bc = t / 6400;
    const float* p = g_bufB + (bc * 160 + 2 * y) * 160 + 2 * xx;
    float v0 = fmaxf(fmaxf(p[0], p[1]), fmaxf(p[160], p[161]));
    float v1 = v0;
    if (xx < 79) v1 = fmaxf(fmaxf(p[2], p[3]), fmaxf(p[162], p[163]));
    uint32_t h, l; split2(v0, v1, h, l);
    g_poolH2[t] = h; g_poolL2[t] = l;
}

// c4 -> overlapping-pair split (for conv5 MMA)
__global__ void split_c4() {
    int t = blockIdx.x * blockDim.x + threadIdx.x;
    if (t >= NC4) return;
    float v0 = g_c4[t];
    float v1 = (t + 1 < NC4) ? g_c4[t + 1] : 0.f;
    uint32_t h, l; split2(v0, v1, h, l);
    g_c4H2[t] = h; g_c4L2[t] = l;
}

// ------------------------- conv1: M=256/CTA (32/warp), N=32, K=396 real (25 k-steps) -------------------------
#define C1_SM 57344   // B_HI 7*4096 @0, B_LO @28672
__global__ void __launch_bounds__(256) conv1_mma(const float* __restrict__ bias) {
    extern __shared__ char smem[];
    __shared__ int soffs[224];
    uint32_t sb = smem_u32(smem);
    int tid = threadIdx.x, wid = tid >> 5, lane = tid & 31;

    for (int pr = tid; pr < 224; pr += 256) {
        int off = 0;
        if (pr < 198) {
            int k = 2*pr, row = k / 12, col = k % 12;
            off = (row/11)*28900 + (row%11)*170 + col;
        }
        soffs[pr] = off;
    }
#pragma unroll
    for (int e = tid; e < 7168; e += 256) {
        int chunk = e >> 10, idx = e & 1023;
        int oc = idx >> 5, i = idx & 31;
        uint2 w2 = __ldg((const uint2*)(g_w1HL + oc*448 + chunk*64 + 2*i));
        uint32_t off = chunk*4096 + sw128((uint32_t)(oc*128 + i*4));
        *(uint32_t*)(smem + off)         = __byte_perm(w2.x, w2.y, 0x5410);
        *(uint32_t*)(smem + 28672 + off) = __byte_perm(w2.x, w2.y, 0x7632);
    }
    int xoff[4];
#pragma unroll
    for (int h = 0; h < 4; h++) {
        int pp = blockIdx.x*256 + wid*32 + (h>>1)*16 + (h&1)*8 + (lane>>2);
        int xo = pp % 160, yo = (pp/160) % 160, b = pp / 25600;
        xoff[h] = b*86700 + yo*170 + xo;
    }
    float acc[32];
#pragma unroll
    for (int i = 0; i < 32; i++) acc[i] = 0.f;
    __syncthreads();

#pragma unroll 1
    for (int kk = 0; kk < 25; kk++) {          // 25 k-steps cover K=396..400; padded steps removed
        int cc = kk >> 2, ks = kk & 3;
        uint32_t bHi = sb + cc*4096;
        uint32_t bLo = sb + 28672 + cc*4096;
        int prA = kk*8 + (lane & 3);
        int oA = soffs[prA], oB = soffs[prA + 4];
        uint32_t b_hi[8], b_lo[8];
        uint32_t bbyte = (uint32_t)(((((lane >> 4) << 3) + (lane & 7))*128) + (ks*16 + (lane & 8))*2);
        ldsm4(&b_hi[0], bHi + sw128(bbyte));
        ldsm4(&b_hi[4], bHi + sw128(bbyte) + 2048);
        ldsm4(&b_lo[0], bLo + sw128(bbyte));
        ldsm4(&b_lo[4], bLo + sw128(bbyte) + 2048);
#pragma unroll
        for (int mt = 0; mt < 2; mt++) {
            int q0 = xoff[mt*2], q1 = xoff[mt*2 + 1];
            uint32_t ah0 = __ldg(g_xH2 + q0 + oA);
            uint32_t ah1 = __ldg(g_xH2 + q1 + oA);
            uint32_t ah2 = __ldg(g_xH2 + q0 + oB);
            uint32_t ah3 = __ldg(g_xH2 + q1 + oB);
            uint32_t al0 = __ldg(g_xL2 + q0 + oA);
            uint32_t al1 = __ldg(g_xL2 + q1 + oA);
            uint32_t al2 = __ldg(g_xL2 + q0 + oB);
            uint32_t al3 = __ldg(g_xL2 + q1 + oB);
            MMA3(4, acc + mt*16);
        }
    }
    __syncthreads();
    float* stg = (float*)smem;
#pragma unroll
    for (int h = 0; h < 2; h++) {
        if ((wid >> 2) == h) {
#pragma unroll
            for (int mt = 0; mt < 2; mt++)
#pragma unroll
                for (int nt = 0; nt < 4; nt++)
#pragma unroll
                    for (int r = 0; r < 4; r++) {
                        int row = (wid & 3)*32 + mt*16 + (lane >> 2) + ((r >> 1) << 3);
                        int col = nt*8 + ((lane & 3) << 1) + (r & 1);
                        stg[row*33 + col] = acc[(mt*4 + nt)*4 + r];
                    }
        }
        __syncthreads();
        {
            int r  = tid & 127;
            int j0 = (tid >> 7) * 16;
            int pp = blockIdx.x * 256 + h * 128 + r;
            int xo2 = pp % 160, yo2 = (pp / 160) % 160, b2 = pp / 25600;
            float* op = g_bufA + (b2 * 32 * 160 + yo2) * 160 + xo2;
#pragma unroll
            for (int j = 0; j < 16; j++) {
                int jj = j0 + j;
                op[jj * 25600] = stg[r*33 + jj] + __ldg(bias + jj);
            }
        }
        __syncthreads();
    }
}

// ------------------------- stats -------------------------
__global__ void stats_kernel(const float* __restrict__ gamma, const float* __restrict__ beta) {
    int rc = blockIdx.x;
    int region = rc >> 5;
    int c  = rc & 31;
    int ri = region >> 2, ci = region & 3;
    int tid = threadIdx.x;

    double s = 0.0, ss = 0.0;
    for (int i = tid; i < 64 * 1600; i += 256) {
        int b = i / 1600;
        int p = i - b * 1600;
        int y = ri * 40 + p / 40;
        int xx = ci * 40 + (p % 40);
        float v = g_bufA[((b * 32 + c) * 160 + y) * 160 + xx];
        s += (double)v; ss += (double)v * (double)v;
    }
    __shared__ double sh_s[256], sh_ss[256];
    sh_s[tid] = s; sh_ss[tid] = ss;
    __syncthreads();
    for (int off = 128; off > 0; off >>= 1) {
        if (tid < off) { sh_s[tid] += sh_s[tid + off]; sh_ss[tid] += sh_ss[tid + off]; }
        __syncthreads();
    }
    if (tid == 0) {
        double mean = sh_s[0] / 102400.0;
        double var  = sh_ss[0] / 102400.0 - mean * mean;
        float sc = __ldg(gamma + c) * rsqrtf((float)var + 1e-5f);
        g_scale[rc] = sc;
        g_shift[rc] = __ldg(beta + c) - (float)mean * sc;
    }
}

// ------------------------- rconv: M=256/CTA (32/warp), N=32, K=288 real (18 k-steps) -------------------------
#define RC_SM 40960   // B_HI 5*4096 @0, B_LO @20480
__global__ void __launch_bounds__(256) rconv_mma(const float* __restrict__ bias) {
    extern __shared__ char smem[];
    uint32_t sb = smem_u32(smem);
    int tid = threadIdx.x, wid = tid >> 5, lane = tid & 31;

#pragma unroll
    for (int e = tid; e < 5120; e += 256) {
        int chunk = e >> 10, idx = e & 1023;
        int oc = idx >> 5, i = idx & 31;
        uint2 w2 = __ldg((const uint2*)(g_wrHL + oc*320 + chunk*64 + 2*i));
        uint32_t off = chunk*4096 + sw128((uint32_t)(oc*128 + i*4));
        *(uint32_t*)(smem + off)         = __byte_perm(w2.x, w2.y, 0x5410);
        *(uint32_t*)(smem + 20480 + off) = __byte_perm(w2.x, w2.y, 0x7632);
    }

    int px[4], msk[4];
#pragma unroll
    for (int h = 0; h < 4; h++) {
        int pp = blockIdx.x*256 + wid*32 + (h>>1)*16 + (h&1)*8 + (lane>>2);
        int xo = pp % 160, yo = (pp/160) % 160, b = pp / 25600;
        px[h] = b*409600 + yo*160 + xo;
        int lx = xo % 40, ly = yo % 40;
        int ry = ((ly > 0) ? 1 : 0) | 2 | ((ly < 39) ? 4 : 0);
        int cx = ((lx > 0) ? 1 : 0) | 2 | ((lx < 39) ? 4 : 0);
        int m = 0;
#pragma unroll
        for (int ty = 0; ty < 3; ty++)
#pragma unroll
            for (int tx = 0; tx < 3; tx++)
                if (((ry >> ty) & 1) && ((cx >> tx) & 1)) m |= 1 << (ty*3 + tx);
        msk[h] = m;
    }

    float acc[32];
#pragma unroll
    for (int i = 0; i < 32; i++) acc[i] = 0.f;
    __syncthreads();

#pragma unroll 1
    for (int kk = 0; kk < 18; kk++) {          // 18 k-steps = 9 real taps; padded tap removed
        int t  = kk >> 1;
        int cc = kk >> 2, ks = kk & 3;
        int ty = t / 3;
        int dd = (ty - 1)*160 + (t - 3*ty - 1);
        uint32_t bHi = sb + cc*4096;
        uint32_t bLo = sb + 20480 + cc*4096;
        int q   = (kk & 1)*8 + (lane & 3);
        int co0 = q*25600 + dd;
        int co1 = co0 + 4*25600;
        uint32_t b_hi[8], b_lo[8];
        uint32_t bbyte = (uint32_t)(((((lane >> 4) << 3) + (lane & 7))*128) + (ks*16 + (lane & 8))*2);
        ldsm4(&b_hi[0], bHi + sw128(bbyte));
        ldsm4(&b_hi[4], bHi + sw128(bbyte) + 2048);
        ldsm4(&b_lo[0], bLo + sw128(bbyte));
        ldsm4(&b_lo[4], bLo + sw128(bbyte) + 2048);
#pragma unroll
        for (int mt = 0; mt < 2; mt++) {
            bool ok0 = (msk[mt*2]     >> t) & 1;
            bool ok1 = (msk[mt*2 + 1] >> t) & 1;
            int q0 = px[mt*2], q1 = px[mt*2 + 1];
            uint32_t ah0 = ok0 ? __ldg(g_actH2 + q0 + co0) : 0u;
            uint32_t ah1 = ok1 ? __ldg(g_actH2 + q1 + co0) : 0u;
            uint32_t ah2 = ok0 ? __ldg(g_actH2 + q0 + co1) : 0u;
            uint32_t ah3 = ok1 ? __ldg(g_actH2 + q1 + co1) : 0u;
            uint32_t al0 = ok0 ? __ldg(g_actL2 + q0 + co0) : 0u;
            uint32_t al1 = ok1 ? __ldg(g_actL2 + q1 + co0) : 0u;
            uint32_t al2 = ok0 ? __ldg(g_actL2 + q0 + co1) : 0u;
            uint32_t al3 = ok1 ? __ldg(g_actL2 + q1 + co1) : 0u;
            MMA3(4, acc + mt*16);
        }
    }
    __syncthreads();
    float* stg = (float*)smem;
#pragma unroll
    for (int h = 0; h < 2; h++) {
        if ((wid >> 2) == h) {
#pragma unroll
            for (int mt = 0; mt < 2; mt++)
#pragma unroll
                for (int nt = 0; nt < 4; nt++)
#pragma unroll
                    for (int r = 0; r < 4; r++) {
                        int row = (wid & 3)*32 + mt*16 + (lane >> 2) + ((r >> 1) << 3);
                        int col = nt*8 + ((lane & 3) << 1) + (r & 1);
                        stg[row*33 + col] = acc[(mt*4 + nt)*4 + r];
                    }
        }
        __syncthreads();
        {
            int r  = tid & 127;
            int j0 = (tid >> 7) * 16;
            int pp = blockIdx.x * 256 + h * 128 + r;
            int xo2 = pp % 160, yo2 = (pp / 160) % 160, b2 = pp / 25600;
            float* op = g_bufB + (b2 * 32 * 160 + yo2) * 160 + xo2;
#pragma unroll
            for (int j = 0; j < 16; j++) {
                int jj = j0 + j;
                op[jj * 25600] = stg[r*33 + jj] + __ldg(bias + jj);
            }
        }
        __syncthreads();
    }
}

// ------------------------- conv4: M=512/CTA (64/warp), N=16, K=2048, pair loads -------------------------
#define CONV4_M (BATCH * 73 * 73)
#define C4_SM 32768
__global__ void __launch_bounds__(256) conv4_mma(const float* __restrict__ bias) {
    extern __shared__ char smem[];
    uint32_t sb = smem_u32(smem);
    int tid = threadIdx.x, wid = tid >> 5, lane = tid & 31;

    int px[8];
    bool pvh[8];
#pragma unroll
    for (int h = 0; h < 8; h++) {
        int pp = blockIdx.x*512 + wid*64 + (h>>1)*16 + (h&1)*8 + (lane>>2);
        pvh[h] = pp < CONV4_M;
        int pq = pvh[h] ? pp : 0;
        int xo = pq % 73, yo = (pq/73) % 73, b = pq / 5329;
        px[h] = b*204800 + yo*80 + xo;
    }

    float acc[32];
#pragma unroll
    for (int i = 0; i < 32; i++) acc[i] = 0.f;

    for (int qt = 0; qt < 4; qt++) {
        if (qt) __syncthreads();
#pragma unroll
        for (int e = tid; e < 4096; e += 256) {
            int chunk = e >> 9, idx = e & 511;
            int oc = idx >> 5, i = idx & 31;
            uint2 w2 = __ldg((const uint2*)(g_w4HL + oc*2048 + qt*512 + chunk*64 + 2*i));
            uint32_t off = chunk*2048 + sw128((uint32_t)(oc*128 + i*4));
            *(uint32_t*)(smem + off)         = __byte_perm(w2.x, w2.y, 0x5410);
            *(uint32_t*)(smem + 16384 + off) = __byte_perm(w2.x, w2.y, 0x7632);
        }
        __syncthreads();
#pragma unroll 1
        for (int cc = 0; cc < 8; cc++) {
            int c = qt*8 + cc;
            uint32_t bHi = sb + cc*2048;
            uint32_t bLo = sb + 16384 + cc*2048;
#pragma unroll
            for (int ks = 0; ks < 4; ks++) {
                int k  = c*64 + ks*16 + ((lane & 3) << 1);
                int co = (k >> 6)*6400 + ((k >> 3) & 7)*80 + (k & 7);
                uint32_t b_hi[4], b_lo[4];
                uint32_t bbyte = (uint32_t)(((((lane >> 4) << 3) + (lane & 7))*128) + (ks*16 + (lane & 8))*2);
                ldsm4(b_hi, bHi + sw128(bbyte));
                ldsm4(b_lo, bLo + sw128(bbyte));
#pragma unroll
                for (int mt = 0; mt < 4; mt++) {
                    bool v0 = pvh[mt*2], v1 = pvh[mt*2 + 1];
                    int q0 = px[mt*2], q1 = px[mt*2 + 1];
                    uint32_t ah0 = v0 ? __ldg(g_poolH2 + q0 + co)      : 0u;
                    uint32_t ah1 = v1 ? __ldg(g_poolH2 + q1 + co)      : 0u;
                    uint32_t ah2 = v0 ? __ldg(g_poolH2 + q0 + co + 80) : 0u;
                    uint32_t ah3 = v1 ? __ldg(g_poolH2 + q1 + co + 80) : 0u;
                    uint32_t al0 = v0 ? __ldg(g_poolL2 + q0 + co)      : 0u;
                    uint32_t al1 = v1 ? __ldg(g_poolL2 + q1 + co)      : 0u;
                    uint32_t al2 = v0 ? __ldg(g_poolL2 + q0 + co + 80) : 0u;
                    uint32_t al3 = v1 ? __ldg(g_poolL2 + q1 + co + 80) : 0u;
                    MMA3(2, acc + mt*8);
                }
            }
        }
    }
    __syncthreads();
    float* stg = (float*)smem;
#pragma unroll
    for (int h = 0; h < 4; h++) {
        if ((wid >> 1) == h) {
#pragma unroll
            for (int mt = 0; mt < 4; mt++)
#pragma unroll
                for (int nt = 0; nt < 2; nt++)
#pragma unroll
                    for (int r = 0; r < 4; r++) {
                        int row = (wid & 1)*64 + mt*16 + (lane >> 2) + ((r >> 1) << 3);
                        int col = nt*8 + ((lane & 3) << 1) + (r & 1);
                        stg[row*17 + col] = acc[(mt*2 + nt)*4 + r];
                    }
        }
        __syncthreads();
        {
            int r  = tid & 127;
            int j0 = (tid >> 7) * 8;
            int pq = blockIdx.x * 512 + h * 128 + r;
            if (pq < CONV4_M) {
                int xo2 = pq % 73, yo2 = (pq / 73) % 73, b2 = pq / 5329;
                float* op = g_c4 + (b2 * 16 * 73 + yo2) * 73 + xo2;
#pragma unroll
                for (int j = 0; j < 8; j++) {
                    int jj = j0 + j;
                    op[jj * 5329] = stg[r*17 + jj] + __ldg(bias + jj);
                }
            }
        }
        __syncthreads();
    }
}

// ------------------------- conv5: MMA, M=256/CTA, N=16, K=1024, stride 2 -------------------------
#define CONV5_M (BATCH * 33 * 33)
#define C5_SM 65536   // B_HI 16*2048 @0, B_LO @32768
__global__ void __launch_bounds__(256) conv5_mma(const float* __restrict__ bias) {
    extern __shared__ char smem[];
    uint32_t sb = smem_u32(smem);
    int tid = threadIdx.x, wid = tid >> 5, lane = tid & 31;

#pragma unroll
    for (int e = tid; e < 8192; e += 256) {
        int chunk = e >> 9, idx = e & 511;
        int oc = idx >> 5, i = idx & 31;
        uint2 w2 = __ldg((const uint2*)(g_w5HL + oc*1024 + chunk*64 + 2*i));
        uint32_t off = chunk*2048 + sw128((uint32_t)(oc*128 + i*4));
        *(uint32_t*)(smem + off)         = __byte_perm(w2.x, w2.y, 0x5410);
        *(uint32_t*)(smem + 32768 + off) = __byte_perm(w2.x, w2.y, 0x7632);
    }

    int px[4];
    bool pvh[4];
#pragma unroll
    for (int h = 0; h < 4; h++) {
        int pp = blockIdx.x*256 + wid*32 + (h>>1)*16 + (h&1)*8 + (lane>>2);
        pvh[h] = pp < CONV5_M;
        int pq = pvh[h] ? pp : 0;
        int xo = pq % 33, yo = (pq/33) % 33, b = pq / 1089;
        px[h] = b*85264 + (2*yo)*73 + 2*xo;
    }

    float acc[16];
#pragma unroll
    for (int i = 0; i < 16; i++) acc[i] = 0.f;
    __syncthreads();

#pragma unroll 1
    for (int c = 0; c < 16; c++) {
        uint32_t bHi = sb + c*2048;
        uint32_t bLo = sb + 32768 + c*2048;
#pragma unroll
        for (int ks = 0; ks < 4; ks++) {
            int k  = c*64 + ks*16 + ((lane & 3) << 1);
            int co = (k >> 6)*5329 + ((k >> 3) & 7)*73 + (k & 7);
            uint32_t b_hi[4], b_lo[4];
            uint32_t bbyte = (uint32_t)(((((lane >> 4) << 3) + (lane & 7))*128) + (ks*16 + (lane & 8))*2);
            ldsm4(b_hi, bHi + sw128(bbyte));
            ldsm4(b_lo, bLo + sw128(bbyte));
#pragma unroll
            for (int mt = 0; mt < 2; mt++) {
                bool v0 = pvh[mt*2], v1 = pvh[mt*2 + 1];
                int q0 = px[mt*2], q1 = px[mt*2 + 1];
                uint32_t ah0 = v0 ? __ldg(g_c4H2 + q0 + co)      : 0u;
                uint32_t ah1 = v1 ? __ldg(g_c4H2 + q1 + co)      : 0u;
                uint32_t ah2 = v0 ? __ldg(g_c4H2 + q0 + co + 73) : 0u;
                uint32_t ah3 = v1 ? __ldg(g_c4H2 + q1 + co + 73) : 0u;
                uint32_t al0 = v0 ? __ldg(g_c4L2 + q0 + co)      : 0u;
                uint32_t al1 = v1 ? __ldg(g_c4L2 + q1 + co)      : 0u;
                uint32_t al2 = v0 ? __ldg(g_c4L2 + q0 + co + 73) : 0u;
                uint32_t al3 = v1 ? __ldg(g_c4L2 + q1 + co + 73) : 0u;
                MMA3(2, acc + mt*8);
            }
        }
    }
    __syncthreads();
    float* stg = (float*)smem;
#pragma unroll
    for (int h = 0; h < 2; h++) {
        if ((wid >> 2) == h) {
#pragma unroll
            for (int mt = 0; mt < 2; mt++)
#pragma unroll
                for (int nt = 0; nt < 2; nt++)
#pragma unroll
                    for (int r = 0; r < 4; r++) {
                        int row = (wid & 3)*32 + mt*16 + (lane >> 2) + ((r >> 1) << 3);
                        int col = nt*8 + ((lane & 3) << 1) + (r & 1);
                        stg[row*17 + col] = acc[(mt*2 + nt)*4 + r];
                    }
        }
        __syncthreads();
        {
            int r  = tid & 127;
            int j0 = (tid >> 7) * 8;
            int pq = blockIdx.x * 256 + h * 128 + r;
            if (pq < CONV5_M) {
                int xo2 = pq % 33, yo2 = (pq / 33) % 33, b2 = pq / 1089;
                float* op = g_c5 + (b2 * 16 * 33 + yo2) * 33 + xo2;
#pragma unroll
                for (int j = 0; j < 8; j++) {
                    int jj = j0 + j;
                    op[jj * 1089] = stg[r*17 + jj] + __ldg(bias + jj);
                }
            }
        }
        __syncthreads();
    }
}

// ------------------------- weight transpose for remaining direct convs -------------------------
#define DEFINE_TRANS(NAME, OC, R, DST)                                        \
__global__ void NAME(const float* __restrict__ w) {                           \
    int e = blockIdx.x * blockDim.x + threadIdx.x;                            \
    if (e < (OC)*(R)) {                                                       \
        int oc = e / (R);                                                     \
        int r  = e - oc * (R);                                                \
        DST[r*(OC) + oc] = w[e];                                              \
    }                                                                         \
}
DEFINE_TRANS(t_w6,  16,  576, g_wT6)
DEFINE_TRANS(t_w7,  16,  400, g_wT7)
DEFINE_TRANS(t_w8,  16,  144, g_wT8)
DEFINE_TRANS(t_wfc, 512, 1024, g_wTfc)

// ------------------------- generic OC=16 direct conv, 2 pixels/thread -------------------------
#define DEFINE_CONV16(NAME, IC, K, S, IH, IW, OH, OW, INBUF, WTBUF, OUTBUF)          \
__global__ void __launch_bounds__(128) NAME(const float* __restrict__ bias) {        \
    const int XP  = ((OW) + 1) / 2;                                                  \
    const int OFF = (OW) - XP;                                                       \
    int t = blockIdx.x * 128 + threadIdx.x;                                          \
    if (t >= BATCH * (OH) * XP) return;                                              \
    int xo = t % XP;                                                                 \
    int yo = (t / XP) % (OH);                                                        \
    int b  = t / (XP * (OH));                                                        \
    float a0[16], a1[16];                                                            \
    _Pragma("unroll")                                                                \
    for (int j = 0; j < 16; j++) { float bv = __ldg(bias + j); a0[j] = bv; a1[j] = bv; } \
    for (int ic = 0; ic < (IC); ic++) {                                              \
        const float* inp = INBUF + ((b*(IC) + ic)*(IH) + yo*(S))*(IW) + xo*(S);      \
        _Pragma("unroll 1")                                                          \
        for (int ky = 0; ky < (K); ky++) {                                           \
            const float* row = inp + ky*(IW);                                        \
            const float4* wrow = (const float4*)(WTBUF + (ic*(K)*(K) + ky*(K))*16);  \
            _Pragma("unroll")                                                        \
            for (int kx = 0; kx < (K); kx++) {                                       \
                float v0 = __ldg(row + kx);                                          \
                float v1 = __ldg(row + OFF*(S) + kx);                                \
                _Pragma("unroll")                                                    \
                for (int j = 0; j < 4; j++) {                                        \
                    float4 w4 = __ldg(wrow + kx*4 + j);                              \
                    a0[4*j+0] = fmaf(v0, w4.x, a0[4*j+0]); a1[4*j+0] = fmaf(v1, w4.x, a1[4*j+0]); \
                    a0[4*j+1] = fmaf(v0, w4.y, a0[4*j+1]); a1[4*j+1] = fmaf(v1, w4.y, a1[4*j+1]); \
                    a0[4*j+2] = fmaf(v0, w4.z, a0[4*j+2]); a1[4*j+2] = fmaf(v1, w4.z, a1[4*j+2]); \
                    a0[4*j+3] = fmaf(v0, w4.w, a0[4*j+3]); a1[4*j+3] = fmaf(v1, w4.w, a1[4*j+3]); \
                }                                                                    \
            }                                                                        \
        }                                                                            \
    }                                                                                \
    float* op = OUTBUF + (b*16*(OH) + yo)*(OW) + xo;                                 \
    _Pragma("unroll")                                                                \
    for (int j = 0; j < 16; j++) {                                                   \
        op[j*(OH)*(OW)]       = a0[j];                                               \
        op[j*(OH)*(OW) + OFF] = a1[j];                                               \
    }                                                                                \
}

DEFINE_CONV16(conv6_kernel, 16, 6, 1, 33, 33, 28, 28, g_c5, g_wT6, g_c6)
DEFINE_CONV16(conv7_kernel, 16, 5, 1, 28, 28, 24, 24, g_c6, g_wT7, g_c7)
DEFINE_CONV16(conv8_kernel, 16, 3, 3, 24, 24,  8,  8, g_c7, g_wT8, g_c8)

// ------------------------- FC -------------------------
__global__ void fc_kernel(const float* __restrict__ bias, float* __restrict__ out) {
    __shared__ float sm[1024];
    int b = blockIdx.x;
    int o = threadIdx.x;
    sm[o]       = g_c8[b * 1024 + o];
    sm[o + 512] = g_c8[b * 1024 + o + 512];
    __syncthreads();
    float acc = __ldg(bias + o);
#pragma unroll 4
    for (int k = 0; k < 1024; k++)
        acc = fmaf(sm[k], g_wTfc[k * 512 + o], acc);
    out[b * 512 + o] = acc;
}

// ------------------------- launch -------------------------
static inline int gridFor(long n, int bs) { return (int)((n + bs - 1) / bs); }

extern "C" void kernel_launch(void* const* d_in, const int* in_sizes, int n_in,
                              void* d_out, int out_size) {
    const float* x        = (const float*)d_in[0];
    const float* conv1_w  = (const float*)d_in[1];
    const float* conv1_b  = (const float*)d_in[2];
    const float* bn_gamma = (const float*)d_in[3];
    const float* bn_beta  = (const float*)d_in[4];
    const float* prelu_a  = (const float*)d_in[5];
    const float* rconv_w  = (const float*)d_in[6];
    const float* rconv_b  = (const float*)d_in[7];
    const float* conv4_w  = (const float*)d_in[8];
    const float* conv4_b  = (const float*)d_in[9];
    const float* conv5_b  = (const float*)d_in[11];
    const float* conv6_b  = (const float*)d_in[13];
    const float* conv7_b  = (const float*)d_in[15];
    const float* conv8_b  = (const float*)d_in[17];
    const float* fc_b     = (const float*)d_in[19];
    float* out = (float*)d_out;

    cudaFuncSetAttribute(conv1_mma, cudaFuncAttributeMaxDynamicSharedMemorySize, C1_SM);
    cudaFuncSetAttribute(rconv_mma, cudaFuncAttributeMaxDynamicSharedMemorySize, RC_SM);
    cudaFuncSetAttribute(conv4_mma, cudaFuncAttributeMaxDynamicSharedMemorySize, C4_SM);
    cudaFuncSetAttribute(conv5_mma, cudaFuncAttributeMaxDynamicSharedMemorySize, C5_SM);

    // launches ordered so conv1_mma is the 4th launch (ncu captures it)
    split_x<<<gridFor(NX, 256), 256>>>(x);
    t_w1hl<<<gridFor(32*448, 256), 256>>>(conv1_w);
    t_wrhl<<<gridFor(32*320, 256), 256>>>(rconv_w);
    conv1_mma<<<6400, 256, C1_SM>>>(conv1_b);

    t_w4hl<<<gridFor(16*2048, 256), 256>>>(conv4_w);
    t_w5hl<<<gridFor(16*1024, 256), 256>>>((const float*)d_in[10]);
    t_w6 <<<gridFor(16*576,  256), 256>>>((const float*)d_in[12]);
    t_w7 <<<gridFor(16*400,  256), 256>>>((const float*)d_in[14]);
    t_w8 <<<gridFor(16*144,  256), 256>>>((const float*)d_in[16]);
    t_wfc<<<gridFor(512*1024,256), 256>>>((const float*)d_in[18]);

    stats_kernel<<<512, 256>>>(bn_gamma, bn_beta);
    act_kernel<<<gridFor(NACT, 256), 256>>>(prelu_a);
    rconv_mma<<<6400, 256, RC_SM>>>(rconv_b);
    pool_kernel<<<gridFor(NPOOL, 256), 256>>>();

    conv4_mma<<<gridFor(CONV4_M, 512), 256, C4_SM>>>(conv4_b);
    split_c4<<<gridFor(NC4, 256), 256>>>();
    conv5_mma<<<gridFor(CONV5_M, 256), 256, C5_SM>>>(conv5_b);
    conv6_kernel<<<gridFor((long)BATCH*28*14, 128), 128>>>(conv6_b);
    conv7_kernel<<<gridFor((long)BATCH*24*12, 128), 128>>>(conv7_b);
    conv8_kernel<<<gridFor((long)BATCH*8*4,   128), 128>>>(conv8_b);

    fc_kernel<<<BATCH, 512>>>(fc_b, out);
}

// round 14
// speedup vs baseline: 1.2138x; 1.1200x over previous
#include <cuda_runtime.h>
#include <cuda_bf16.h>
#include <cstdint>

#define BATCH 64

// ------------------------- scratch (no allocs allowed) -------------------------
__device__ float    g_bufA[BATCH*32*160*160];
__device__ float    g_bufB[BATCH*32*160*160];
#define NX (BATCH*3*170*170)
__device__ uint32_t g_xH2[NX];
__device__ uint32_t g_xL2[NX];
#define NACT (BATCH*16*160*160)
__device__ uint32_t g_actH2[NACT];
__device__ uint32_t g_actL2[NACT];
#define NPOOL (BATCH*32*80*80)
__device__ uint32_t g_poolH2[NPOOL];
__device__ uint32_t g_poolL2[NPOOL];
__device__ float g_c4[BATCH*16*73*73];
#define NC4 (BATCH*16*73*73)
__device__ uint32_t g_c4H2[NC4];
__device__ uint32_t g_c4L2[NC4];
__device__ float g_c5[BATCH*16*33*33];
#define NC5 (BATCH*16*33*33)
__device__ uint32_t g_c5H2[NC5];
__device__ uint32_t g_c5L2[NC5];
__device__ float g_c6[BATCH*16*28*28];
#define NC6 (BATCH*16*28*28)
__device__ uint32_t g_c6H2[NC6];
__device__ uint32_t g_c6L2[NC6];
__device__ float g_c7[BATCH*16*24*24];
__device__ float g_c8[BATCH*16*8*8];

__device__ uint32_t g_w1HL[32*448];
__device__ uint32_t g_wrHL[32*320];
__device__ uint32_t g_w4HL[16*2048];
__device__ uint32_t g_w5HL[16*1024];
__device__ uint32_t g_w6HL[16*576];
__device__ uint32_t g_w7HL[16*512];   // conv7, rows padded 5->6, K=480 (+pad to 512)

__device__ float g_wT8[144*16];
__device__ float g_wTfc[1024*512];

__device__ float g_scale[512];
__device__ float g_shift[512];

// ------------------------- helpers -------------------------
__device__ __forceinline__ uint32_t smem_u32(const void* p) {
    uint32_t a;
    asm("{ .reg .u64 t; cvta.to.shared.u64 t, %1; cvt.u32.u64 %0, t; }" : "=r"(a) : "l"(p));
    return a;
}
__device__ __forceinline__ uint32_t sw128(uint32_t o) { return o ^ ((o >> 3) & 0x70); }

__device__ __forceinline__ uint32_t packHL(float v) {
    __nv_bfloat16 h = __float2bfloat16(v);
    float r = v - __bfloat162float(h);
    __nv_bfloat16 l = __float2bfloat16(r);
    uint16_t hb = *reinterpret_cast<uint16_t*>(&h);
    uint16_t lb = *reinterpret_cast<uint16_t*>(&l);
    return (uint32_t)hb | ((uint32_t)lb << 16);
}
__device__ __forceinline__ void split2(float a, float b, uint32_t& hi, uint32_t& lo) {
    __nv_bfloat162 h = __floats2bfloat162_rn(a, b);
    float ra = a - __bfloat162float(h.x);
    float rb = b - __bfloat162float(h.y);
    __nv_bfloat162 l = __floats2bfloat162_rn(ra, rb);
    hi = *reinterpret_cast<uint32_t*>(&h);
    lo = *reinterpret_cast<uint32_t*>(&l);
}

__device__ __forceinline__ void ldsm4(uint32_t* r, uint32_t addr) {
    asm volatile("ldmatrix.sync.aligned.m8n8.x4.shared.b16 {%0,%1,%2,%3}, [%4];"
                 : "=r"(r[0]), "=r"(r[1]), "=r"(r[2]), "=r"(r[3]) : "r"(addr));
}

__device__ __forceinline__ void mma_bf16(float* c,
        uint32_t a0, uint32_t a1, uint32_t a2, uint32_t a3,
        uint32_t b0, uint32_t b1) {
    asm volatile(
        "mma.sync.aligned.m16n8k16.row.col.f32.bf16.bf16.f32 "
        "{%0,%1,%2,%3}, {%4,%5,%6,%7}, {%8,%9}, {%0,%1,%2,%3};"
        : "+f"(c[0]), "+f"(c[1]), "+f"(c[2]), "+f"(c[3])
        : "r"(a0), "r"(a1), "r"(a2), "r"(a3), "r"(b0), "r"(b1));
}

#define MMA3(NT, ACCM)                                                              \
    do {                                                                            \
        _Pragma("unroll")                                                           \
        for (int nt = 0; nt < (NT); nt++) {                                         \
            float* cc2 = (ACCM) + nt*4;                                             \
            mma_bf16(cc2, ah0,ah1,ah2,ah3, b_hi[nt*2], b_hi[nt*2+1]);               \
            mma_bf16(cc2, al0,al1,al2,al3, b_hi[nt*2], b_hi[nt*2+1]);               \
            mma_bf16(cc2, ah0,ah1,ah2,ah3, b_lo[nt*2], b_lo[nt*2+1]);               \
        }                                                                           \
    } while (0)

// ------------------------- pre-pass kernels -------------------------
__global__ void split_x(const float* __restrict__ x) {
    int t = blockIdx.x * blockDim.x + threadIdx.x;
    if (t >= NX) return;
    float v0 = x[t];
    float v1 = (t + 1 < NX) ? x[t + 1] : 0.f;
    uint32_t h, l; split2(v0, v1, h, l);
    g_xH2[t] = h; g_xL2[t] = l;
}
__global__ void t_w1hl(const float* __restrict__ w) {
    int e = blockIdx.x * blockDim.x + threadIdx.x;
    if (e < 32*448) {
        int oc = e / 448, k = e - oc*448;
        int row = k / 12, col = k % 12;
        float v = 0.f;
        if (row < 33 && col < 11) {
            int ic = row / 11, ky = row % 11;
            v = w[oc*363 + ic*121 + ky*11 + col];
        }
        g_w1HL[e] = packHL(v);
    }
}
__global__ void t_wrhl(const float* __restrict__ w) {
    int e = blockIdx.x * blockDim.x + threadIdx.x;
    if (e < 32*320) {
        int oc = e / 320, k = e - oc*320;
        int t9 = k >> 5, ic = k & 31;
        g_wrHL[e] = (t9 < 9) ? packHL(w[oc*288 + ic*9 + t9]) : 0u;
    }
}
__global__ void t_w4hl(const float* __restrict__ w) {
    int e = blockIdx.x * blockDim.x + threadIdx.x;
    if (e < 16*2048) g_w4HL[e] = packHL(w[e]);
}
__global__ void t_w5hl(const float* __restrict__ w) {
    int e = blockIdx.x * blockDim.x + threadIdx.x;
    if (e < 16*1024) g_w5HL[e] = packHL(w[e]);
}
__global__ void t_w6hl(const float* __restrict__ w) {
    int e = blockIdx.x * blockDim.x + threadIdx.x;
    if (e < 16*576) g_w6HL[e] = packHL(w[e]);   // layout already rows-of-6
}
__global__ void t_w7hl(const float* __restrict__ w) {
    int e = blockIdx.x * blockDim.x + threadIdx.x;
    if (e < 16*512) {
        int oc = e / 512, k = e - oc*512;
        float v = 0.f;
        if (k < 480) {
            int ic = k / 30, r = k % 30, ky = r / 6, kx = r % 6;
            if (kx < 5) v = w[oc*400 + ic*25 + ky*5 + kx];
        }
        g_w7HL[e] = packHL(v);
    }
}

// norm + PReLU + channel-pair split
__global__ void act_kernel(const float* __restrict__ pa) {
    int t = blockIdx.x * blockDim.x + threadIdx.x;
    if (t >= NACT) return;
    int xx = t % 160;
    int y  = (t / 160) % 160;
    int q  = (t / 25600) % 16;
    int b  = t / 409600;
    int region = (y / 40) * 4 + (xx / 40);
    int c0 = 2*q;
    int base = ((b*32 + c0)*160 + y)*160 + xx;
    float v0 = g_bufA[base];
    float v1 = g_bufA[base + 25600];
    float a = __ldg(pa);
    float r0 = fmaf(v0, g_scale[region*32 + c0],     g_shift[region*32 + c0]);
    float r1 = fmaf(v1, g_scale[region*32 + c0 + 1], g_shift[region*32 + c0 + 1]);
    r0 = (r0 > 0.f) ? r0 : a * r0;
    r1 = (r1 > 0.f) ? r1 : a * r1;
    uint32_t h, l; split2(r0, r1, h, l);
    g_actH2[t] = h; g_actL2[t] = l;
}

__global__ void pool_kernel() {
    int t = blockIdx.x * blockDim.x + threadIdx.x;
    if (t >= NPOOL) return;
    int xx = t % 80;
    int y  = (t / 80) % 80;
    int bc = t / 6400;
    const float* p = g_bufB + (bc * 160 + 2 * y) * 160 + 2 * xx;
    float v0 = fmaxf(fmaxf(p[0], p[1]), fmaxf(p[160], p[161]));
    float v1 = v0;
    if (xx < 79) v1 = fmaxf(fmaxf(p[2], p[3]), fmaxf(p[162], p[163]));
    uint32_t h, l; split2(v0, v1, h, l);
    g_poolH2[t] = h; g_poolL2[t] = l;
}

#define DEFINE_SPLIT(NAME, SRC, DH, DL, N)                                    \
__global__ void NAME() {                                                      \
    int t = blockIdx.x * blockDim.x + threadIdx.x;                            \
    if (t >= (N)) return;                                                     \
    float v0 = SRC[t];                                                        \
    float v1 = (t + 1 < (N)) ? SRC[t + 1] : 0.f;                              \
    uint32_t h, l; split2(v0, v1, h, l);                                      \
    DH[t] = h; DL[t] = l;                                                     \
}
DEFINE_SPLIT(split_c4, g_c4, g_c4H2, g_c4L2, NC4)
DEFINE_SPLIT(split_c5, g_c5, g_c5H2, g_c5L2, NC5)
DEFINE_SPLIT(split_c6, g_c6, g_c6H2, g_c6L2, NC6)

// ------------------------- conv1: M=256/CTA, N=32, 25 k-steps -------------------------
#define C1_SM 57344
__global__ void __launch_bounds__(256) conv1_mma(const float* __restrict__ bias) {
    extern __shared__ char smem[];
    __shared__ int soffs[224];
    uint32_t sb = smem_u32(smem);
    int tid = threadIdx.x, wid = tid >> 5, lane = tid & 31;

    for (int pr = tid; pr < 224; pr += 256) {
        int off = 0;
        if (pr < 198) {
            int k = 2*pr, row = k / 12, col = k % 12;
            off = (row/11)*28900 + (row%11)*170 + col;
        }
        soffs[pr] = off;
    }
#pragma unroll
    for (int e = tid; e < 7168; e += 256) {
        int chunk = e >> 10, idx = e & 1023;
        int oc = idx >> 5, i = idx & 31;
        uint2 w2 = __ldg((const uint2*)(g_w1HL + oc*448 + chunk*64 + 2*i));
        uint32_t off = chunk*4096 + sw128((uint32_t)(oc*128 + i*4));
        *(uint32_t*)(smem + off)         = __byte_perm(w2.x, w2.y, 0x5410);
        *(uint32_t*)(smem + 28672 + off) = __byte_perm(w2.x, w2.y, 0x7632);
    }
    int xoff[4];
#pragma unroll
    for (int h = 0; h < 4; h++) {
        int pp = blockIdx.x*256 + wid*32 + (h>>1)*16 + (h&1)*8 + (lane>>2);
        int xo = pp % 160, yo = (pp/160) % 160, b = pp / 25600;
        xoff[h] = b*86700 + yo*170 + xo;
    }
    float acc[32];
#pragma unroll
    for (int i = 0; i < 32; i++) acc[i] = 0.f;
    __syncthreads();

#pragma unroll 1
    for (int kk = 0; kk < 25; kk++) {
        int cc = kk >> 2, ks = kk & 3;
        uint32_t bHi = sb + cc*4096;
        uint32_t bLo = sb + 28672 + cc*4096;
        int prA = kk*8 + (lane & 3);
        int oA = soffs[prA], oB = soffs[prA + 4];
        uint32_t b_hi[8], b_lo[8];
        uint32_t bbyte = (uint32_t)(((((lane >> 4) << 3) + (lane & 7))*128) + (ks*16 + (lane & 8))*2);
        ldsm4(&b_hi[0], bHi + sw128(bbyte));
        ldsm4(&b_hi[4], bHi + sw128(bbyte) + 2048);
        ldsm4(&b_lo[0], bLo + sw128(bbyte));
        ldsm4(&b_lo[4], bLo + sw128(bbyte) + 2048);
#pragma unroll
        for (int mt = 0; mt < 2; mt++) {
            int q0 = xoff[mt*2], q1 = xoff[mt*2 + 1];
            uint32_t ah0 = __ldg(g_xH2 + q0 + oA);
            uint32_t ah1 = __ldg(g_xH2 + q1 + oA);
            uint32_t ah2 = __ldg(g_xH2 + q0 + oB);
            uint32_t ah3 = __ldg(g_xH2 + q1 + oB);
            uint32_t al0 = __ldg(g_xL2 + q0 + oA);
            uint32_t al1 = __ldg(g_xL2 + q1 + oA);
            uint32_t al2 = __ldg(g_xL2 + q0 + oB);
            uint32_t al3 = __ldg(g_xL2 + q1 + oB);
            MMA3(4, acc + mt*16);
        }
    }
    __syncthreads();
    float* stg = (float*)smem;
#pragma unroll
    for (int h = 0; h < 2; h++) {
        if ((wid >> 2) == h) {
#pragma unroll
            for (int mt = 0; mt < 2; mt++)
#pragma unroll
                for (int nt = 0; nt < 4; nt++)
#pragma unroll
                    for (int r = 0; r < 4; r++) {
                        int row = (wid & 3)*32 + mt*16 + (lane >> 2) + ((r >> 1) << 3);
                        int col = nt*8 + ((lane & 3) << 1) + (r & 1);
                        stg[row*33 + col] = acc[(mt*4 + nt)*4 + r];
                    }
        }
        __syncthreads();
        {
            int r  = tid & 127;
            int j0 = (tid >> 7) * 16;
            int pp = blockIdx.x * 256 + h * 128 + r;
            int xo2 = pp % 160, yo2 = (pp / 160) % 160, b2 = pp / 25600;
            float* op = g_bufA + (b2 * 32 * 160 + yo2) * 160 + xo2;
#pragma unroll
            for (int j = 0; j < 16; j++) {
                int jj = j0 + j;
                op[jj * 25600] = stg[r*33 + jj] + __ldg(bias + jj);
            }
        }
        __syncthreads();
    }
}

// ------------------------- stats -------------------------
__global__ void stats_kernel(const float* __restrict__ gamma, const float* __restrict__ beta) {
    int rc = blockIdx.x;
    int region = rc >> 5;
    int c  = rc & 31;
    int ri = region >> 2, ci = region & 3;
    int tid = threadIdx.x;

    double s = 0.0, ss = 0.0;
    for (int i = tid; i < 64 * 1600; i += 256) {
        int b = i / 1600;
        int p = i - b * 1600;
        int y = ri * 40 + p / 40;
        int xx = ci * 40 + (p % 40);
        float v = g_bufA[((b * 32 + c) * 160 + y) * 160 + xx];
        s += (double)v; ss += (double)v * (double)v;
    }
    __shared__ double sh_s[256], sh_ss[256];
    sh_s[tid] = s; sh_ss[tid] = ss;
    __syncthreads();
    for (int off = 128; off > 0; off >>= 1) {
        if (tid < off) { sh_s[tid] += sh_s[tid + off]; sh_ss[tid] += sh_ss[tid + off]; }
        __syncthreads();
    }
    if (tid == 0) {
        double mean = sh_s[0] / 102400.0;
        double var  = sh_ss[0] / 102400.0 - mean * mean;
        float sc = __ldg(gamma + c) * rsqrtf((float)var + 1e-5f);
        g_scale[rc] = sc;
        g_shift[rc] = __ldg(beta + c) - (float)mean * sc;
    }
}

// ------------------------- rconv: M=256/CTA, N=32, 18 k-steps -------------------------
#define RC_SM 40960
__global__ void __launch_bounds__(256) rconv_mma(const float* __restrict__ bias) {
    extern __shared__ char smem[];
    uint32_t sb = smem_u32(smem);
    int tid = threadIdx.x, wid = tid >> 5, lane = tid & 31;

#pragma unroll
    for (int e = tid; e < 5120; e += 256) {
        int chunk = e >> 10, idx = e & 1023;
        int oc = idx >> 5, i = idx & 31;
        uint2 w2 = __ldg((const uint2*)(g_wrHL + oc*320 + chunk*64 + 2*i));
        uint32_t off = chunk*4096 + sw128((uint32_t)(oc*128 + i*4));
        *(uint32_t*)(smem + off)         = __byte_perm(w2.x, w2.y, 0x5410);
        *(uint32_t*)(smem + 20480 + off) = __byte_perm(w2.x, w2.y, 0x7632);
    }

    int px[4], msk[4];
#pragma unroll
    for (int h = 0; h < 4; h++) {
        int pp = blockIdx.x*256 + wid*32 + (h>>1)*16 + (h&1)*8 + (lane>>2);
        int xo = pp % 160, yo = (pp/160) % 160, b = pp / 25600;
        px[h] = b*409600 + yo*160 + xo;
        int lx = xo % 40, ly = yo % 40;
        int ry = ((ly > 0) ? 1 : 0) | 2 | ((ly < 39) ? 4 : 0);
        int cx = ((lx > 0) ? 1 : 0) | 2 | ((lx < 39) ? 4 : 0);
        int m = 0;
#pragma unroll
        for (int ty = 0; ty < 3; ty++)
#pragma unroll
            for (int tx = 0; tx < 3; tx++)
                if (((ry >> ty) & 1) && ((cx >> tx) & 1)) m |= 1 << (ty*3 + tx);
        msk[h] = m;
    }

    float acc[32];
#pragma unroll
    for (int i = 0; i < 32; i++) acc[i] = 0.f;
    __syncthreads();

#pragma unroll 1
    for (int kk = 0; kk < 18; kk++) {
        int t  = kk >> 1;
        int cc = kk >> 2, ks = kk & 3;
        int ty = t / 3;
        int dd = (ty - 1)*160 + (t - 3*ty - 1);
        uint32_t bHi = sb + cc*4096;
        uint32_t bLo = sb + 20480 + cc*4096;
        int q   = (kk & 1)*8 + (lane & 3);
        int co0 = q*25600 + dd;
        int co1 = co0 + 4*25600;
        uint32_t b_hi[8], b_lo[8];
        uint32_t bbyte = (uint32_t)(((((lane >> 4) << 3) + (lane & 7))*128) + (ks*16 + (lane & 8))*2);
        ldsm4(&b_hi[0], bHi + sw128(bbyte));
        ldsm4(&b_hi[4], bHi + sw128(bbyte) + 2048);
        ldsm4(&b_lo[0], bLo + sw128(bbyte));
        ldsm4(&b_lo[4], bLo + sw128(bbyte) + 2048);
#pragma unroll
        for (int mt = 0; mt < 2; mt++) {
            bool ok0 = (msk[mt*2]     >> t) & 1;
            bool ok1 = (msk[mt*2 + 1] >> t) & 1;
            int q0 = px[mt*2], q1 = px[mt*2 + 1];
            uint32_t ah0 = ok0 ? __ldg(g_actH2 + q0 + co0) : 0u;
            uint32_t ah1 = ok1 ? __ldg(g_actH2 + q1 + co0) : 0u;
            uint32_t ah2 = ok0 ? __ldg(g_actH2 + q0 + co1) : 0u;
            uint32_t ah3 = ok1 ? __ldg(g_actH2 + q1 + co1) : 0u;
            uint32_t al0 = ok0 ? __ldg(g_actL2 + q0 + co0) : 0u;
            uint32_t al1 = ok1 ? __ldg(g_actL2 + q1 + co0) : 0u;
            uint32_t al2 = ok0 ? __ldg(g_actL2 + q0 + co1) : 0u;
            uint32_t al3 = ok1 ? __ldg(g_actL2 + q1 + co1) : 0u;
            MMA3(4, acc + mt*16);
        }
    }
    __syncthreads();
    float* stg = (float*)smem;
#pragma unroll
    for (int h = 0; h < 2; h++) {
        if ((wid >> 2) == h) {
#pragma unroll
            for (int mt = 0; mt < 2; mt++)
#pragma unroll
                for (int nt = 0; nt < 4; nt++)
#pragma unroll
                    for (int r = 0; r < 4; r++) {
                        int row = (wid & 3)*32 + mt*16 + (lane >> 2) + ((r >> 1) << 3);
                        int col = nt*8 + ((lane & 3) << 1) + (r & 1);
                        stg[row*33 + col] = acc[(mt*4 + nt)*4 + r];
                    }
        }
        __syncthreads();
        {
            int r  = tid & 127;
            int j0 = (tid >> 7) * 16;
            int pp = blockIdx.x * 256 + h * 128 + r;
            int xo2 = pp % 160, yo2 = (pp / 160) % 160, b2 = pp / 25600;
            float* op = g_bufB + (b2 * 32 * 160 + yo2) * 160 + xo2;
#pragma unroll
            for (int j = 0; j < 16; j++) {
                int jj = j0 + j;
                op[jj * 25600] = stg[r*33 + jj] + __ldg(bias + jj);
            }
        }
        __syncthreads();
    }
}

// ------------------------- conv4: M=512/CTA, N=16, K=2048 -------------------------
#define CONV4_M (BATCH * 73 * 73)
#define C4_SM 32768
__global__ void __launch_bounds__(256) conv4_mma(const float* __restrict__ bias) {
    extern __shared__ char smem[];
    uint32_t sb = smem_u32(smem);
    int tid = threadIdx.x, wid = tid >> 5, lane = tid & 31;

    int px[8];
    bool pvh[8];
#pragma unroll
    for (int h = 0; h < 8; h++) {
        int pp = blockIdx.x*512 + wid*64 + (h>>1)*16 + (h&1)*8 + (lane>>2);
        pvh[h] = pp < CONV4_M;
        int pq = pvh[h] ? pp : 0;
        int xo = pq % 73, yo = (pq/73) % 73, b = pq / 5329;
        px[h] = b*204800 + yo*80 + xo;
    }

    float acc[32];
#pragma unroll
    for (int i = 0; i < 32; i++) acc[i] = 0.f;

    for (int qt = 0; qt < 4; qt++) {
        if (qt) __syncthreads();
#pragma unroll
        for (int e = tid; e < 4096; e += 256) {
            int chunk = e >> 9, idx = e & 511;
            int oc = idx >> 5, i = idx & 31;
            uint2 w2 = __ldg((const uint2*)(g_w4HL + oc*2048 + qt*512 + chunk*64 + 2*i));
            uint32_t off = chunk*2048 + sw128((uint32_t)(oc*128 + i*4));
            *(uint32_t*)(smem + off)         = __byte_perm(w2.x, w2.y, 0x5410);
            *(uint32_t*)(smem + 16384 + off) = __byte_perm(w2.x, w2.y, 0x7632);
        }
        __syncthreads();
#pragma unroll 1
        for (int cc = 0; cc < 8; cc++) {
            int c = qt*8 + cc;
            uint32_t bHi = sb + cc*2048;
            uint32_t bLo = sb + 16384 + cc*2048;
#pragma unroll
            for (int ks = 0; ks < 4; ks++) {
                int k  = c*64 + ks*16 + ((lane & 3) << 1);
                int co = (k >> 6)*6400 + ((k >> 3) & 7)*80 + (k & 7);
                uint32_t b_hi[4], b_lo[4];
                uint32_t bbyte = (uint32_t)(((((lane >> 4) << 3) + (lane & 7))*128) + (ks*16 + (lane & 8))*2);
                ldsm4(b_hi, bHi + sw128(bbyte));
                ldsm4(b_lo, bLo + sw128(bbyte));
#pragma unroll
                for (int mt = 0; mt < 4; mt++) {
                    bool v0 = pvh[mt*2], v1 = pvh[mt*2 + 1];
                    int q0 = px[mt*2], q1 = px[mt*2 + 1];
                    uint32_t ah0 = v0 ? __ldg(g_poolH2 + q0 + co)      : 0u;
                    uint32_t ah1 = v1 ? __ldg(g_poolH2 + q1 + co)      : 0u;
                    uint32_t ah2 = v0 ? __ldg(g_poolH2 + q0 + co + 80) : 0u;
                    uint32_t ah3 = v1 ? __ldg(g_poolH2 + q1 + co + 80) : 0u;
                    uint32_t al0 = v0 ? __ldg(g_poolL2 + q0 + co)      : 0u;
                    uint32_t al1 = v1 ? __ldg(g_poolL2 + q1 + co)      : 0u;
                    uint32_t al2 = v0 ? __ldg(g_poolL2 + q0 + co + 80) : 0u;
                    uint32_t al3 = v1 ? __ldg(g_poolL2 + q1 + co + 80) : 0u;
                    MMA3(2, acc + mt*8);
                }
            }
        }
    }
    __syncthreads();
    float* stg = (float*)smem;
#pragma unroll
    for (int h = 0; h < 4; h++) {
        if ((wid >> 1) == h) {
#pragma unroll
            for (int mt = 0; mt < 4; mt++)
#pragma unroll
                for (int nt = 0; nt < 2; nt++)
#pragma unroll
                    for (int r = 0; r < 4; r++) {
                        int row = (wid & 1)*64 + mt*16 + (lane >> 2) + ((r >> 1) << 3);
                        int col = nt*8 + ((lane & 3) << 1) + (r & 1);
                        stg[row*17 + col] = acc[(mt*2 + nt)*4 + r];
                    }
        }
        __syncthreads();
        {
            int r  = tid & 127;
            int j0 = (tid >> 7) * 8;
            int pq = blockIdx.x * 512 + h * 128 + r;
            if (pq < CONV4_M) {
                int xo2 = pq % 73, yo2 = (pq / 73) % 73, b2 = pq / 5329;
                float* op = g_c4 + (b2 * 16 * 73 + yo2) * 73 + xo2;
#pragma unroll
                for (int j = 0; j < 8; j++) {
                    int jj = j0 + j;
                    op[jj * 5329] = stg[r*17 + jj] + __ldg(bias + jj);
                }
            }
        }
        __syncthreads();
    }
}

// ------------- generic small MMA conv: M=256/CTA, N=16, table-driven offsets -------------
// IPLANE = INPUT channel-plane size; OPLANE = OUTPUT plane size.
#define DEFINE_SMALL_MMA(NAME, M_TOT, OW, OH, IPLANE, STRIDE, ROWW, WSRC, KTOT, KSTEPS, NCHUNK, NPAIR, OFF_EXPR, AH2, AL2, OUTBUF, OPLANE)  \
__global__ void __launch_bounds__(256) NAME(const float* __restrict__ bias) {        \
    extern __shared__ char smem[];                                                   \
    __shared__ int soffs[NPAIR];                                                     \
    uint32_t sb = smem_u32(smem);                                                    \
    int tid = threadIdx.x, wid = tid >> 5, lane = tid & 31;                          \
    for (int pr = tid; pr < (NPAIR); pr += 256) {                                    \
        int k = 2*pr;                                                                \
        soffs[pr] = (k < (KTOT)) ? (OFF_EXPR) : 0;                                   \
    }                                                                                \
    _Pragma("unroll")                                                                \
    for (int e = tid; e < (NCHUNK)*512; e += 256) {                                  \
        int chunk = e >> 9, idx = e & 511;                                           \
        int oc = idx >> 5, i = idx & 31;                                             \
        uint2 w2 = __ldg((const uint2*)(WSRC + oc*((NCHUNK)*64) + chunk*64 + 2*i));  \
        uint32_t off = chunk*2048 + sw128((uint32_t)(oc*128 + i*4));                 \
        *(uint32_t*)(smem + off)                  = __byte_perm(w2.x, w2.y, 0x5410); \
        *(uint32_t*)(smem + (NCHUNK)*2048 + off)  = __byte_perm(w2.x, w2.y, 0x7632); \
    }                                                                                \
    int px[4]; bool pvh[4];                                                          \
    _Pragma("unroll")                                                                \
    for (int h = 0; h < 4; h++) {                                                    \
        int pp = blockIdx.x*256 + wid*32 + (h>>1)*16 + (h&1)*8 + (lane>>2);          \
        pvh[h] = pp < (M_TOT);                                                       \
        int pq = pvh[h] ? pp : 0;                                                    \
        int xo = pq % (OW), yo = (pq/(OW)) % (OH), b = pq / ((OW)*(OH));             \
        px[h] = b*(IPLANE)*16 + ((STRIDE)*yo)*(ROWW) + (STRIDE)*xo;                  \
    }                                                                                \
    float acc[16];                                                                   \
    _Pragma("unroll")                                                                \
    for (int i = 0; i < 16; i++) acc[i] = 0.f;                                       \
    __syncthreads();                                                                 \
    _Pragma("unroll 1")                                                              \
    for (int kk = 0; kk < (KSTEPS); kk++) {                                          \
        int cc = kk >> 2, ks = kk & 3;                                               \
        uint32_t bHi = sb + cc*2048;                                                 \
        uint32_t bLo = sb + (NCHUNK)*2048 + cc*2048;                                 \
        int prA = kk*8 + (lane & 3);                                                 \
        int oA = soffs[prA], oB = soffs[prA + 4];                                    \
        uint32_t b_hi[4], b_lo[4];                                                   \
        uint32_t bbyte = (uint32_t)(((((lane >> 4) << 3) + (lane & 7))*128) + (ks*16 + (lane & 8))*2); \
        ldsm4(b_hi, bHi + sw128(bbyte));                                             \
        ldsm4(b_lo, bLo + sw128(bbyte));                                             \
        _Pragma("unroll")                                                            \
        for (int mt = 0; mt < 2; mt++) {                                             \
            bool v0 = pvh[mt*2], v1 = pvh[mt*2 + 1];                                 \
            int q0 = px[mt*2], q1 = px[mt*2 + 1];                                    \
            uint32_t ah0 = v0 ? __ldg(AH2 + q0 + oA) : 0u;                           \
            uint32_t ah1 = v1 ? __ldg(AH2 + q1 + oA) : 0u;                           \
            uint32_t ah2 = v0 ? __ldg(AH2 + q0 + oB) : 0u;                           \
            uint32_t ah3 = v1 ? __ldg(AH2 + q1 + oB) : 0u;                           \
            uint32_t al0 = v0 ? __ldg(AL2 + q0 + oA) : 0u;                           \
            uint32_t al1 = v1 ? __ldg(AL2 + q1 + oA) : 0u;                           \
            uint32_t al2 = v0 ? __ldg(AL2 + q0 + oB) : 0u;                           \
            uint32_t al3 = v1 ? __ldg(AL2 + q1 + oB) : 0u;                           \
            MMA3(2, acc + mt*8);                                                     \
        }                                                                            \
    }                                                                                \
    __syncthreads();                                                                 \
    float* stg = (float*)smem;                                                       \
    _Pragma("unroll")                                                                \
    for (int h = 0; h < 2; h++) {                                                    \
        if ((wid >> 2) == h) {                                                       \
            _Pragma("unroll")                                                        \
            for (int mt = 0; mt < 2; mt++)                                           \
                for (int nt = 0; nt < 2; nt++)                                       \
                    for (int r = 0; r < 4; r++) {                                    \
                        int row = (wid & 3)*32 + mt*16 + (lane >> 2) + ((r >> 1) << 3); \
                        int col = nt*8 + ((lane & 3) << 1) + (r & 1);                \
                        stg[row*17 + col] = acc[(mt*2 + nt)*4 + r];                  \
                    }                                                                \
        }                                                                            \
        __syncthreads();                                                             \
        {                                                                            \
            int r  = tid & 127;                                                      \
            int j0 = (tid >> 7) * 8;                                                 \
            int pq = blockIdx.x * 256 + h * 128 + r;                                 \
            if (pq < (M_TOT)) {                                                      \
                int xo2 = pq % (OW), yo2 = (pq / (OW)) % (OH), b2 = pq / ((OW)*(OH)); \
                float* op = OUTBUF + (b2 * 16 * (OH) + yo2) * (OW) + xo2;            \
                _Pragma("unroll")                                                    \
                for (int j = 0; j < 8; j++) {                                        \
                    int jj = j0 + j;                                                 \
                    op[jj * (OPLANE)] = stg[r*17 + jj] + __ldg(bias + jj);           \
                }                                                                    \
            }                                                                        \
        }                                                                            \
        __syncthreads();                                                             \
    }                                                                                \
}

// conv5: in c4 (73x73, plane 5329), 8x8 s2, out 33x33
#define CONV5_M (BATCH*33*33)
DEFINE_SMALL_MMA(conv5_mma, CONV5_M, 33, 33, 5329, 2, 73, g_w5HL, 1024, 64, 16, 512,
                 ((k >> 6)*5329 + ((k >> 3) & 7)*73 + (k & 7)), g_c4H2, g_c4L2, g_c5, 1089)
// conv6: in c5 (33x33, plane 1089), 6x6 s1, out 28x28
#define CONV6_M (BATCH*28*28)
DEFINE_SMALL_MMA(conv6_mma, CONV6_M, 28, 28, 1089, 1, 33, g_w6HL, 576, 36, 9, 288,
                 ((k/36)*1089 + ((k%36)/6)*33 + (k%36)%6), g_c5H2, g_c5L2, g_c6, 784)
// conv7: in c6 (28x28, plane 784), 5x5 s1 padded rows->6, out 24x24
#define CONV7_M (BATCH*24*24)
DEFINE_SMALL_MMA(conv7_mma, CONV7_M, 24, 24, 784, 1, 28, g_w7HL, 480, 30, 8, 256,
                 ((k/30)*784 + ((k%30)/6)*28 + (k%30)%6), g_c6H2, g_c6L2, g_c7, 576)

// ------------------------- weight transpose for conv8 / fc -------------------------
#define DEFINE_TRANS(NAME, OC, R, DST)                                        \
__global__ void NAME(const float* __restrict__ w) {                           \
    int e = blockIdx.x * blockDim.x + threadIdx.x;                            \
    if (e < (OC)*(R)) {                                                       \
        int oc = e / (R);                                                     \
        int r  = e - oc * (R);                                                \
        DST[r*(OC) + oc] = w[e];                                              \
    }                                                                         \
}
DEFINE_TRANS(t_w8,  16,  144, g_wT8)
DEFINE_TRANS(t_wfc, 512, 1024, g_wTfc)

// ------------------------- conv8: direct fp32 (tiny) -------------------------
__global__ void __launch_bounds__(128) conv8_kernel(const float* __restrict__ bias) {
    const int XP = 4;
    int t = blockIdx.x * 128 + threadIdx.x;
    if (t >= BATCH * 8 * XP) return;
    int xo = t % XP;
    int yo = (t / XP) % 8;
    int b  = t / (XP * 8);
    float a0[16], a1[16];
#pragma unroll
    for (int j = 0; j < 16; j++) { float bv = __ldg(bias + j); a0[j] = bv; a1[j] = bv; }
    for (int ic = 0; ic < 16; ic++) {
        const float* inp = g_c7 + ((b*16 + ic)*24 + yo*3)*24 + xo*3;
#pragma unroll 1
        for (int ky = 0; ky < 3; ky++) {
            const float* row = inp + ky*24;
            const float4* wrow = (const float4*)(g_wT8 + (ic*9 + ky*3)*16);
#pragma unroll
            for (int kx = 0; kx < 3; kx++) {
                float v0 = __ldg(row + kx);
                float v1 = __ldg(row + 12 + kx);
#pragma unroll
                for (int j = 0; j < 4; j++) {
                    float4 w4 = __ldg(wrow + kx*4 + j);
                    a0[4*j+0] = fmaf(v0, w4.x, a0[4*j+0]); a1[4*j+0] = fmaf(v1, w4.x, a1[4*j+0]);
                    a0[4*j+1] = fmaf(v0, w4.y, a0[4*j+1]); a1[4*j+1] = fmaf(v1, w4.y, a1[4*j+1]);
                    a0[4*j+2] = fmaf(v0, w4.z, a0[4*j+2]); a1[4*j+2] = fmaf(v1, w4.z, a1[4*j+2]);
                    a0[4*j+3] = fmaf(v0, w4.w, a0[4*j+3]); a1[4*j+3] = fmaf(v1, w4.w, a1[4*j+3]);
                }
            }
        }
    }
    float* op = g_c8 + (b*16*8 + yo)*8 + xo;
#pragma unroll
    for (int j = 0; j < 16; j++) {
        op[j*64]     = a0[j];
        op[j*64 + 4] = a1[j];
    }
}

// ------------------------- FC -------------------------
__global__ void fc_kernel(const float* __restrict__ bias, float* __restrict__ out) {
    __shared__ float sm[1024];
    int b = blockIdx.x;
    int o = threadIdx.x;
    sm[o]       = g_c8[b * 1024 + o];
    sm[o + 512] = g_c8[b * 1024 + o + 512];
    __syncthreads();
    float acc = __ldg(bias + o);
#pragma unroll 4
    for (int k = 0; k < 1024; k++)
        acc = fmaf(sm[k], g_wTfc[k * 512 + o], acc);
    out[b * 512 + o] = acc;
}

// ------------------------- launch -------------------------
static inline int gridFor(long n, int bs) { return (int)((n + bs - 1) / bs); }

extern "C" void kernel_launch(void* const* d_in, const int* in_sizes, int n_in,
                              void* d_out, int out_size) {
    const float* x        = (const float*)d_in[0];
    const float* conv1_w  = (const float*)d_in[1];
    const float* conv1_b  = (const float*)d_in[2];
    const float* bn_gamma = (const float*)d_in[3];
    const float* bn_beta  = (const float*)d_in[4];
    const float* prelu_a  = (const float*)d_in[5];
    const float* rconv_w  = (const float*)d_in[6];
    const float* rconv_b  = (const float*)d_in[7];
    const float* conv4_w  = (const float*)d_in[8];
    const float* conv4_b  = (const float*)d_in[9];
    const float* conv5_b  = (const float*)d_in[11];
    const float* conv6_b  = (const float*)d_in[13];
    const float* conv7_b  = (const float*)d_in[15];
    const float* conv8_b  = (const float*)d_in[17];
    const float* fc_b     = (const float*)d_in[19];
    float* out = (float*)d_out;

    cudaFuncSetAttribute(conv1_mma, cudaFuncAttributeMaxDynamicSharedMemorySize, C1_SM);
    cudaFuncSetAttribute(rconv_mma, cudaFuncAttributeMaxDynamicSharedMemorySize, RC_SM);
    cudaFuncSetAttribute(conv4_mma, cudaFuncAttributeMaxDynamicSharedMemorySize, C4_SM);
    cudaFuncSetAttribute(conv5_mma, cudaFuncAttributeMaxDynamicSharedMemorySize, 65536);

    // launches ordered so conv1_mma is the 4th launch (ncu captures it)
    split_x<<<gridFor(NX, 256), 256>>>(x);
    t_w1hl<<<gridFor(32*448, 256), 256>>>(conv1_w);
    t_wrhl<<<gridFor(32*320, 256), 256>>>(rconv_w);
    conv1_mma<<<6400, 256, C1_SM>>>(conv1_b);

    t_w4hl<<<gridFor(16*2048, 256), 256>>>(conv4_w);
    t_w5hl<<<gridFor(16*1024, 256), 256>>>((const float*)d_in[10]);
    t_w6hl<<<gridFor(16*576,  256), 256>>>((const float*)d_in[12]);
    t_w7hl<<<gridFor(16*512,  256), 256>>>((const float*)d_in[14]);
    t_w8 <<<gridFor(16*144,  256), 256>>>((const float*)d_in[16]);
    t_wfc<<<gridFor(512*1024,256), 256>>>((const float*)d_in[18]);

    stats_kernel<<<512, 256>>>(bn_gamma, bn_beta);
    act_kernel<<<gridFor(NACT, 256), 256>>>(prelu_a);
    rconv_mma<<<6400, 256, RC_SM>>>(rconv_b);
    pool_kernel<<<gridFor(NPOOL, 256), 256>>>();

    conv4_mma<<<gridFor(CONV4_M, 512), 256, C4_SM>>>(conv4_b);
    split_c4<<<gridFor(NC4, 256), 256>>>();
    conv5_mma<<<gridFor(CONV5_M, 256), 256, 65536>>>(conv5_b);
    split_c5<<<gridFor(NC5, 256), 256>>>();
    conv6_mma<<<gridFor(CONV6_M, 256), 256, 36864>>>(conv6_b);
    split_c6<<<gridFor(NC6, 256), 256>>>();
    conv7_mma<<<gridFor(CONV7_M, 256), 256, 32768>>>(conv7_b);
    conv8_kernel<<<gridFor((long)BATCH*8*4, 128), 128>>>(conv8_b);

    fc_kernel<<<BATCH, 512>>>(fc_b, out);
}

// round 15
// speedup vs baseline: 1.3567x; 1.1177x over previous
#include <cuda_runtime.h>
#include <cuda_bf16.h>
#include <cstdint>

#define BATCH 64

// ------------------------- scratch (no allocs allowed) -------------------------
__device__ float    g_bufA[BATCH*32*160*160];
__device__ float    g_bufB[BATCH*32*160*160];
#define NX (BATCH*3*170*170)
__device__ uint32_t g_xH2[NX];
__device__ uint32_t g_xL2[NX];
#define NACT (BATCH*16*160*160)
__device__ uint32_t g_actH2[NACT];
__device__ uint32_t g_actL2[NACT];
#define NPOOL (BATCH*32*80*80)
__device__ uint32_t g_poolH2[NPOOL];
__device__ uint32_t g_poolL2[NPOOL];
__device__ float g_c4[BATCH*16*73*73];
#define NC4 (BATCH*16*73*73)
__device__ uint32_t g_c4H2[NC4];
__device__ uint32_t g_c4L2[NC4];
__device__ float g_c5[BATCH*16*33*33];
#define NC5 (BATCH*16*33*33)
__device__ uint32_t g_c5H2[NC5];
__device__ uint32_t g_c5L2[NC5];
__device__ float g_c6[BATCH*16*28*28];
#define NC6 (BATCH*16*28*28)
__device__ uint32_t g_c6H2[NC6];
__device__ uint32_t g_c6L2[NC6];
__device__ float g_c7[BATCH*16*24*24];
__device__ float g_c8[BATCH*16*8*8];

__device__ uint32_t g_w1HL[32*448];
__device__ uint32_t g_wrHL[32*320];
__device__ uint32_t g_w4HL[16*2048];
__device__ uint32_t g_w5HL[16*1024];
__device__ uint32_t g_w6HL[16*576];
__device__ uint32_t g_w7HL[16*512];   // conv7, rows padded 5->6, K=480 (+pad to 512)

__device__ float g_wT8[144*16];
__device__ float g_wTfc[1024*512];

__device__ float g_scale[512];
__device__ float g_shift[512];

// ------------------------- helpers -------------------------
__device__ __forceinline__ uint32_t smem_u32(const void* p) {
    uint32_t a;
    asm("{ .reg .u64 t; cvta.to.shared.u64 t, %1; cvt.u32.u64 %0, t; }" : "=r"(a) : "l"(p));
    return a;
}
__device__ __forceinline__ uint32_t sw128(uint32_t o) { return o ^ ((o >> 3) & 0x70); }

__device__ __forceinline__ uint32_t packHL(float v) {
    __nv_bfloat16 h = __float2bfloat16(v);
    float r = v - __bfloat162float(h);
    __nv_bfloat16 l = __float2bfloat16(r);
    uint16_t hb = *reinterpret_cast<uint16_t*>(&h);
    uint16_t lb = *reinterpret_cast<uint16_t*>(&l);
    return (uint32_t)hb | ((uint32_t)lb << 16);
}
__device__ __forceinline__ void split2(float a, float b, uint32_t& hi, uint32_t& lo) {
    __nv_bfloat162 h = __floats2bfloat162_rn(a, b);
    float ra = a - __bfloat162float(h.x);
    float rb = b - __bfloat162float(h.y);
    __nv_bfloat162 l = __floats2bfloat162_rn(ra, rb);
    hi = *reinterpret_cast<uint32_t*>(&h);
    lo = *reinterpret_cast<uint32_t*>(&l);
}

__device__ __forceinline__ void ldsm4(uint32_t* r, uint32_t addr) {
    asm volatile("ldmatrix.sync.aligned.m8n8.x4.shared.b16 {%0,%1,%2,%3}, [%4];"
                 : "=r"(r[0]), "=r"(r[1]), "=r"(r[2]), "=r"(r[3]) : "r"(addr));
}

__device__ __forceinline__ void mma_bf16(float* c,
        uint32_t a0, uint32_t a1, uint32_t a2, uint32_t a3,
        uint32_t b0, uint32_t b1) {
    asm volatile(
        "mma.sync.aligned.m16n8k16.row.col.f32.bf16.bf16.f32 "
        "{%0,%1,%2,%3}, {%4,%5,%6,%7}, {%8,%9}, {%0,%1,%2,%3};"
        : "+f"(c[0]), "+f"(c[1]), "+f"(c[2]), "+f"(c[3])
        : "r"(a0), "r"(a1), "r"(a2), "r"(a3), "r"(b0), "r"(b1));
}

#define MMA3(NT, ACCM)                                                              \
    do {                                                                            \
        _Pragma("unroll")                                                           \
        for (int nt = 0; nt < (NT); nt++) {                                         \
            float* cc2 = (ACCM) + nt*4;                                             \
            mma_bf16(cc2, ah0,ah1,ah2,ah3, b_hi[nt*2], b_hi[nt*2+1]);               \
            mma_bf16(cc2, al0,al1,al2,al3, b_hi[nt*2], b_hi[nt*2+1]);               \
            mma_bf16(cc2, ah0,ah1,ah2,ah3, b_lo[nt*2], b_lo[nt*2+1]);               \
        }                                                                           \
    } while (0)

// ------------------------- pre-pass kernels -------------------------
__global__ void split_x(const float* __restrict__ x) {
    int t = blockIdx.x * blockDim.x + threadIdx.x;
    if (t >= NX) return;
    float v0 = x[t];
    float v1 = (t + 1 < NX) ? x[t + 1] : 0.f;
    uint32_t h, l; split2(v0, v1, h, l);
    g_xH2[t] = h; g_xL2[t] = l;
}
__global__ void t_w1hl(const float* __restrict__ w) {
    int e = blockIdx.x * blockDim.x + threadIdx.x;
    if (e < 32*448) {
        int oc = e / 448, k = e - oc*448;
        int row = k / 12, col = k % 12;
        float v = 0.f;
        if (row < 33 && col < 11) {
            int ic = row / 11, ky = row % 11;
            v = w[oc*363 + ic*121 + ky*11 + col];
        }
        g_w1HL[e] = packHL(v);
    }
}
__global__ void t_wrhl(const float* __restrict__ w) {
    int e = blockIdx.x * blockDim.x + threadIdx.x;
    if (e < 32*320) {
        int oc = e / 320, k = e - oc*320;
        int t9 = k >> 5, ic = k & 31;
        g_wrHL[e] = (t9 < 9) ? packHL(w[oc*288 + ic*9 + t9]) : 0u;
    }
}
__global__ void t_w4hl(const float* __restrict__ w) {
    int e = blockIdx.x * blockDim.x + threadIdx.x;
    if (e < 16*2048) g_w4HL[e] = packHL(w[e]);
}
__global__ void t_w5hl(const float* __restrict__ w) {
    int e = blockIdx.x * blockDim.x + threadIdx.x;
    if (e < 16*1024) g_w5HL[e] = packHL(w[e]);
}
__global__ void t_w6hl(const float* __restrict__ w) {
    int e = blockIdx.x * blockDim.x + threadIdx.x;
    if (e < 16*576) g_w6HL[e] = packHL(w[e]);   // layout already rows-of-6
}
__global__ void t_w7hl(const float* __restrict__ w) {
    int e = blockIdx.x * blockDim.x + threadIdx.x;
    if (e < 16*512) {
        int oc = e / 512, k = e - oc*512;
        float v = 0.f;
        if (k < 480) {
            int ic = k / 30, r = k % 30, ky = r / 6, kx = r % 6;
            if (kx < 5) v = w[oc*400 + ic*25 + ky*5 + kx];
        }
        g_w7HL[e] = packHL(v);
    }
}

// norm + PReLU + channel-pair split
__global__ void act_kernel(const float* __restrict__ pa) {
    int t = blockIdx.x * blockDim.x + threadIdx.x;
    if (t >= NACT) return;
    int xx = t % 160;
    int y  = (t / 160) % 160;
    int q  = (t / 25600) % 16;
    int b  = t / 409600;
    int region = (y / 40) * 4 + (xx / 40);
    int c0 = 2*q;
    int base = ((b*32 + c0)*160 + y)*160 + xx;
    float v0 = g_bufA[base];
    float v1 = g_bufA[base + 25600];
    float a = __ldg(pa);
    float r0 = fmaf(v0, g_scale[region*32 + c0],     g_shift[region*32 + c0]);
    float r1 = fmaf(v1, g_scale[region*32 + c0 + 1], g_shift[region*32 + c0 + 1]);
    r0 = (r0 > 0.f) ? r0 : a * r0;
    r1 = (r1 > 0.f) ? r1 : a * r1;
    uint32_t h, l; split2(r0, r1, h, l);
    g_actH2[t] = h; g_actL2[t] = l;
}

__global__ void pool_kernel() {
    int t = blockIdx.x * blockDim.x + threadIdx.x;
    if (t >= NPOOL) return;
    int xx = t % 80;
    int y  = (t / 80) % 80;
    int bc = t / 6400;
    const float* p = g_bufB + (bc * 160 + 2 * y) * 160 + 2 * xx;
    float v0 = fmaxf(fmaxf(p[0], p[1]), fmaxf(p[160], p[161]));
    float v1 = v0;
    if (xx < 79) v1 = fmaxf(fmaxf(p[2], p[3]), fmaxf(p[162], p[163]));
    uint32_t h, l; split2(v0, v1, h, l);
    g_poolH2[t] = h; g_poolL2[t] = l;
}

#define DEFINE_SPLIT(NAME, SRC, DH, DL, N)                                    \
__global__ void NAME() {                                                      \
    int t = blockIdx.x * blockDim.x + threadIdx.x;                            \
    if (t >= (N)) return;                                                     \
    float v0 = SRC[t];                                                        \
    float v1 = (t + 1 < (N)) ? SRC[t + 1] : 0.f;                              \
    uint32_t h, l; split2(v0, v1, h, l);                                      \
    DH[t] = h; DL[t] = l;                                                     \
}
DEFINE_SPLIT(split_c4, g_c4, g_c4H2, g_c4L2, NC4)
DEFINE_SPLIT(split_c5, g_c5, g_c5H2, g_c5L2, NC5)
DEFINE_SPLIT(split_c6, g_c6, g_c6H2, g_c6L2, NC6)

// ------------------------- conv1: M=256/CTA, N=32, 25 k-steps -------------------------
#define C1_SM 57344
__global__ void __launch_bounds__(256) conv1_mma(const float* __restrict__ bias) {
    extern __shared__ char smem[];
    __shared__ int soffs[224];
    uint32_t sb = smem_u32(smem);
    int tid = threadIdx.x, wid = tid >> 5, lane = tid & 31;

    for (int pr = tid; pr < 224; pr += 256) {
        int off = 0;
        if (pr < 198) {
            int k = 2*pr, row = k / 12, col = k % 12;
            off = (row/11)*28900 + (row%11)*170 + col;
        }
        soffs[pr] = off;
    }
#pragma unroll
    for (int e = tid; e < 7168; e += 256) {
        int chunk = e >> 10, idx = e & 1023;
        int oc = idx >> 5, i = idx & 31;
        uint2 w2 = __ldg((const uint2*)(g_w1HL + oc*448 + chunk*64 + 2*i));
        uint32_t off = chunk*4096 + sw128((uint32_t)(oc*128 + i*4));
        *(uint32_t*)(smem + off)         = __byte_perm(w2.x, w2.y, 0x5410);
        *(uint32_t*)(smem + 28672 + off) = __byte_perm(w2.x, w2.y, 0x7632);
    }
    int xoff[4];
#pragma unroll
    for (int h = 0; h < 4; h++) {
        int pp = blockIdx.x*256 + wid*32 + (h>>1)*16 + (h&1)*8 + (lane>>2);
        int xo = pp % 160, yo = (pp/160) % 160, b = pp / 25600;
        xoff[h] = b*86700 + yo*170 + xo;
    }
    float acc[32];
#pragma unroll
    for (int i = 0; i < 32; i++) acc[i] = 0.f;
    __syncthreads();

#pragma unroll 1
    for (int kk = 0; kk < 25; kk++) {
        int cc = kk >> 2, ks = kk & 3;
        uint32_t bHi = sb + cc*4096;
        uint32_t bLo = sb + 28672 + cc*4096;
        int prA = kk*8 + (lane & 3);
        int oA = soffs[prA], oB = soffs[prA + 4];
        uint32_t b_hi[8], b_lo[8];
        uint32_t bbyte = (uint32_t)(((((lane >> 4) << 3) + (lane & 7))*128) + (ks*16 + (lane & 8))*2);
        ldsm4(&b_hi[0], bHi + sw128(bbyte));
        ldsm4(&b_hi[4], bHi + sw128(bbyte) + 2048);
        ldsm4(&b_lo[0], bLo + sw128(bbyte));
        ldsm4(&b_lo[4], bLo + sw128(bbyte) + 2048);
#pragma unroll
        for (int mt = 0; mt < 2; mt++) {
            int q0 = xoff[mt*2], q1 = xoff[mt*2 + 1];
            uint32_t ah0 = __ldg(g_xH2 + q0 + oA);
            uint32_t ah1 = __ldg(g_xH2 + q1 + oA);
            uint32_t ah2 = __ldg(g_xH2 + q0 + oB);
            uint32_t ah3 = __ldg(g_xH2 + q1 + oB);
            uint32_t al0 = __ldg(g_xL2 + q0 + oA);
            uint32_t al1 = __ldg(g_xL2 + q1 + oA);
            uint32_t al2 = __ldg(g_xL2 + q0 + oB);
            uint32_t al3 = __ldg(g_xL2 + q1 + oB);
            MMA3(4, acc + mt*16);
        }
    }
    __syncthreads();
    float* stg = (float*)smem;
#pragma unroll
    for (int h = 0; h < 2; h++) {
        if ((wid >> 2) == h) {
#pragma unroll
            for (int mt = 0; mt < 2; mt++)
#pragma unroll
                for (int nt = 0; nt < 4; nt++)
#pragma unroll
                    for (int r = 0; r < 4; r++) {
                        int row = (wid & 3)*32 + mt*16 + (lane >> 2) + ((r >> 1) << 3);
                        int col = nt*8 + ((lane & 3) << 1) + (r & 1);
                        stg[row*33 + col] = acc[(mt*4 + nt)*4 + r];
                    }
        }
        __syncthreads();
        {
            int r  = tid & 127;
            int j0 = (tid >> 7) * 16;
            int pp = blockIdx.x * 256 + h * 128 + r;
            int xo2 = pp % 160, yo2 = (pp / 160) % 160, b2 = pp / 25600;
            float* op = g_bufA + (b2 * 32 * 160 + yo2) * 160 + xo2;
#pragma unroll
            for (int j = 0; j < 16; j++) {
                int jj = j0 + j;
                op[jj * 25600] = stg[r*33 + jj] + __ldg(bias + jj);
            }
        }
        __syncthreads();
    }
}

// ------------------------- stats -------------------------
__global__ void stats_kernel(const float* __restrict__ gamma, const float* __restrict__ beta) {
    int rc = blockIdx.x;
    int region = rc >> 5;
    int c  = rc & 31;
    int ri = region >> 2, ci = region & 3;
    int tid = threadIdx.x;

    double s = 0.0, ss = 0.0;
    for (int i = tid; i < 64 * 1600; i += 256) {
        int b = i / 1600;
        int p = i - b * 1600;
        int y = ri * 40 + p / 40;
        int xx = ci * 40 + (p % 40);
        float v = g_bufA[((b * 32 + c) * 160 + y) * 160 + xx];
        s += (double)v; ss += (double)v * (double)v;
    }
    __shared__ double sh_s[256], sh_ss[256];
    sh_s[tid] = s; sh_ss[tid] = ss;
    __syncthreads();
    for (int off = 128; off > 0; off >>= 1) {
        if (tid < off) { sh_s[tid] += sh_s[tid + off]; sh_ss[tid] += sh_ss[tid + off]; }
        __syncthreads();
    }
    if (tid == 0) {
        double mean = sh_s[0] / 102400.0;
        double var  = sh_ss[0] / 102400.0 - mean * mean;
        float sc = __ldg(gamma + c) * rsqrtf((float)var + 1e-5f);
        g_scale[rc] = sc;
        g_shift[rc] = __ldg(beta + c) - (float)mean * sc;
    }
}

// ------------------------- rconv: M=256/CTA, N=32, 18 k-steps -------------------------
#define RC_SM 40960
__global__ void __launch_bounds__(256) rconv_mma(const float* __restrict__ bias) {
    extern __shared__ char smem[];
    uint32_t sb = smem_u32(smem);
    int tid = threadIdx.x, wid = tid >> 5, lane = tid & 31;

#pragma unroll
    for (int e = tid; e < 5120; e += 256) {
        int chunk = e >> 10, idx = e & 1023;
        int oc = idx >> 5, i = idx & 31;
        uint2 w2 = __ldg((const uint2*)(g_wrHL + oc*320 + chunk*64 + 2*i));
        uint32_t off = chunk*4096 + sw128((uint32_t)(oc*128 + i*4));
        *(uint32_t*)(smem + off)         = __byte_perm(w2.x, w2.y, 0x5410);
        *(uint32_t*)(smem + 20480 + off) = __byte_perm(w2.x, w2.y, 0x7632);
    }

    int px[4], msk[4];
#pragma unroll
    for (int h = 0; h < 4; h++) {
        int pp = blockIdx.x*256 + wid*32 + (h>>1)*16 + (h&1)*8 + (lane>>2);
        int xo = pp % 160, yo = (pp/160) % 160, b = pp / 25600;
        px[h] = b*409600 + yo*160 + xo;
        int lx = xo % 40, ly = yo % 40;
        int ry = ((ly > 0) ? 1 : 0) | 2 | ((ly < 39) ? 4 : 0);
        int cx = ((lx > 0) ? 1 : 0) | 2 | ((lx < 39) ? 4 : 0);
        int m = 0;
#pragma unroll
        for (int ty = 0; ty < 3; ty++)
#pragma unroll
            for (int tx = 0; tx < 3; tx++)
                if (((ry >> ty) & 1) && ((cx >> tx) & 1)) m |= 1 << (ty*3 + tx);
        msk[h] = m;
    }

    float acc[32];
#pragma unroll
    for (int i = 0; i < 32; i++) acc[i] = 0.f;
    __syncthreads();

#pragma unroll 1
    for (int kk = 0; kk < 18; kk++) {
        int t  = kk >> 1;
        int cc = kk >> 2, ks = kk & 3;
        int ty = t / 3;
        int dd = (ty - 1)*160 + (t - 3*ty - 1);
        uint32_t bHi = sb + cc*4096;
        uint32_t bLo = sb + 20480 + cc*4096;
        int q   = (kk & 1)*8 + (lane & 3);
        int co0 = q*25600 + dd;
        int co1 = co0 + 4*25600;
        uint32_t b_hi[8], b_lo[8];
        uint32_t bbyte = (uint32_t)(((((lane >> 4) << 3) + (lane & 7))*128) + (ks*16 + (lane & 8))*2);
        ldsm4(&b_hi[0], bHi + sw128(bbyte));
        ldsm4(&b_hi[4], bHi + sw128(bbyte) + 2048);
        ldsm4(&b_lo[0], bLo + sw128(bbyte));
        ldsm4(&b_lo[4], bLo + sw128(bbyte) + 2048);
#pragma unroll
        for (int mt = 0; mt < 2; mt++) {
            bool ok0 = (msk[mt*2]     >> t) & 1;
            bool ok1 = (msk[mt*2 + 1] >> t) & 1;
            int q0 = px[mt*2], q1 = px[mt*2 + 1];
            uint32_t ah0 = ok0 ? __ldg(g_actH2 + q0 + co0) : 0u;
            uint32_t ah1 = ok1 ? __ldg(g_actH2 + q1 + co0) : 0u;
            uint32_t ah2 = ok0 ? __ldg(g_actH2 + q0 + co1) : 0u;
            uint32_t ah3 = ok1 ? __ldg(g_actH2 + q1 + co1) : 0u;
            uint32_t al0 = ok0 ? __ldg(g_actL2 + q0 + co0) : 0u;
            uint32_t al1 = ok1 ? __ldg(g_actL2 + q1 + co0) : 0u;
            uint32_t al2 = ok0 ? __ldg(g_actL2 + q0 + co1) : 0u;
            uint32_t al3 = ok1 ? __ldg(g_actL2 + q1 + co1) : 0u;
            MMA3(4, acc + mt*16);
        }
    }
    __syncthreads();
    float* stg = (float*)smem;
#pragma unroll
    for (int h = 0; h < 2; h++) {
        if ((wid >> 2) == h) {
#pragma unroll
            for (int mt = 0; mt < 2; mt++)
#pragma unroll
                for (int nt = 0; nt < 4; nt++)
#pragma unroll
                    for (int r = 0; r < 4; r++) {
                        int row = (wid & 3)*32 + mt*16 + (lane >> 2) + ((r >> 1) << 3);
                        int col = nt*8 + ((lane & 3) << 1) + (r & 1);
                        stg[row*33 + col] = acc[(mt*4 + nt)*4 + r];
                    }
        }
        __syncthreads();
        {
            int r  = tid & 127;
            int j0 = (tid >> 7) * 16;
            int pp = blockIdx.x * 256 + h * 128 + r;
            int xo2 = pp % 160, yo2 = (pp / 160) % 160, b2 = pp / 25600;
            float* op = g_bufB + (b2 * 32 * 160 + yo2) * 160 + xo2;
#pragma unroll
            for (int j = 0; j < 16; j++) {
                int jj = j0 + j;
                op[jj * 25600] = stg[r*33 + jj] + __ldg(bias + jj);
            }
        }
        __syncthreads();
    }
}

// ------------------------- conv4: M=256/CTA (32/warp), N=16, K=2048 -------------------------
#define CONV4_M (BATCH * 73 * 73)
#define C4_SM 32768
__global__ void __launch_bounds__(256) conv4_mma(const float* __restrict__ bias) {
    extern __shared__ char smem[];
    uint32_t sb = smem_u32(smem);
    int tid = threadIdx.x, wid = tid >> 5, lane = tid & 31;

    int px[4];
    bool pvh[4];
#pragma unroll
    for (int h = 0; h < 4; h++) {
        int pp = blockIdx.x*256 + wid*32 + (h>>1)*16 + (h&1)*8 + (lane>>2);
        pvh[h] = pp < CONV4_M;
        int pq = pvh[h] ? pp : 0;
        int xo = pq % 73, yo = (pq/73) % 73, b = pq / 5329;
        px[h] = b*204800 + yo*80 + xo;
    }

    float acc[16];
#pragma unroll
    for (int i = 0; i < 16; i++) acc[i] = 0.f;

    for (int qt = 0; qt < 4; qt++) {
        if (qt) __syncthreads();
#pragma unroll
        for (int e = tid; e < 4096; e += 256) {
            int chunk = e >> 9, idx = e & 511;
            int oc = idx >> 5, i = idx & 31;
            uint2 w2 = __ldg((const uint2*)(g_w4HL + oc*2048 + qt*512 + chunk*64 + 2*i));
            uint32_t off = chunk*2048 + sw128((uint32_t)(oc*128 + i*4));
            *(uint32_t*)(smem + off)         = __byte_perm(w2.x, w2.y, 0x5410);
            *(uint32_t*)(smem + 16384 + off) = __byte_perm(w2.x, w2.y, 0x7632);
        }
        __syncthreads();
#pragma unroll 1
        for (int cc = 0; cc < 8; cc++) {
            int c = qt*8 + cc;
            uint32_t bHi = sb + cc*2048;
            uint32_t bLo = sb + 16384 + cc*2048;
#pragma unroll
            for (int ks = 0; ks < 4; ks++) {
                int k  = c*64 + ks*16 + ((lane & 3) << 1);
                int co = (k >> 6)*6400 + ((k >> 3) & 7)*80 + (k & 7);
                uint32_t b_hi[4], b_lo[4];
                uint32_t bbyte = (uint32_t)(((((lane >> 4) << 3) + (lane & 7))*128) + (ks*16 + (lane & 8))*2);
                ldsm4(b_hi, bHi + sw128(bbyte));
                ldsm4(b_lo, bLo + sw128(bbyte));
#pragma unroll
                for (int mt = 0; mt < 2; mt++) {
                    bool v0 = pvh[mt*2], v1 = pvh[mt*2 + 1];
                    int q0 = px[mt*2], q1 = px[mt*2 + 1];
                    uint32_t ah0 = v0 ? __ldg(g_poolH2 + q0 + co)      : 0u;
                    uint32_t ah1 = v1 ? __ldg(g_poolH2 + q1 + co)      : 0u;
                    uint32_t ah2 = v0 ? __ldg(g_poolH2 + q0 + co + 80) : 0u;
                    uint32_t ah3 = v1 ? __ldg(g_poolH2 + q1 + co + 80) : 0u;
                    uint32_t al0 = v0 ? __ldg(g_poolL2 + q0 + co)      : 0u;
                    uint32_t al1 = v1 ? __ldg(g_poolL2 + q1 + co)      : 0u;
                    uint32_t al2 = v0 ? __ldg(g_poolL2 + q0 + co + 80) : 0u;
                    uint32_t al3 = v1 ? __ldg(g_poolL2 + q1 + co + 80) : 0u;
                    MMA3(2, acc + mt*8);
                }
            }
        }
    }
    __syncthreads();
    float* stg = (float*)smem;
#pragma unroll
    for (int h = 0; h < 2; h++) {
        if ((wid >> 2) == h) {
#pragma unroll
            for (int mt = 0; mt < 2; mt++)
#pragma unroll
                for (int nt = 0; nt < 2; nt++)
#pragma unroll
                    for (int r = 0; r < 4; r++) {
                        int row = (wid & 3)*32 + mt*16 + (lane >> 2) + ((r >> 1) << 3);
                        int col = nt*8 + ((lane & 3) << 1) + (r & 1);
                        stg[row*17 + col] = acc[(mt*2 + nt)*4 + r];
                    }
        }
        __syncthreads();
        {
            int r  = tid & 127;
            int j0 = (tid >> 7) * 8;
            int pq = blockIdx.x * 256 + h * 128 + r;
            if (pq < CONV4_M) {
                int xo2 = pq % 73, yo2 = (pq / 73) % 73, b2 = pq / 5329;
                float* op = g_c4 + (b2 * 16 * 73 + yo2) * 73 + xo2;
#pragma unroll
                for (int j = 0; j < 8; j++) {
                    int jj = j0 + j;
                    op[jj * 5329] = stg[r*17 + jj] + __ldg(bias + jj);
                }
            }
        }
        __syncthreads();
    }
}

// ------------- generic small MMA conv: M=256/CTA, N=16, table-driven offsets -------------
// IPLANE = INPUT channel-plane size; OPLANE = OUTPUT plane size.
#define DEFINE_SMALL_MMA(NAME, M_TOT, OW, OH, IPLANE, STRIDE, ROWW, WSRC, KTOT, KSTEPS, NCHUNK, NPAIR, OFF_EXPR, AH2, AL2, OUTBUF, OPLANE)  \
__global__ void __launch_bounds__(256) NAME(const float* __restrict__ bias) {        \
    extern __shared__ char smem[];                                                   \
    __shared__ int soffs[NPAIR];                                                     \
    uint32_t sb = smem_u32(smem);                                                    \
    int tid = threadIdx.x, wid = tid >> 5, lane = tid & 31;                          \
    for (int pr = tid; pr < (NPAIR); pr += 256) {                                    \
        int k = 2*pr;                                                                \
        soffs[pr] = (k < (KTOT)) ? (OFF_EXPR) : 0;                                   \
    }                                                                                \
    _Pragma("unroll")                                                                \
    for (int e = tid; e < (NCHUNK)*512; e += 256) {                                  \
        int chunk = e >> 9, idx = e & 511;                                           \
        int oc = idx >> 5, i = idx & 31;                                             \
        uint2 w2 = __ldg((const uint2*)(WSRC + oc*((NCHUNK)*64) + chunk*64 + 2*i));  \
        uint32_t off = chunk*2048 + sw128((uint32_t)(oc*128 + i*4));                 \
        *(uint32_t*)(smem + off)                  = __byte_perm(w2.x, w2.y, 0x5410); \
        *(uint32_t*)(smem + (NCHUNK)*2048 + off)  = __byte_perm(w2.x, w2.y, 0x7632); \
    }                                                                                \
    int px[4]; bool pvh[4];                                                          \
    _Pragma("unroll")                                                                \
    for (int h = 0; h < 4; h++) {                                                    \
        int pp = blockIdx.x*256 + wid*32 + (h>>1)*16 + (h&1)*8 + (lane>>2);          \
        pvh[h] = pp < (M_TOT);                                                       \
        int pq = pvh[h] ? pp : 0;                                                    \
        int xo = pq % (OW), yo = (pq/(OW)) % (OH), b = pq / ((OW)*(OH));             \
        px[h] = b*(IPLANE)*16 + ((STRIDE)*yo)*(ROWW) + (STRIDE)*xo;                  \
    }                                                                                \
    float acc[16];                                                                   \
    _Pragma("unroll")                                                                \
    for (int i = 0; i < 16; i++) acc[i] = 0.f;                                       \
    __syncthreads();                                                                 \
    _Pragma("unroll 1")                                                              \
    for (int kk = 0; kk < (KSTEPS); kk++) {                                          \
        int cc = kk >> 2, ks = kk & 3;                                               \
        uint32_t bHi = sb + cc*2048;                                                 \
        uint32_t bLo = sb + (NCHUNK)*2048 + cc*2048;                                 \
        int prA = kk*8 + (lane & 3);                                                 \
        int oA = soffs[prA], oB = soffs[prA + 4];                                    \
        uint32_t b_hi[4], b_lo[4];                                                   \
        uint32_t bbyte = (uint32_t)(((((lane >> 4) << 3) + (lane & 7))*128) + (ks*16 + (lane & 8))*2); \
        ldsm4(b_hi, bHi + sw128(bbyte));                                             \
        ldsm4(b_lo, bLo + sw128(bbyte));                                             \
        _Pragma("unroll")                                                            \
        for (int mt = 0; mt < 2; mt++) {                                             \
            bool v0 = pvh[mt*2], v1 = pvh[mt*2 + 1];                                 \
            int q0 = px[mt*2], q1 = px[mt*2 + 1];                                    \
            uint32_t ah0 = v0 ? __ldg(AH2 + q0 + oA) : 0u;                           \
            uint32_t ah1 = v1 ? __ldg(AH2 + q1 + oA) : 0u;                           \
            uint32_t ah2 = v0 ? __ldg(AH2 + q0 + oB) : 0u;                           \
            uint32_t ah3 = v1 ? __ldg(AH2 + q1 + oB) : 0u;                           \
            uint32_t al0 = v0 ? __ldg(AL2 + q0 + oA) : 0u;                           \
            uint32_t al1 = v1 ? __ldg(AL2 + q1 + oA) : 0u;                           \
            uint32_t al2 = v0 ? __ldg(AL2 + q0 + oB) : 0u;                           \
            uint32_t al3 = v1 ? __ldg(AL2 + q1 + oB) : 0u;                           \
            MMA3(2, acc + mt*8);                                                     \
        }                                                                            \
    }                                                                                \
    __syncthreads();                                                                 \
    float* stg = (float*)smem;                                                       \
    _Pragma("unroll")                                                                \
    for (int h = 0; h < 2; h++) {                                                    \
        if ((wid >> 2) == h) {                                                       \
            _Pragma("unroll")                                                        \
            for (int mt = 0; mt < 2; mt++)                                           \
                for (int nt = 0; nt < 2; nt++)                                       \
                    for (int r = 0; r < 4; r++) {                                    \
                        int row = (wid & 3)*32 + mt*16 + (lane >> 2) + ((r >> 1) << 3); \
                        int col = nt*8 + ((lane & 3) << 1) + (r & 1);                \
                        stg[row*17 + col] = acc[(mt*2 + nt)*4 + r];                  \
                    }                                                                \
        }                                                                            \
        __syncthreads();                                                             \
        {                                                                            \
            int r  = tid & 127;                                                      \
            int j0 = (tid >> 7) * 8;                                                 \
            int pq = blockIdx.x * 256 + h * 128 + r;                                 \
            if (pq < (M_TOT)) {                                                      \
                int xo2 = pq % (OW), yo2 = (pq / (OW)) % (OH), b2 = pq / ((OW)*(OH)); \
                float* op = OUTBUF + (b2 * 16 * (OH) + yo2) * (OW) + xo2;            \
                _Pragma("unroll")                                                    \
                for (int j = 0; j < 8; j++) {                                        \
                    int jj = j0 + j;                                                 \
                    op[jj * (OPLANE)] = stg[r*17 + jj] + __ldg(bias + jj);           \
                }                                                                    \
            }                                                                        \
        }                                                                            \
        __syncthreads();                                                             \
    }                                                                                \
}

// conv5: in c4 (73x73, plane 5329), 8x8 s2, out 33x33
#define CONV5_M (BATCH*33*33)
DEFINE_SMALL_MMA(conv5_mma, CONV5_M, 33, 33, 5329, 2, 73, g_w5HL, 1024, 64, 16, 512,
                 ((k >> 6)*5329 + ((k >> 3) & 7)*73 + (k & 7)), g_c4H2, g_c4L2, g_c5, 1089)
// conv6: in c5 (33x33, plane 1089), 6x6 s1, out 28x28
#define CONV6_M (BATCH*28*28)
DEFINE_SMALL_MMA(conv6_mma, CONV6_M, 28, 28, 1089, 1, 33, g_w6HL, 576, 36, 9, 288,
                 ((k/36)*1089 + ((k%36)/6)*33 + (k%36)%6), g_c5H2, g_c5L2, g_c6, 784)
// conv7: in c6 (28x28, plane 784), 5x5 s1 padded rows->6, out 24x24
#define CONV7_M (BATCH*24*24)
DEFINE_SMALL_MMA(conv7_mma, CONV7_M, 24, 24, 784, 1, 28, g_w7HL, 480, 30, 8, 256,
                 ((k/30)*784 + ((k%30)/6)*28 + (k%30)%6), g_c6H2, g_c6L2, g_c7, 576)

// ------------------------- weight transpose for conv8 / fc -------------------------
#define DEFINE_TRANS(NAME, OC, R, DST)                                        \
__global__ void NAME(const float* __restrict__ w) {                           \
    int e = blockIdx.x * blockDim.x + threadIdx.x;                            \
    if (e < (OC)*(R)) {                                                       \
        int oc = e / (R);                                                     \
        int r  = e - oc * (R);                                                \
        DST[r*(OC) + oc] = w[e];                                              \
    }                                                                         \
}
DEFINE_TRANS(t_w8,  16,  144, g_wT8)
DEFINE_TRANS(t_wfc, 512, 1024, g_wTfc)

// ------------------------- conv8: direct fp32 (tiny) -------------------------
__global__ void __launch_bounds__(128) conv8_kernel(const float* __restrict__ bias) {
    const int XP = 4;
    int t = blockIdx.x * 128 + threadIdx.x;
    if (t >= BATCH * 8 * XP) return;
    int xo = t % XP;
    int yo = (t / XP) % 8;
    int b  = t / (XP * 8);
    float a0[16], a1[16];
#pragma unroll
    for (int j = 0; j < 16; j++) { float bv = __ldg(bias + j); a0[j] = bv; a1[j] = bv; }
    for (int ic = 0; ic < 16; ic++) {
        const float* inp = g_c7 + ((b*16 + ic)*24 + yo*3)*24 + xo*3;
#pragma unroll 1
        for (int ky = 0; ky < 3; ky++) {
            const float* row = inp + ky*24;
            const float4* wrow = (const float4*)(g_wT8 + (ic*9 + ky*3)*16);
#pragma unroll
            for (int kx = 0; kx < 3; kx++) {
                float v0 = __ldg(row + kx);
                float v1 = __ldg(row + 12 + kx);
#pragma unroll
                for (int j = 0; j < 4; j++) {
                    float4 w4 = __ldg(wrow + kx*4 + j);
                    a0[4*j+0] = fmaf(v0, w4.x, a0[4*j+0]); a1[4*j+0] = fmaf(v1, w4.x, a1[4*j+0]);
                    a0[4*j+1] = fmaf(v0, w4.y, a0[4*j+1]); a1[4*j+1] = fmaf(v1, w4.y, a1[4*j+1]);
                    a0[4*j+2] = fmaf(v0, w4.z, a0[4*j+2]); a1[4*j+2] = fmaf(v1, w4.z, a1[4*j+2]);
                    a0[4*j+3] = fmaf(v0, w4.w, a0[4*j+3]); a1[4*j+3] = fmaf(v1, w4.w, a1[4*j+3]);
                }
            }
        }
    }
    float* op = g_c8 + (b*16*8 + yo)*8 + xo;
#pragma unroll
    for (int j = 0; j < 16; j++) {
        op[j*64]     = a0[j];
        op[j*64 + 4] = a1[j];
    }
}

// ------------------------- FC -------------------------
__global__ void fc_kernel(const float* __restrict__ bias, float* __restrict__ out) {
    __shared__ float sm[1024];
    int b = blockIdx.x;
    int o = threadIdx.x;
    sm[o]       = g_c8[b * 1024 + o];
    sm[o + 512] = g_c8[b * 1024 + o + 512];
    __syncthreads();
    float acc = __ldg(bias + o);
#pragma unroll 4
    for (int k = 0; k < 1024; k++)
        acc = fmaf(sm[k], g_wTfc[k * 512 + o], acc);
    out[b * 512 + o] = acc;
}

// ------------------------- launch -------------------------
static inline int gridFor(long n, int bs) { return (int)((n + bs - 1) / bs); }

extern "C" void kernel_launch(void* const* d_in, const int* in_sizes, int n_in,
                              void* d_out, int out_size) {
    const float* x        = (const float*)d_in[0];
    const float* conv1_w  = (const float*)d_in[1];
    const float* conv1_b  = (const float*)d_in[2];
    const float* bn_gamma = (const float*)d_in[3];
    const float* bn_beta  = (const float*)d_in[4];
    const float* prelu_a  = (const float*)d_in[5];
    const float* rconv_w  = (const float*)d_in[6];
    const float* rconv_b  = (const float*)d_in[7];
    const float* conv4_w  = (const float*)d_in[8];
    const float* conv4_b  = (const float*)d_in[9];
    const float* conv5_b  = (const float*)d_in[11];
    const float* conv6_b  = (const float*)d_in[13];
    const float* conv7_b  = (const float*)d_in[15];
    const float* conv8_b  = (const float*)d_in[17];
    const float* fc_b     = (const float*)d_in[19];
    float* out = (float*)d_out;

    cudaFuncSetAttribute(conv1_mma, cudaFuncAttributeMaxDynamicSharedMemorySize, C1_SM);
    cudaFuncSetAttribute(rconv_mma, cudaFuncAttributeMaxDynamicSharedMemorySize, RC_SM);
    cudaFuncSetAttribute(conv4_mma, cudaFuncAttributeMaxDynamicSharedMemorySize, C4_SM);
    cudaFuncSetAttribute(conv5_mma, cudaFuncAttributeMaxDynamicSharedMemorySize, 65536);

    // launches ordered so conv1_mma is the 4th launch (ncu captures it)
    split_x<<<gridFor(NX, 256), 256>>>(x);
    t_w1hl<<<gridFor(32*448, 256), 256>>>(conv1_w);
    t_wrhl<<<gridFor(32*320, 256), 256>>>(rconv_w);
    conv1_mma<<<6400, 256, C1_SM>>>(conv1_b);

    t_w4hl<<<gridFor(16*2048, 256), 256>>>(conv4_w);
    t_w5hl<<<gridFor(16*1024, 256), 256>>>((const float*)d_in[10]);
    t_w6hl<<<gridFor(16*576,  256), 256>>>((const float*)d_in[12]);
    t_w7hl<<<gridFor(16*512,  256), 256>>>((const float*)d_in[14]);
    t_w8 <<<gridFor(16*144,  256), 256>>>((const float*)d_in[16]);
    t_wfc<<<gridFor(512*1024,256), 256>>>((const float*)d_in[18]);

    stats_kernel<<<512, 256>>>(bn_gamma, bn_beta);
    act_kernel<<<gridFor(NACT, 256), 256>>>(prelu_a);
    rconv_mma<<<6400, 256, RC_SM>>>(rconv_b);
    pool_kernel<<<gridFor(NPOOL, 256), 256>>>();

    conv4_mma<<<gridFor(CONV4_M, 256), 256, C4_SM>>>(conv4_b);
    split_c4<<<gridFor(NC4, 256), 256>>>();
    conv5_mma<<<gridFor(CONV5_M, 256), 256, 65536>>>(conv5_b);
    split_c5<<<gridFor(NC5, 256), 256>>>();
    conv6_mma<<<gridFor(CONV6_M, 256), 256, 36864>>>(conv6_b);
    split_c6<<<gridFor(NC6, 256), 256>>>();
    conv7_mma<<<gridFor(CONV7_M, 256), 256, 32768>>>(conv7_b);
    conv8_kernel<<<gridFor((long)BATCH*8*4, 128), 128>>>(conv8_b);

    fc_kernel<<<BATCH, 512>>>(fc_b, out);
}

// round 16
// speedup vs baseline: 1.4037x; 1.0347x over previous
#include <cuda_runtime.h>
#include <cuda_bf16.h>
#include <cstdint>

#define BATCH 64

// ------------------------- scratch (no allocs allowed) -------------------------
__device__ float    g_bufA[BATCH*32*160*160];
__device__ float    g_bufB[BATCH*32*160*160];
#define NX (BATCH*3*170*170)
__device__ uint32_t g_xH2[NX];
__device__ uint32_t g_xL2[NX];
#define NACT (BATCH*16*160*160)
__device__ uint32_t g_actH2[NACT];
__device__ uint32_t g_actL2[NACT];
#define NPOOL (BATCH*32*80*80)
__device__ uint32_t g_poolH2[NPOOL];
__device__ uint32_t g_poolL2[NPOOL];
__device__ float g_c4[BATCH*16*73*73];
#define NC4 (BATCH*16*73*73)
__device__ uint32_t g_c4H2[NC4];
__device__ uint32_t g_c4L2[NC4];
__device__ float g_c5[BATCH*16*33*33];
#define NC5 (BATCH*16*33*33)
__device__ uint32_t g_c5H2[NC5];
__device__ uint32_t g_c5L2[NC5];
__device__ float g_c6[BATCH*16*28*28];
#define NC6 (BATCH*16*28*28)
__device__ uint32_t g_c6H2[NC6];
__device__ uint32_t g_c6L2[NC6];
__device__ float g_c7[BATCH*16*24*24];

__device__ uint32_t g_w1HL[32*448];
__device__ uint32_t g_wrHL[32*320];
__device__ uint32_t g_w4HL[16*2048];
__device__ uint32_t g_w5HL[16*1024];
__device__ uint32_t g_w6HL[16*576];
__device__ uint32_t g_w7HL[16*512];   // conv7, rows padded 5->6, K=480 (+pad to 512)

__device__ float g_wTfc[1024*512];

__device__ float g_scale[512];
__device__ float g_shift[512];

// ------------------------- helpers -------------------------
__device__ __forceinline__ uint32_t smem_u32(const void* p) {
    uint32_t a;
    asm("{ .reg .u64 t; cvta.to.shared.u64 t, %1; cvt.u32.u64 %0, t; }" : "=r"(a) : "l"(p));
    return a;
}
__device__ __forceinline__ uint32_t sw128(uint32_t o) { return o ^ ((o >> 3) & 0x70); }

__device__ __forceinline__ uint32_t packHL(float v) {
    __nv_bfloat16 h = __float2bfloat16(v);
    float r = v - __bfloat162float(h);
    __nv_bfloat16 l = __float2bfloat16(r);
    uint16_t hb = *reinterpret_cast<uint16_t*>(&h);
    uint16_t lb = *reinterpret_cast<uint16_t*>(&l);
    return (uint32_t)hb | ((uint32_t)lb << 16);
}
__device__ __forceinline__ void split2(float a, float b, uint32_t& hi, uint32_t& lo) {
    __nv_bfloat162 h = __floats2bfloat162_rn(a, b);
    float ra = a - __bfloat162float(h.x);
    float rb = b - __bfloat162float(h.y);
    __nv_bfloat162 l = __floats2bfloat162_rn(ra, rb);
    hi = *reinterpret_cast<uint32_t*>(&h);
    lo = *reinterpret_cast<uint32_t*>(&l);
}

__device__ __forceinline__ void ldsm4(uint32_t* r, uint32_t addr) {
    asm volatile("ldmatrix.sync.aligned.m8n8.x4.shared.b16 {%0,%1,%2,%3}, [%4];"
                 : "=r"(r[0]), "=r"(r[1]), "=r"(r[2]), "=r"(r[3]) : "r"(addr));
}

__device__ __forceinline__ void mma_bf16(float* c,
        uint32_t a0, uint32_t a1, uint32_t a2, uint32_t a3,
        uint32_t b0, uint32_t b1) {
    asm volatile(
        "mma.sync.aligned.m16n8k16.row.col.f32.bf16.bf16.f32 "
        "{%0,%1,%2,%3}, {%4,%5,%6,%7}, {%8,%9}, {%0,%1,%2,%3};"
        : "+f"(c[0]), "+f"(c[1]), "+f"(c[2]), "+f"(c[3])
        : "r"(a0), "r"(a1), "r"(a2), "r"(a3), "r"(b0), "r"(b1));
}

#define MMA3(NT, ACCM)                                                              \
    do {                                                                            \
        _Pragma("unroll")                                                           \
        for (int nt = 0; nt < (NT); nt++) {                                         \
            float* cc2 = (ACCM) + nt*4;                                             \
            mma_bf16(cc2, ah0,ah1,ah2,ah3, b_hi[nt*2], b_hi[nt*2+1]);               \
            mma_bf16(cc2, al0,al1,al2,al3, b_hi[nt*2], b_hi[nt*2+1]);               \
            mma_bf16(cc2, ah0,ah1,ah2,ah3, b_lo[nt*2], b_lo[nt*2+1]);               \
        }                                                                           \
    } while (0)

// ------------------------- pre-pass kernels (consolidated) -------------------------
__global__ void split_x(const float* __restrict__ x) {
    int t = blockIdx.x * blockDim.x + threadIdx.x;
    if (t >= NX) return;
    float v0 = x[t];
    float v1 = (t + 1 < NX) ? x[t + 1] : 0.f;
    uint32_t h, l; split2(v0, v1, h, l);
    g_xH2[t] = h; g_xL2[t] = l;
}

// conv1 weight prep (rows padded to 12, K padded to 448)
__global__ void prep_w1(const float* __restrict__ w) {
    int e = blockIdx.x * blockDim.x + threadIdx.x;
    if (e < 32*448) {
        int oc = e / 448, k = e - oc*448;
        int row = k / 12, col = k % 12;
        float v = 0.f;
        if (row < 33 && col < 11) {
            int ic = row / 11, ky = row % 11;
            v = w[oc*363 + ic*121 + ky*11 + col];
        }
        g_w1HL[e] = packHL(v);
    }
}

// all other weight transforms in one launch
#define PR_WR   10240                 // 32*320
#define PR_W4   (PR_WR + 32768)      // 16*2048
#define PR_W5   (PR_W4 + 16384)      // 16*1024
#define PR_W6   (PR_W5 + 9216)       // 16*576
#define PR_W7   (PR_W6 + 8192)       // 16*512
#define PR_WFC  (PR_W7 + 524288)     // 512*1024
__global__ void prep_rest(const float* __restrict__ wr, const float* __restrict__ w4,
                          const float* __restrict__ w5, const float* __restrict__ w6,
                          const float* __restrict__ w7, const float* __restrict__ wfc) {
    int e = blockIdx.x * blockDim.x + threadIdx.x;
    if (e < PR_WR) {
        int oc = e / 320, k = e - oc*320;
        int t9 = k >> 5, ic = k & 31;
        g_wrHL[e] = (t9 < 9) ? packHL(wr[oc*288 + ic*9 + t9]) : 0u;
    } else if (e < PR_W4) {
        int i = e - PR_WR;
        g_w4HL[i] = packHL(w4[i]);
    } else if (e < PR_W5) {
        int i = e - PR_W4;
        g_w5HL[i] = packHL(w5[i]);
    } else if (e < PR_W6) {
        int i = e - PR_W5;
        g_w6HL[i] = packHL(w6[i]);
    } else if (e < PR_W7) {
        int i = e - PR_W6;
        int oc = i / 512, k = i - oc*512;
        float v = 0.f;
        if (k < 480) {
            int ic = k / 30, r = k % 30, ky = r / 6, kx = r % 6;
            if (kx < 5) v = w7[oc*400 + ic*25 + ky*5 + kx];
        }
        g_w7HL[i] = packHL(v);
    } else if (e < PR_WFC) {
        int i = e - PR_W7;              // [512][1024] -> [1024][512]
        int oc = i / 1024, r = i - oc*1024;
        g_wTfc[r*512 + oc] = wfc[i];
    }
}

// norm + PReLU + channel-pair split
__global__ void act_kernel(const float* __restrict__ pa) {
    int t = blockIdx.x * blockDim.x + threadIdx.x;
    if (t >= NACT) return;
    int xx = t % 160;
    int y  = (t / 160) % 160;
    int q  = (t / 25600) % 16;
    int b  = t / 409600;
    int region = (y / 40) * 4 + (xx / 40);
    int c0 = 2*q;
    int base = ((b*32 + c0)*160 + y)*160 + xx;
    float v0 = g_bufA[base];
    float v1 = g_bufA[base + 25600];
    float a = __ldg(pa);
    float r0 = fmaf(v0, g_scale[region*32 + c0],     g_shift[region*32 + c0]);
    float r1 = fmaf(v1, g_scale[region*32 + c0 + 1], g_shift[region*32 + c0 + 1]);
    r0 = (r0 > 0.f) ? r0 : a * r0;
    r1 = (r1 > 0.f) ? r1 : a * r1;
    uint32_t h, l; split2(r0, r1, h, l);
    g_actH2[t] = h; g_actL2[t] = l;
}

__global__ void pool_kernel() {
    int t = blockIdx.x * blockDim.x + threadIdx.x;
    if (t >= NPOOL) return;
    int xx = t % 80;
    int y  = (t / 80) % 80;
    int bc = t / 6400;
    const float* p = g_bufB + (bc * 160 + 2 * y) * 160 + 2 * xx;
    float v0 = fmaxf(fmaxf(p[0], p[1]), fmaxf(p[160], p[161]));
    float v1 = v0;
    if (xx < 79) v1 = fmaxf(fmaxf(p[2], p[3]), fmaxf(p[162], p[163]));
    uint32_t h, l; split2(v0, v1, h, l);
    g_poolH2[t] = h; g_poolL2[t] = l;
}

#define DEFINE_SPLIT(NAME, SRC, DH, DL, N)                                    \
__global__ void NAME() {                                                      \
    int t = blockIdx.x * blockDim.x + threadIdx.x;                            \
    if (t >= (N)) return;                                                     \
    float v0 = SRC[t];                                                        \
    float v1 = (t + 1 < (N)) ? SRC[t + 1] : 0.f;                              \
    uint32_t h, l; split2(v0, v1, h, l);                                      \
    DH[t] = h; DL[t] = l;                                                     \
}
DEFINE_SPLIT(split_c4, g_c4, g_c4H2, g_c4L2, NC4)
DEFINE_SPLIT(split_c5, g_c5, g_c5H2, g_c5L2, NC5)
DEFINE_SPLIT(split_c6, g_c6, g_c6H2, g_c6L2, NC6)

// ------------------------- conv1: M=256/CTA, N=32, 25 k-steps -------------------------
#define C1_SM 57344
__global__ void __launch_bounds__(256) conv1_mma(const float* __restrict__ bias) {
    extern __shared__ char smem[];
    __shared__ int soffs[224];
    uint32_t sb = smem_u32(smem);
    int tid = threadIdx.x, wid = tid >> 5, lane = tid & 31;

    for (int pr = tid; pr < 224; pr += 256) {
        int off = 0;
        if (pr < 198) {
            int k = 2*pr, row = k / 12, col = k % 12;
            off = (row/11)*28900 + (row%11)*170 + col;
        }
        soffs[pr] = off;
    }
#pragma unroll
    for (int e = tid; e < 7168; e += 256) {
        int chunk = e >> 10, idx = e & 1023;
        int oc = idx >> 5, i = idx & 31;
        uint2 w2 = __ldg((const uint2*)(g_w1HL + oc*448 + chunk*64 + 2*i));
        uint32_t off = chunk*4096 + sw128((uint32_t)(oc*128 + i*4));
        *(uint32_t*)(smem + off)         = __byte_perm(w2.x, w2.y, 0x5410);
        *(uint32_t*)(smem + 28672 + off) = __byte_perm(w2.x, w2.y, 0x7632);
    }
    int xoff[4];
#pragma unroll
    for (int h = 0; h < 4; h++) {
        int pp = blockIdx.x*256 + wid*32 + (h>>1)*16 + (h&1)*8 + (lane>>2);
        int xo = pp % 160, yo = (pp/160) % 160, b = pp / 25600;
        xoff[h] = b*86700 + yo*170 + xo;
    }
    float acc[32];
#pragma unroll
    for (int i = 0; i < 32; i++) acc[i] = 0.f;
    __syncthreads();

#pragma unroll 1
    for (int kk = 0; kk < 25; kk++) {
        int cc = kk >> 2, ks = kk & 3;
        uint32_t bHi = sb + cc*4096;
        uint32_t bLo = sb + 28672 + cc*4096;
        int prA = kk*8 + (lane & 3);
        int oA = soffs[prA], oB = soffs[prA + 4];
        uint32_t b_hi[8], b_lo[8];
        uint32_t bbyte = (uint32_t)(((((lane >> 4) << 3) + (lane & 7))*128) + (ks*16 + (lane & 8))*2);
        ldsm4(&b_hi[0], bHi + sw128(bbyte));
        ldsm4(&b_hi[4], bHi + sw128(bbyte) + 2048);
        ldsm4(&b_lo[0], bLo + sw128(bbyte));
        ldsm4(&b_lo[4], bLo + sw128(bbyte) + 2048);
#pragma unroll
        for (int mt = 0; mt < 2; mt++) {
            int q0 = xoff[mt*2], q1 = xoff[mt*2 + 1];
            uint32_t ah0 = __ldg(g_xH2 + q0 + oA);
            uint32_t ah1 = __ldg(g_xH2 + q1 + oA);
            uint32_t ah2 = __ldg(g_xH2 + q0 + oB);
            uint32_t ah3 = __ldg(g_xH2 + q1 + oB);
            uint32_t al0 = __ldg(g_xL2 + q0 + oA);
            uint32_t al1 = __ldg(g_xL2 + q1 + oA);
            uint32_t al2 = __ldg(g_xL2 + q0 + oB);
            uint32_t al3 = __ldg(g_xL2 + q1 + oB);
            MMA3(4, acc + mt*16);
        }
    }
    __syncthreads();
    float* stg = (float*)smem;
#pragma unroll
    for (int h = 0; h < 2; h++) {
        if ((wid >> 2) == h) {
#pragma unroll
            for (int mt = 0; mt < 2; mt++)
#pragma unroll
                for (int nt = 0; nt < 4; nt++)
#pragma unroll
                    for (int r = 0; r < 4; r++) {
                        int row = (wid & 3)*32 + mt*16 + (lane >> 2) + ((r >> 1) << 3);
                        int col = nt*8 + ((lane & 3) << 1) + (r & 1);
                        stg[row*33 + col] = acc[(mt*4 + nt)*4 + r];
                    }
        }
        __syncthreads();
        {
            int r  = tid & 127;
            int j0 = (tid >> 7) * 16;
            int pp = blockIdx.x * 256 + h * 128 + r;
            int xo2 = pp % 160, yo2 = (pp / 160) % 160, b2 = pp / 25600;
            float* op = g_bufA + (b2 * 32 * 160 + yo2) * 160 + xo2;
#pragma unroll
            for (int j = 0; j < 16; j++) {
                int jj = j0 + j;
                op[jj * 25600] = stg[r*33 + jj] + __ldg(bias + jj);
            }
        }
        __syncthreads();
    }
}

// ------------------------- stats -------------------------
__global__ void stats_kernel(const float* __restrict__ gamma, const float* __restrict__ beta) {
    int rc = blockIdx.x;
    int region = rc >> 5;
    int c  = rc & 31;
    int ri = region >> 2, ci = region & 3;
    int tid = threadIdx.x;

    double s = 0.0, ss = 0.0;
    for (int i = tid; i < 64 * 1600; i += 256) {
        int b = i / 1600;
        int p = i - b * 1600;
        int y = ri * 40 + p / 40;
        int xx = ci * 40 + (p % 40);
        float v = g_bufA[((b * 32 + c) * 160 + y) * 160 + xx];
        s += (double)v; ss += (double)v * (double)v;
    }
    __shared__ double sh_s[256], sh_ss[256];
    sh_s[tid] = s; sh_ss[tid] = ss;
    __syncthreads();
    for (int off = 128; off > 0; off >>= 1) {
        if (tid < off) { sh_s[tid] += sh_s[tid + off]; sh_ss[tid] += sh_ss[tid + off]; }
        __syncthreads();
    }
    if (tid == 0) {
        double mean = sh_s[0] / 102400.0;
        double var  = sh_ss[0] / 102400.0 - mean * mean;
        float sc = __ldg(gamma + c) * rsqrtf((float)var + 1e-5f);
        g_scale[rc] = sc;
        g_shift[rc] = __ldg(beta + c) - (float)mean * sc;
    }
}

// ------------------------- rconv: M=256/CTA, N=32, 18 k-steps -------------------------
#define RC_SM 40960
__global__ void __launch_bounds__(256) rconv_mma(const float* __restrict__ bias) {
    extern __shared__ char smem[];
    uint32_t sb = smem_u32(smem);
    int tid = threadIdx.x, wid = tid >> 5, lane = tid & 31;

#pragma unroll
    for (int e = tid; e < 5120; e += 256) {
        int chunk = e >> 10, idx = e & 1023;
        int oc = idx >> 5, i = idx & 31;
        uint2 w2 = __ldg((const uint2*)(g_wrHL + oc*320 + chunk*64 + 2*i));
        uint32_t off = chunk*4096 + sw128((uint32_t)(oc*128 + i*4));
        *(uint32_t*)(smem + off)         = __byte_perm(w2.x, w2.y, 0x5410);
        *(uint32_t*)(smem + 20480 + off) = __byte_perm(w2.x, w2.y, 0x7632);
    }

    int px[4], msk[4];
#pragma unroll
    for (int h = 0; h < 4; h++) {
        int pp = blockIdx.x*256 + wid*32 + (h>>1)*16 + (h&1)*8 + (lane>>2);
        int xo = pp % 160, yo = (pp/160) % 160, b = pp / 25600;
        px[h] = b*409600 + yo*160 + xo;
        int lx = xo % 40, ly = yo % 40;
        int ry = ((ly > 0) ? 1 : 0) | 2 | ((ly < 39) ? 4 : 0);
        int cx = ((lx > 0) ? 1 : 0) | 2 | ((lx < 39) ? 4 : 0);
        int m = 0;
#pragma unroll
        for (int ty = 0; ty < 3; ty++)
#pragma unroll
            for (int tx = 0; tx < 3; tx++)
                if (((ry >> ty) & 1) && ((cx >> tx) & 1)) m |= 1 << (ty*3 + tx);
        msk[h] = m;
    }

    float acc[32];
#pragma unroll
    for (int i = 0; i < 32; i++) acc[i] = 0.f;
    __syncthreads();

#pragma unroll 1
    for (int kk = 0; kk < 18; kk++) {
        int t  = kk >> 1;
        int cc = kk >> 2, ks = kk & 3;
        int ty = t / 3;
        int dd = (ty - 1)*160 + (t - 3*ty - 1);
        uint32_t bHi = sb + cc*4096;
        uint32_t bLo = sb + 20480 + cc*4096;
        int q   = (kk & 1)*8 + (lane & 3);
        int co0 = q*25600 + dd;
        int co1 = co0 + 4*25600;
        uint32_t b_hi[8], b_lo[8];
        uint32_t bbyte = (uint32_t)(((((lane >> 4) << 3) + (lane & 7))*128) + (ks*16 + (lane & 8))*2);
        ldsm4(&b_hi[0], bHi + sw128(bbyte));
        ldsm4(&b_hi[4], bHi + sw128(bbyte) + 2048);
        ldsm4(&b_lo[0], bLo + sw128(bbyte));
        ldsm4(&b_lo[4], bLo + sw128(bbyte) + 2048);
#pragma unroll
        for (int mt = 0; mt < 2; mt++) {
            bool ok0 = (msk[mt*2]     >> t) & 1;
            bool ok1 = (msk[mt*2 + 1] >> t) & 1;
            int q0 = px[mt*2], q1 = px[mt*2 + 1];
            uint32_t ah0 = ok0 ? __ldg(g_actH2 + q0 + co0) : 0u;
            uint32_t ah1 = ok1 ? __ldg(g_actH2 + q1 + co0) : 0u;
            uint32_t ah2 = ok0 ? __ldg(g_actH2 + q0 + co1) : 0u;
            uint32_t ah3 = ok1 ? __ldg(g_actH2 + q1 + co1) : 0u;
            uint32_t al0 = ok0 ? __ldg(g_actL2 + q0 + co0) : 0u;
            uint32_t al1 = ok1 ? __ldg(g_actL2 + q1 + co0) : 0u;
            uint32_t al2 = ok0 ? __ldg(g_actL2 + q0 + co1) : 0u;
            uint32_t al3 = ok1 ? __ldg(g_actL2 + q1 + co1) : 0u;
            MMA3(4, acc + mt*16);
        }
    }
    __syncthreads();
    float* stg = (float*)smem;
#pragma unroll
    for (int h = 0; h < 2; h++) {
        if ((wid >> 2) == h) {
#pragma unroll
            for (int mt = 0; mt < 2; mt++)
#pragma unroll
                for (int nt = 0; nt < 4; nt++)
#pragma unroll
                    for (int r = 0; r < 4; r++) {
                        int row = (wid & 3)*32 + mt*16 + (lane >> 2) + ((r >> 1) << 3);
                        int col = nt*8 + ((lane & 3) << 1) + (r & 1);
                        stg[row*33 + col] = acc[(mt*4 + nt)*4 + r];
                    }
        }
        __syncthreads();
        {
            int r  = tid & 127;
            int j0 = (tid >> 7) * 16;
            int pp = blockIdx.x * 256 + h * 128 + r;
            int xo2 = pp % 160, yo2 = (pp / 160) % 160, b2 = pp / 25600;
            float* op = g_bufB + (b2 * 32 * 160 + yo2) * 160 + xo2;
#pragma unroll
            for (int j = 0; j < 16; j++) {
                int jj = j0 + j;
                op[jj * 25600] = stg[r*33 + jj] + __ldg(bias + jj);
            }
        }
        __syncthreads();
    }
}

// ------------------------- conv4: M=256/CTA (32/warp), N=16, K=2048 -------------------------
#define CONV4_M (BATCH * 73 * 73)
#define C4_SM 32768
__global__ void __launch_bounds__(256) conv4_mma(const float* __restrict__ bias) {
    extern __shared__ char smem[];
    uint32_t sb = smem_u32(smem);
    int tid = threadIdx.x, wid = tid >> 5, lane = tid & 31;

    int px[4];
    bool pvh[4];
#pragma unroll
    for (int h = 0; h < 4; h++) {
        int pp = blockIdx.x*256 + wid*32 + (h>>1)*16 + (h&1)*8 + (lane>>2);
        pvh[h] = pp < CONV4_M;
        int pq = pvh[h] ? pp : 0;
        int xo = pq % 73, yo = (pq/73) % 73, b = pq / 5329;
        px[h] = b*204800 + yo*80 + xo;
    }

    float acc[16];
#pragma unroll
    for (int i = 0; i < 16; i++) acc[i] = 0.f;

    for (int qt = 0; qt < 4; qt++) {
        if (qt) __syncthreads();
#pragma unroll
        for (int e = tid; e < 4096; e += 256) {
            int chunk = e >> 9, idx = e & 511;
            int oc = idx >> 5, i = idx & 31;
            uint2 w2 = __ldg((const uint2*)(g_w4HL + oc*2048 + qt*512 + chunk*64 + 2*i));
            uint32_t off = chunk*2048 + sw128((uint32_t)(oc*128 + i*4));
            *(uint32_t*)(smem + off)         = __byte_perm(w2.x, w2.y, 0x5410);
            *(uint32_t*)(smem + 16384 + off) = __byte_perm(w2.x, w2.y, 0x7632);
        }
        __syncthreads();
#pragma unroll 1
        for (int cc = 0; cc < 8; cc++) {
            int c = qt*8 + cc;
            uint32_t bHi = sb + cc*2048;
            uint32_t bLo = sb + 16384 + cc*2048;
#pragma unroll
            for (int ks = 0; ks < 4; ks++) {
                int k  = c*64 + ks*16 + ((lane & 3) << 1);
                int co = (k >> 6)*6400 + ((k >> 3) & 7)*80 + (k & 7);
                uint32_t b_hi[4], b_lo[4];
                uint32_t bbyte = (uint32_t)(((((lane >> 4) << 3) + (lane & 7))*128) + (ks*16 + (lane & 8))*2);
                ldsm4(b_hi, bHi + sw128(bbyte));
                ldsm4(b_lo, bLo + sw128(bbyte));
#pragma unroll
                for (int mt = 0; mt < 2; mt++) {
                    bool v0 = pvh[mt*2], v1 = pvh[mt*2 + 1];
                    int q0 = px[mt*2], q1 = px[mt*2 + 1];
                    uint32_t ah0 = v0 ? __ldg(g_poolH2 + q0 + co)      : 0u;
                    uint32_t ah1 = v1 ? __ldg(g_poolH2 + q1 + co)      : 0u;
                    uint32_t ah2 = v0 ? __ldg(g_poolH2 + q0 + co + 80) : 0u;
                    uint32_t ah3 = v1 ? __ldg(g_poolH2 + q1 + co + 80) : 0u;
                    uint32_t al0 = v0 ? __ldg(g_poolL2 + q0 + co)      : 0u;
                    uint32_t al1 = v1 ? __ldg(g_poolL2 + q1 + co)      : 0u;
                    uint32_t al2 = v0 ? __ldg(g_poolL2 + q0 + co + 80) : 0u;
                    uint32_t al3 = v1 ? __ldg(g_poolL2 + q1 + co + 80) : 0u;
                    MMA3(2, acc + mt*8);
                }
            }
        }
    }
    __syncthreads();
    float* stg = (float*)smem;
#pragma unroll
    for (int h = 0; h < 2; h++) {
        if ((wid >> 2) == h) {
#pragma unroll
            for (int mt = 0; mt < 2; mt++)
#pragma unroll
                for (int nt = 0; nt < 2; nt++)
#pragma unroll
                    for (int r = 0; r < 4; r++) {
                        int row = (wid & 3)*32 + mt*16 + (lane >> 2) + ((r >> 1) << 3);
                        int col = nt*8 + ((lane & 3) << 1) + (r & 1);
                        stg[row*17 + col] = acc[(mt*2 + nt)*4 + r];
                    }
        }
        __syncthreads();
        {
            int r  = tid & 127;
            int j0 = (tid >> 7) * 8;
            int pq = blockIdx.x * 256 + h * 128 + r;
            if (pq < CONV4_M) {
                int xo2 = pq % 73, yo2 = (pq / 73) % 73, b2 = pq / 5329;
                float* op = g_c4 + (b2 * 16 * 73 + yo2) * 73 + xo2;
#pragma unroll
                for (int j = 0; j < 8; j++) {
                    int jj = j0 + j;
                    op[jj * 5329] = stg[r*17 + jj] + __ldg(bias + jj);
                }
            }
        }
        __syncthreads();
    }
}

// ------------- generic small MMA conv: M=256/CTA, N=16, table-driven offsets -------------
#define DEFINE_SMALL_MMA(NAME, M_TOT, OW, OH, IPLANE, STRIDE, ROWW, WSRC, KTOT, KSTEPS, NCHUNK, NPAIR, OFF_EXPR, AH2, AL2, OUTBUF, OPLANE)  \
__global__ void __launch_bounds__(256) NAME(const float* __restrict__ bias) {        \
    extern __shared__ char smem[];                                                   \
    __shared__ int soffs[NPAIR];                                                     \
    uint32_t sb = smem_u32(smem);                                                    \
    int tid = threadIdx.x, wid = tid >> 5, lane = tid & 31;                          \
    for (int pr = tid; pr < (NPAIR); pr += 256) {                                    \
        int k = 2*pr;                                                                \
        soffs[pr] = (k < (KTOT)) ? (OFF_EXPR) : 0;                                   \
    }                                                                                \
    _Pragma("unroll")                                                                \
    for (int e = tid; e < (NCHUNK)*512; e += 256) {                                  \
        int chunk = e >> 9, idx = e & 511;                                           \
        int oc = idx >> 5, i = idx & 31;                                             \
        uint2 w2 = __ldg((const uint2*)(WSRC + oc*((NCHUNK)*64) + chunk*64 + 2*i));  \
        uint32_t off = chunk*2048 + sw128((uint32_t)(oc*128 + i*4));                 \
        *(uint32_t*)(smem + off)                  = __byte_perm(w2.x, w2.y, 0x5410); \
        *(uint32_t*)(smem + (NCHUNK)*2048 + off)  = __byte_perm(w2.x, w2.y, 0x7632); \
    }                                                                                \
    int px[4]; bool pvh[4];                                                          \
    _Pragma("unroll")                                                                \
    for (int h = 0; h < 4; h++) {                                                    \
        int pp = blockIdx.x*256 + wid*32 + (h>>1)*16 + (h&1)*8 + (lane>>2);          \
        pvh[h] = pp < (M_TOT);                                                       \
        int pq = pvh[h] ? pp : 0;                                                    \
        int xo = pq % (OW), yo = (pq/(OW)) % (OH), b = pq / ((OW)*(OH));             \
        px[h] = b*(IPLANE)*16 + ((STRIDE)*yo)*(ROWW) + (STRIDE)*xo;                  \
    }                                                                                \
    float acc[16];                                                                   \
    _Pragma("unroll")                                                                \
    for (int i = 0; i < 16; i++) acc[i] = 0.f;                                       \
    __syncthreads();                                                                 \
    _Pragma("unroll 1")                                                              \
    for (int kk = 0; kk < (KSTEPS); kk++) {                                          \
        int cc = kk >> 2, ks = kk & 3;                                               \
        uint32_t bHi = sb + cc*2048;                                                 \
        uint32_t bLo = sb + (NCHUNK)*2048 + cc*2048;                                 \
        int prA = kk*8 + (lane & 3);                                                 \
        int oA = soffs[prA], oB = soffs[prA + 4];                                    \
        uint32_t b_hi[4], b_lo[4];                                                   \
        uint32_t bbyte = (uint32_t)(((((lane >> 4) << 3) + (lane & 7))*128) + (ks*16 + (lane & 8))*2); \
        ldsm4(b_hi, bHi + sw128(bbyte));                                             \
        ldsm4(b_lo, bLo + sw128(bbyte));                                             \
        _Pragma("unroll")                                                            \
        for (int mt = 0; mt < 2; mt++) {                                             \
            bool v0 = pvh[mt*2], v1 = pvh[mt*2 + 1];                                 \
            int q0 = px[mt*2], q1 = px[mt*2 + 1];                                    \
            uint32_t ah0 = v0 ? __ldg(AH2 + q0 + oA) : 0u;                           \
            uint32_t ah1 = v1 ? __ldg(AH2 + q1 + oA) : 0u;                           \
            uint32_t ah2 = v0 ? __ldg(AH2 + q0 + oB) : 0u;                           \
            uint32_t ah3 = v1 ? __ldg(AH2 + q1 + oB) : 0u;                           \
            uint32_t al0 = v0 ? __ldg(AL2 + q0 + oA) : 0u;                           \
            uint32_t al1 = v1 ? __ldg(AL2 + q1 + oA) : 0u;                           \
            uint32_t al2 = v0 ? __ldg(AL2 + q0 + oB) : 0u;                           \
            uint32_t al3 = v1 ? __ldg(AL2 + q1 + oB) : 0u;                           \
            MMA3(2, acc + mt*8);                                                     \
        }                                                                            \
    }                                                                                \
    __syncthreads();                                                                 \
    float* stg = (float*)smem;                                                       \
    _Pragma("unroll")                                                                \
    for (int h = 0; h < 2; h++) {                                                    \
        if ((wid >> 2) == h) {                                                       \
            _Pragma("unroll")                                                        \
            for (int mt = 0; mt < 2; mt++)                                           \
                for (int nt = 0; nt < 2; nt++)                                       \
                    for (int r = 0; r < 4; r++) {                                    \
                        int row = (wid & 3)*32 + mt*16 + (lane >> 2) + ((r >> 1) << 3); \
                        int col = nt*8 + ((lane & 3) << 1) + (r & 1);                \
                        stg[row*17 + col] = acc[(mt*2 + nt)*4 + r];                  \
                    }                                                                \
        }                                                                            \
        __syncthreads();                                                             \
        {                                                                            \
            int r  = tid & 127;                                                      \
            int j0 = (tid >> 7) * 8;                                                 \
            int pq = blockIdx.x * 256 + h * 128 + r;                                 \
            if (pq < (M_TOT)) {                                                      \
                int xo2 = pq % (OW), yo2 = (pq / (OW)) % (OH), b2 = pq / ((OW)*(OH)); \
                float* op = OUTBUF + (b2 * 16 * (OH) + yo2) * (OW) + xo2;            \
                _Pragma("unroll")                                                    \
                for (int j = 0; j < 8; j++) {                                        \
                    int jj = j0 + j;                                                 \
                    op[jj * (OPLANE)] = stg[r*17 + jj] + __ldg(bias + jj);           \
                }                                                                    \
            }                                                                        \
        }                                                                            \
        __syncthreads();                                                             \
    }                                                                                \
}

// conv5: in c4 (73x73, plane 5329), 8x8 s2, out 33x33
#define CONV5_M (BATCH*33*33)
DEFINE_SMALL_MMA(conv5_mma, CONV5_M, 33, 33, 5329, 2, 73, g_w5HL, 1024, 64, 16, 512,
                 ((k >> 6)*5329 + ((k >> 3) & 7)*73 + (k & 7)), g_c4H2, g_c4L2, g_c5, 1089)
// conv6: in c5 (33x33, plane 1089), 6x6 s1, out 28x28
#define CONV6_M (BATCH*28*28)
DEFINE_SMALL_MMA(conv6_mma, CONV6_M, 28, 28, 1089, 1, 33, g_w6HL, 576, 36, 9, 288,
                 ((k/36)*1089 + ((k%36)/6)*33 + (k%36)%6), g_c5H2, g_c5L2, g_c6, 784)
// conv7: in c6 (28x28, plane 784), 5x5 s1 padded rows->6, out 24x24
#define CONV7_M (BATCH*24*24)
DEFINE_SMALL_MMA(conv7_mma, CONV7_M, 24, 24, 784, 1, 28, g_w7HL, 480, 30, 8, 256,
                 ((k/30)*784 + ((k%30)/6)*28 + (k%30)%6), g_c6H2, g_c6L2, g_c7, 576)

// ------------------------- tail: conv8 (3x3 s3) fused with FC -------------------------
// block b: conv8 outputs for batch b -> smem[1024] -> FC 1024->512
__global__ void __launch_bounds__(512) tail_kernel(const float* __restrict__ w8,
                                                   const float* __restrict__ b8,
                                                   const float* __restrict__ fcb,
                                                   float* __restrict__ out) {
    __shared__ float c8s[1024];
    int b = blockIdx.x;
    int tid = threadIdx.x;

    // each thread computes 2 conv8 outputs (idx = tid, tid+512); idx = oc*64 + yo*8 + xo
#pragma unroll
    for (int half = 0; half < 2; half++) {
        int idx = tid + half * 512;
        int oc = idx >> 6;
        int yo = (idx >> 3) & 7;
        int xo = idx & 7;
        float a = __ldg(b8 + oc);
        const float* inp = g_c7 + (b*16*24 + yo*3)*24 + xo*3;   // + ic*576
        const float* wp  = w8 + oc*144;                          // [ic][ky][kx]
        for (int ic = 0; ic < 16; ic++) {
#pragma unroll
            for (int ky = 0; ky < 3; ky++) {
#pragma unroll
                for (int kx = 0; kx < 3; kx++) {
                    a = fmaf(__ldg(inp + ic*576 + ky*24 + kx), __ldg(wp + ic*9 + ky*3 + kx), a);
                }
            }
        }
        c8s[idx] = a;
    }
    __syncthreads();

    int o = tid;   // 512 outputs
    float acc = __ldg(fcb + o);
#pragma unroll 4
    for (int k = 0; k < 1024; k++)
        acc = fmaf(c8s[k], g_wTfc[k * 512 + o], acc);
    out[b * 512 + o] = acc;
}

// ------------------------- launch -------------------------
static inline int gridFor(long n, int bs) { return (int)((n + bs - 1) / bs); }

extern "C" void kernel_launch(void* const* d_in, const int* in_sizes, int n_in,
                              void* d_out, int out_size) {
    const float* x        = (const float*)d_in[0];
    const float* conv1_w  = (const float*)d_in[1];
    const float* conv1_b  = (const float*)d_in[2];
    const float* bn_gamma = (const float*)d_in[3];
    const float* bn_beta  = (const float*)d_in[4];
    const float* prelu_a  = (const float*)d_in[5];
    const float* rconv_w  = (const float*)d_in[6];
    const float* rconv_b  = (const float*)d_in[7];
    const float* conv4_w  = (const float*)d_in[8];
    const float* conv4_b  = (const float*)d_in[9];
    const float* conv5_w  = (const float*)d_in[10];
    const float* conv5_b  = (const float*)d_in[11];
    const float* conv6_w  = (const float*)d_in[12];
    const float* conv6_b  = (const float*)d_in[13];
    const float* conv7_w  = (const float*)d_in[14];
    const float* conv7_b  = (const float*)d_in[15];
    const float* conv8_w  = (const float*)d_in[16];
    const float* conv8_b  = (const float*)d_in[17];
    const float* fc_w     = (const float*)d_in[18];
    const float* fc_b     = (const float*)d_in[19];
    float* out = (float*)d_out;

    cudaFuncSetAttribute(conv1_mma, cudaFuncAttributeMaxDynamicSharedMemorySize, C1_SM);
    cudaFuncSetAttribute(rconv_mma, cudaFuncAttributeMaxDynamicSharedMemorySize, RC_SM);
    cudaFuncSetAttribute(conv4_mma, cudaFuncAttributeMaxDynamicSharedMemorySize, C4_SM);
    cudaFuncSetAttribute(conv5_mma, cudaFuncAttributeMaxDynamicSharedMemorySize, 65536);

    // launches ordered so conv1_mma stays the 4th launch (ncu captures it)
    split_x<<<gridFor(NX, 256), 256>>>(x);
    prep_w1<<<gridFor(32*448, 256), 256>>>(conv1_w);
    prep_rest<<<gridFor(PR_WFC, 256), 256>>>(rconv_w, conv4_w, conv5_w, conv6_w, conv7_w, fc_w);
    conv1_mma<<<6400, 256, C1_SM>>>(conv1_b);

    stats_kernel<<<512, 256>>>(bn_gamma, bn_beta);
    act_kernel<<<gridFor(NACT, 256), 256>>>(prelu_a);
    rconv_mma<<<6400, 256, RC_SM>>>(rconv_b);
    pool_kernel<<<gridFor(NPOOL, 256), 256>>>();

    conv4_mma<<<gridFor(CONV4_M, 256), 256, C4_SM>>>(conv4_b);
    split_c4<<<gridFor(NC4, 256), 256>>>();
    conv5_mma<<<gridFor(CONV5_M, 256), 256, 65536>>>(conv5_b);
    split_c5<<<gridFor(NC5, 256), 256>>>();
    conv6_mma<<<gridFor(CONV6_M, 256), 256, 36864>>>(conv6_b);
    split_c6<<<gridFor(NC6, 256), 256>>>();
    conv7_mma<<<gridFor(CONV7_M, 256), 256, 32768>>>(conv7_b);
    tail_kernel<<<BATCH, 512>>>(conv8_w, conv8_b, fc_b, out);
}